// round 8
// baseline (speedup 1.0000x reference)
#include <cuda_runtime.h>
#include <cuda_fp16.h>
#include <float.h>
#include <stdint.h>

// ---------------- problem constants ----------------
#define BATCH      8
#define NPTS       1024
#define NPOINTS    (BATCH * NPTS)        // 8192
#define HEADC      8
#define SHAPEC     256
#define XCH        (HEADC + SHAPEC)      // 264
#define NEXPERT    16
#define SC_HID     256
#define SC_OUT     128
#define K0PAD      160                   // 136 padded to 160
#define C1OUT      256
#define C2OUT      512
#define C3OUT      1024
#define DEC1       1024
#define DEC2       2048
#define DEC3       8192
#define ETILE      64
#define MAXTILES   (NPOINTS / ETILE + NEXPERT)   // 144
#define NPART      16                    // pool partials per batch (8192/64/8)

typedef __half h16;

// ---------------- scratch (device globals; no runtime alloc) ----------------
__device__ __align__(256) h16 g_xhi[NPOINTS * SHAPEC];   // [8192,256] point-major
__device__ __align__(256) h16 g_xlo[NPOINTS * SHAPEC];
__device__ __align__(256) h16 g_a0hi[NPOINTS * K0PAD];
__device__ __align__(256) h16 g_a0lo[NPOINTS * K0PAD];
__device__ __align__(256) h16 g_a1hi[NPOINTS * C1OUT];
__device__ __align__(256) h16 g_a1lo[NPOINTS * C1OUT];
__device__ __align__(256) h16 g_a2hi[NPOINTS * C2OUT];
__device__ __align__(256) h16 g_a2lo[NPOINTS * C2OUT];
__device__ __align__(256) h16 g_w1hi[C1OUT * K0PAD];
__device__ __align__(256) h16 g_w1lo[C1OUT * K0PAD];
__device__ __align__(256) h16 g_w2hi[C2OUT * C1OUT];
__device__ __align__(256) h16 g_w2lo[C2OUT * C1OUT];
__device__ __align__(256) h16 g_w3hi[C3OUT * C2OUT];
__device__ __align__(256) h16 g_w3lo[C3OUT * C2OUT];
// expert weights transposed to [e][out][k], f16 hi/lo
__device__ __align__(256) h16 g_e1hi[NEXPERT * SC_HID * SHAPEC];
__device__ __align__(256) h16 g_e1lo[NEXPERT * SC_HID * SHAPEC];
__device__ __align__(256) h16 g_e2hi[NEXPERT * SC_OUT * SC_HID];
__device__ __align__(256) h16 g_e2lo[NEXPERT * SC_OUT * SC_HID];
__device__ float g_part[BATCH * NPART * C3OUT];
__device__ float g_lat[BATCH * C3OUT];
__device__ float g_d1[BATCH * DEC1];
__device__ float g_d2[BATCH * DEC2];
__device__ int   g_idx[NPOINTS];
__device__ int   g_tileExpert[MAXTILES];
__device__ int   g_tileStart[MAXTILES];
__device__ int   g_tileLen[MAXTILES];
__device__ int   g_nTiles;

// ---------------- ptx helpers (sm_80-safe) ----------------
__device__ __forceinline__ uint32_t smem_u32(const void* p) {
    uint32_t a;
    asm("{ .reg .u64 t; cvta.to.shared.u64 t, %1; cvt.u32.u64 %0, t; }" : "=r"(a) : "l"(p));
    return a;
}
#define CP_ASYNC16(dst, src) \
    asm volatile("cp.async.cg.shared.global [%0], [%1], 16;" :: "r"(dst), "l"(src))
#define CP_COMMIT() asm volatile("cp.async.commit_group;" ::: "memory")
#define CP_WAIT0()  asm volatile("cp.async.wait_group 0;" ::: "memory")
#define CP_WAIT1()  asm volatile("cp.async.wait_group 1;" ::: "memory")

#define LDSM4(r, addr) \
    asm volatile("ldmatrix.sync.aligned.m8n8.x4.shared.b16 {%0,%1,%2,%3}, [%4];" \
        : "=r"((r)[0]), "=r"((r)[1]), "=r"((r)[2]), "=r"((r)[3]) : "r"(addr))

__device__ __forceinline__ void mma_f32(float* d, const uint32_t* a,
                                        uint32_t b0, uint32_t b1) {
    asm volatile(
        "mma.sync.aligned.m16n8k16.row.col.f32.f16.f16.f32 "
        "{%0,%1,%2,%3}, {%4,%5,%6,%7}, {%8,%9}, {%0,%1,%2,%3};"
        : "+f"(d[0]), "+f"(d[1]), "+f"(d[2]), "+f"(d[3])
        : "r"(a[0]), "r"(a[1]), "r"(a[2]), "r"(a[3]), "r"(b0), "r"(b1));
}

__device__ __forceinline__ void f16_split(float v, h16& h, h16& l) {
    h = __float2half_rn(v);
    l = __float2half_rn(v - __half2float(h));
}
__device__ __forceinline__ uint32_t pack2h(h16 a, h16 b) {
    __half2 t; t.x = a; t.y = b;
    return *(uint32_t*)&t;
}

// ---------------- 1. fused prep: transpose | tsplit | head | wsplit ---------
#define PREP_T1 2048
#define PREP_T2 3584
#define PREP_T3 4608
#define PREP_NB 7328
#define WS_NB1 160
#define WS_NB2 512

__global__ void __launch_bounds__(256) k_prep(
    const float* __restrict__ x,
    const float* __restrict__ W1, const float* __restrict__ W2,
    const float* __restrict__ Wc1, const float* __restrict__ Wc2,
    const float* __restrict__ Wc3)
{
    __shared__ float t[32][33];
    int bi = blockIdx.x;
    int tid = threadIdx.x;
    int tx = tid & 31, ty = tid >> 5;

    if (bi < PREP_T1) {
        int idx = bi;
        int cB = (idx & 7) * 32;
        int nB = ((idx >> 3) & 31) * 32;
        int b  = idx >> 8;
        const float* xb = x + (size_t)b * XCH * NPTS;
#pragma unroll
        for (int i = ty; i < 32; i += 8)
            t[i][tx] = xb[(size_t)(HEADC + cB + i) * NPTS + nB + tx];
        __syncthreads();
        size_t base = ((size_t)b * NPTS + nB) * SHAPEC + cB;
#pragma unroll
        for (int i = ty; i < 32; i += 8) {
            float v = t[tx][i];
            h16 h, l; f16_split(v, h, l);
            g_xhi[base + (size_t)i * SHAPEC + tx] = h;
            g_xlo[base + (size_t)i * SHAPEC + tx] = l;
        }
    } else if (bi < PREP_T2) {
        int r = bi - PREP_T1;
        const float* src; h16 *hi, *lo; int K, OUT, e, k0, o0;
        if (r < 1024) {
            e = r >> 6; int q = r & 63;
            k0 = (q & 7) * 32; o0 = (q >> 3) * 32;
            src = W1; hi = g_e1hi; lo = g_e1lo; K = SHAPEC; OUT = SC_HID;
        } else {
            r -= 1024;
            e = r >> 5; int q = r & 31;
            k0 = (q & 7) * 32; o0 = (q >> 3) * 32;
            src = W2; hi = g_e2hi; lo = g_e2lo; K = SC_HID; OUT = SC_OUT;
        }
        const float* s = src + (size_t)e * K * OUT;
#pragma unroll
        for (int i = ty; i < 32; i += 8)
            t[i][tx] = s[(size_t)(k0 + i) * OUT + o0 + tx];
        __syncthreads();
        size_t base = (size_t)e * OUT * K + (size_t)o0 * K + k0;
#pragma unroll
        for (int i = ty; i < 32; i += 8) {
            float v = t[tx][i];
            h16 h, l; f16_split(v, h, l);
            hi[base + (size_t)i * K + tx] = h;
            lo[base + (size_t)i * K + tx] = l;
        }
    } else if (bi < PREP_T3) {
        int i = (bi - PREP_T2) * 256 + tid;      // 8192 * 32
        int p = i >> 5, s = i & 31;
        float v = 0.f;
        int col;
        if (s < 8) {
            int b = p >> 10, n = p & 1023;
            v = x[(size_t)b * XCH * NPTS + (size_t)s * NPTS + n];
            col = s;
        } else {
            col = 128 + s;
        }
        h16 h, l; f16_split(v, h, l);
        g_a0hi[(size_t)p * K0PAD + col] = h;
        g_a0lo[(size_t)p * K0PAD + col] = l;
    } else {
        int r = bi - PREP_T3;
        const float* w; h16 *hi, *lo; int Kin, Kpad, total, i;
        if (r < WS_NB1) {
            w = Wc1; hi = g_w1hi; lo = g_w1lo; Kin = 136; Kpad = K0PAD;
            total = C1OUT * K0PAD; i = r * 256 + tid;
        } else if (r < WS_NB1 + WS_NB2) {
            w = Wc2; hi = g_w2hi; lo = g_w2lo; Kin = C1OUT; Kpad = C1OUT;
            total = C2OUT * C1OUT; i = (r - WS_NB1) * 256 + tid;
        } else {
            w = Wc3; hi = g_w3hi; lo = g_w3lo; Kin = C2OUT; Kpad = C2OUT;
            total = C3OUT * C2OUT; i = (r - WS_NB1 - WS_NB2) * 256 + tid;
        }
        if (i >= total) return;
        int c = i / Kpad, k = i - c * Kpad;
        float v = (k < Kin) ? w[(size_t)c * Kin + k] : 0.f;
        h16 h, l; f16_split(v, h, l);
        hi[i] = h;
        lo[i] = l;
    }
}

// ---------------- 2. counting sort points by category (tiles of 64) ---------
__global__ void k_build(const int* __restrict__ cats) {
    __shared__ int cnt[NEXPERT];
    __shared__ int off[NEXPERT + 1];
    __shared__ int cur[NEXPERT];
    int tid = threadIdx.x;
    if (tid < NEXPERT) cnt[tid] = 0;
    __syncthreads();
    for (int i = tid; i < NPOINTS; i += blockDim.x) atomicAdd(&cnt[cats[i]], 1);
    __syncthreads();
    if (tid == 0) {
        int s = 0;
        for (int e = 0; e < NEXPERT; e++) { off[e] = s; s += cnt[e]; }
        off[NEXPERT] = s;
        int t = 0;
        for (int e = 0; e < NEXPERT; e++)
            for (int st = off[e]; st < off[e + 1]; st += ETILE) {
                g_tileExpert[t] = e;
                g_tileStart[t]  = st;
                g_tileLen[t]    = min(ETILE, off[e + 1] - st);
                t++;
            }
        g_nTiles = t;
    }
    __syncthreads();
    if (tid < NEXPERT) cur[tid] = off[tid];
    __syncthreads();
    for (int i = tid; i < NPOINTS; i += blockDim.x) {
        int pos = atomicAdd(&cur[cats[i]], 1);
        g_idx[pos] = i;
    }
}

// ---------------- 3. fused expert MLP on tensor cores (double-buffered) -----
#define ESM_A  0
#define ESM_B  20480
#define ESM_H  102400
#define ESMEM  184320

__global__ void __launch_bounds__(256) k_expert_mma(
    const float* __restrict__ b1g, const float* __restrict__ b2g)
{
    int t = blockIdx.x;
    if (t >= g_nTiles) return;
    int e = g_tileExpert[t], start = g_tileStart[t], len = g_tileLen[t];

    extern __shared__ char smraw[];
    __shared__ int pidx[ETILE];
    __shared__ int gidx[ETILE];

    int tid = threadIdx.x, lane = tid & 31, wid = tid >> 5;
    uint32_t sb = smem_u32(smraw);

    if (tid < ETILE) {
        int pi = (tid < len) ? g_idx[start + tid] : -1;
        pidx[tid] = pi;
        gidx[tid] = pi < 0 ? 0 : pi;
    }
    __syncthreads();

    const h16* w1h = g_e1hi + (size_t)e * SC_HID * SHAPEC;
    const h16* w1l = g_e1lo + (size_t)e * SC_HID * SHAPEC;
    const h16* w2h = g_e2hi + (size_t)e * SC_OUT * SC_HID;
    const h16* w2l = g_e2lo + (size_t)e * SC_OUT * SC_HID;

    auto loadS1 = [&](int ks, int st) {
#pragma unroll
        for (int r = 0; r < 2; r++) {
            int id = tid + r * 256;
            int half = id >> 8, idx = id & 255;
            int row = idx >> 2, ch = idx & 3;
            const h16* src = (half ? g_xlo : g_xhi)
                           + (size_t)gidx[row] * SHAPEC + ks * 32 + ch * 8;
            CP_ASYNC16(sb + ESM_A + st * 10240 + half * 5120 + (uint32_t)row * 80 + ch * 16, src);
        }
#pragma unroll
        for (int r = 0; r < 8; r++) {
            int id = tid + r * 256;
            int half = id >> 10, idx = id & 1023;
            int row = idx >> 2, ch = idx & 3;
            const h16* src = (half ? w1l : w1h)
                           + (size_t)row * SHAPEC + ks * 32 + ch * 8;
            CP_ASYNC16(sb + ESM_B + st * 40960 + half * 20480 + (uint32_t)row * 80 + ch * 16, src);
        }
        CP_COMMIT();
    };
    auto loadS2 = [&](int ks, int st) {
#pragma unroll
        for (int r = 0; r < 4; r++) {
            int id = tid + r * 256;
            int half = id >> 9, idx = id & 511;
            int row = idx >> 2, ch = idx & 3;
            const h16* src = (half ? w2l : w2h)
                           + (size_t)row * SC_HID + ks * 32 + ch * 8;
            CP_ASYNC16(sb + ESM_B + st * 20480 + half * 10240 + (uint32_t)row * 80 + ch * 16, src);
        }
        CP_COMMIT();
    };

    // ======== stage 1: h[64,256] = relu(A @ W1T + b1) ====
    {
        float acc[4][4][4];
#pragma unroll
        for (int a = 0; a < 4; a++)
#pragma unroll
            for (int b = 0; b < 4; b++)
#pragma unroll
                for (int c = 0; c < 4; c++) acc[a][b][c] = 0.f;

        uint32_t rowA = (uint32_t)(lane & 15) * 80 + (lane >> 4) * 16;
        uint32_t rowB = (uint32_t)(wid * 32 + (lane & 15)) * 80 + (lane >> 4) * 16;

        loadS1(0, 0);
        for (int ks = 0; ks < 8; ks++) {
            CP_WAIT0();
            __syncthreads();
            if (ks + 1 < 8) loadS1(ks + 1, (ks + 1) & 1);
            uint32_t sba = sb + ESM_A + (ks & 1) * 10240;
            uint32_t sbb = sb + ESM_B + (ks & 1) * 40960;
#pragma unroll
            for (int s = 0; s < 2; s++) {
                uint32_t aH[4][4], aL[4][4], bH[2][4], bL[2][4];
#pragma unroll
                for (int mf = 0; mf < 4; mf++) {
                    uint32_t ad = sba + rowA + (uint32_t)mf * (16 * 80) + s * 32;
                    LDSM4(aH[mf], ad);
                    LDSM4(aL[mf], ad + 5120);
                }
#pragma unroll
                for (int p = 0; p < 2; p++) {
                    uint32_t bd = sbb + rowB + (uint32_t)p * (16 * 80) + s * 32;
                    LDSM4(bH[p], bd);
                    LDSM4(bL[p], bd + 20480);
                }
#pragma unroll
                for (int mf = 0; mf < 4; mf++)
#pragma unroll
                    for (int nf = 0; nf < 4; nf++) {
                        int p = nf >> 1, sel = nf & 1;
                        mma_f32(acc[mf][nf], aH[mf], bH[p][sel], bH[p][sel + 2]);
                        mma_f32(acc[mf][nf], aH[mf], bL[p][sel], bL[p][sel + 2]);
                        mma_f32(acc[mf][nf], aL[mf], bH[p][sel], bH[p][sel + 2]);
                    }
            }
            __syncthreads();
        }

        loadS2(0, 0);

        const float* b1 = b1g + e * SC_HID;
#pragma unroll
        for (int mf = 0; mf < 4; mf++) {
            int row = mf * 16 + (lane >> 2);
#pragma unroll
            for (int nf = 0; nf < 4; nf++) {
                int col = wid * 32 + nf * 8 + 2 * (lane & 3);
                float b0v = b1[col], b1v = b1[col + 1];
                float v0 = fmaxf(acc[mf][nf][0] + b0v, 0.f);
                float v1 = fmaxf(acc[mf][nf][1] + b1v, 0.f);
                float v2 = fmaxf(acc[mf][nf][2] + b0v, 0.f);
                float v3 = fmaxf(acc[mf][nf][3] + b1v, 0.f);
                int ks = col >> 5, cw = col & 31;
                uint32_t off = (uint32_t)ks * 5120 + (uint32_t)row * 80 + cw * 2;
                h16 h0, l0, h1, l1;
                f16_split(v0, h0, l0); f16_split(v1, h1, l1);
                *(uint32_t*)(smraw + ESM_H + off)         = pack2h(h0, h1);
                *(uint32_t*)(smraw + ESM_H + 40960 + off) = pack2h(l0, l1);
                f16_split(v2, h0, l0); f16_split(v3, h1, l1);
                *(uint32_t*)(smraw + ESM_H + off + 8 * 80)         = pack2h(h0, h1);
                *(uint32_t*)(smraw + ESM_H + 40960 + off + 8 * 80) = pack2h(l0, l1);
            }
        }
    }
    __syncthreads();

    // ======== stage 2: o[64,128] = h @ W2T + b2 ====
    {
        int warp_m = wid & 1, warp_n = wid >> 1;
        float acc[2][4][4];
#pragma unroll
        for (int a = 0; a < 2; a++)
#pragma unroll
            for (int b = 0; b < 4; b++)
#pragma unroll
                for (int c = 0; c < 4; c++) acc[a][b][c] = 0.f;

        uint32_t rowA = (uint32_t)(warp_m * 32 + (lane & 15)) * 80 + (lane >> 4) * 16;
        uint32_t rowB = (uint32_t)(warp_n * 32 + (lane & 15)) * 80 + (lane >> 4) * 16;

        for (int ks = 0; ks < 8; ks++) {
            CP_WAIT0();
            __syncthreads();
            if (ks + 1 < 8) loadS2(ks + 1, (ks + 1) & 1);
            uint32_t hbase = sb + ESM_H + (uint32_t)ks * 5120;
            uint32_t sbb = sb + ESM_B + (ks & 1) * 20480;
#pragma unroll
            for (int s = 0; s < 2; s++) {
                uint32_t aH[2][4], aL[2][4], bH[2][4], bL[2][4];
#pragma unroll
                for (int mf = 0; mf < 2; mf++) {
                    uint32_t ad = hbase + rowA + (uint32_t)mf * (16 * 80) + s * 32;
                    LDSM4(aH[mf], ad);
                    LDSM4(aL[mf], ad + 40960);
                }
#pragma unroll
                for (int p = 0; p < 2; p++) {
                    uint32_t bd = sbb + rowB + (uint32_t)p * (16 * 80) + s * 32;
                    LDSM4(bH[p], bd);
                    LDSM4(bL[p], bd + 10240);
                }
#pragma unroll
                for (int mf = 0; mf < 2; mf++)
#pragma unroll
                    for (int nf = 0; nf < 4; nf++) {
                        int p = nf >> 1, sel = nf & 1;
                        mma_f32(acc[mf][nf], aH[mf], bH[p][sel], bH[p][sel + 2]);
                        mma_f32(acc[mf][nf], aH[mf], bL[p][sel], bL[p][sel + 2]);
                        mma_f32(acc[mf][nf], aL[mf], bH[p][sel], bH[p][sel + 2]);
                    }
            }
            __syncthreads();
        }

        const float* b2 = b2g + e * SC_OUT;
#pragma unroll
        for (int mf = 0; mf < 2; mf++) {
            int row = warp_m * 32 + mf * 16 + (lane >> 2);
#pragma unroll
            for (int nf = 0; nf < 4; nf++) {
                int col = warp_n * 32 + nf * 8 + 2 * (lane & 3);
                float b0v = b2[col], b1v = b2[col + 1];
                float v0 = acc[mf][nf][0] + b0v, v1 = acc[mf][nf][1] + b1v;
                float v2 = acc[mf][nf][2] + b0v, v3 = acc[mf][nf][3] + b1v;
                int pi0 = pidx[row], pi1 = pidx[row + 8];
                if (pi0 >= 0) {
                    h16 h0, l0, h1, l1;
                    f16_split(v0, h0, l0); f16_split(v1, h1, l1);
                    *(uint32_t*)(g_a0hi + (size_t)pi0 * K0PAD + HEADC + col) = pack2h(h0, h1);
                    *(uint32_t*)(g_a0lo + (size_t)pi0 * K0PAD + HEADC + col) = pack2h(l0, l1);
                }
                if (pi1 >= 0) {
                    h16 h0, l0, h1, l1;
                    f16_split(v2, h0, l0); f16_split(v3, h1, l1);
                    *(uint32_t*)(g_a0hi + (size_t)pi1 * K0PAD + HEADC + col) = pack2h(h0, h1);
                    *(uint32_t*)(g_a0lo + (size_t)pi1 * K0PAD + HEADC + col) = pack2h(l0, l1);
                }
            }
        }
    }
}

// ---------------- 4. f16 mma GEMM: 64x128 tiles, 2 CTAs/SM ----------------
// stage: AH 5120 | AL 5120 | BH 10240 | BL 10240 = 30720 B; 2 stages.
#define GSTG  30720
#define GSMEM (2 * GSTG)

template <int KTOT, int RELU, int SPLIT>
__global__ void __launch_bounds__(256, 2) gemm_mma(
    const h16* __restrict__ aHi, const h16* __restrict__ aLo,
    const h16* __restrict__ wHi, const h16* __restrict__ wLo,
    const float* __restrict__ bias,
    h16* __restrict__ oHi, h16* __restrict__ oLo, int KOUT)
{
    extern __shared__ char smraw[];
    const int NK = KTOT / 32;
    int tid = threadIdx.x, lane = tid & 31, wid = tid >> 5;
    int warp_m = wid & 1, warp_n = wid >> 1;     // 2 x 4 warps, warp tile 32x32
    int m0 = blockIdx.x * 64, c0 = blockIdx.y * 128;

    uint32_t smBase = smem_u32(smraw);
    uint32_t rowA = (uint32_t)(warp_m * 32 + (lane & 15)) * 80 + (lane >> 4) * 16;
    uint32_t rowB = (uint32_t)(warp_n * 32 + (lane & 15)) * 80 + (lane >> 4) * 16;

    float acc[2][4][4];
#pragma unroll
    for (int a = 0; a < 2; a++)
#pragma unroll
        for (int b = 0; b < 4; b++)
#pragma unroll
            for (int c = 0; c < 4; c++) acc[a][b][c] = 0.f;

    auto loadStage = [&](int ks, int st) {
        uint32_t sbs = smBase + st * GSTG;
        // A: 512 chunks (hi+lo, 64 rows x 4)
#pragma unroll
        for (int i = 0; i < 2; i++) {
            int c = tid + i * 256;
            int half = c >> 8, idx = c & 255;
            int row = idx >> 2, ch = idx & 3;
            const h16* src = (half ? aLo : aHi) + (size_t)(m0 + row) * KTOT + ks * 32 + ch * 8;
            CP_ASYNC16(sbs + half * 5120 + (uint32_t)row * 80 + ch * 16, src);
        }
        // B: 1024 chunks (hi+lo, 128 rows x 4)
#pragma unroll
        for (int i = 0; i < 4; i++) {
            int c = tid + i * 256;
            int half = c >> 9, idx = c & 511;
            int row = idx >> 2, ch = idx & 3;
            const h16* src = (half ? wLo : wHi) + (size_t)(c0 + row) * KTOT + ks * 32 + ch * 8;
            CP_ASYNC16(sbs + 10240 + half * 10240 + (uint32_t)row * 80 + ch * 16, src);
        }
        CP_COMMIT();
    };

    loadStage(0, 0);
    for (int ks = 0; ks < NK; ks++) {
        if (ks + 1 < NK) { loadStage(ks + 1, (ks + 1) & 1); CP_WAIT1(); }
        else             { CP_WAIT0(); }
        __syncthreads();

        uint32_t sbs = smBase + (ks & 1) * GSTG;
#pragma unroll
        for (int s = 0; s < 2; s++) {
            uint32_t aH[2][4], aL[2][4], bH[2][4], bL[2][4];
#pragma unroll
            for (int mf = 0; mf < 2; mf++) {
                uint32_t ad = sbs + rowA + (uint32_t)mf * (16 * 80) + s * 32;
                LDSM4(aH[mf], ad);
                LDSM4(aL[mf], ad + 5120);
            }
#pragma unroll
            for (int p = 0; p < 2; p++) {
                uint32_t bd = sbs + 10240 + rowB + (uint32_t)p * (16 * 80) + s * 32;
                LDSM4(bH[p], bd);
                LDSM4(bL[p], bd + 10240);
            }
#pragma unroll
            for (int mf = 0; mf < 2; mf++)
#pragma unroll
                for (int nf = 0; nf < 4; nf++) {
                    int p = nf >> 1, sel = nf & 1;
                    mma_f32(acc[mf][nf], aH[mf], bH[p][sel], bH[p][sel + 2]);
                    mma_f32(acc[mf][nf], aH[mf], bL[p][sel], bL[p][sel + 2]);
                    mma_f32(acc[mf][nf], aL[mf], bH[p][sel], bH[p][sel + 2]);
                }
        }
        __syncthreads();
    }

    if (SPLIT) {
#pragma unroll
        for (int mf = 0; mf < 2; mf++) {
            int row = m0 + warp_m * 32 + mf * 16 + (lane >> 2);
#pragma unroll
            for (int nf = 0; nf < 4; nf++) {
                int col = c0 + warp_n * 32 + nf * 8 + 2 * (lane & 3);
                float b0v = bias[col], b1v = bias[col + 1];
                float v0 = acc[mf][nf][0] + b0v, v1 = acc[mf][nf][1] + b1v;
                float v2 = acc[mf][nf][2] + b0v, v3 = acc[mf][nf][3] + b1v;
                if (RELU) {
                    v0 = fmaxf(v0, 0.f); v1 = fmaxf(v1, 0.f);
                    v2 = fmaxf(v2, 0.f); v3 = fmaxf(v3, 0.f);
                }
                h16 h0, l0, h1, l1;
                f16_split(v0, h0, l0); f16_split(v1, h1, l1);
                *(uint32_t*)(oHi + (size_t)row * KOUT + col) = pack2h(h0, h1);
                *(uint32_t*)(oLo + (size_t)row * KOUT + col) = pack2h(l0, l1);
                f16_split(v2, h0, l0); f16_split(v3, h1, l1);
                *(uint32_t*)(oHi + (size_t)(row + 8) * KOUT + col) = pack2h(h0, h1);
                *(uint32_t*)(oLo + (size_t)(row + 8) * KOUT + col) = pack2h(l0, l1);
            }
        }
    } else {
        // ---- fused max-pool epilogue: partial max over 64 rows ----
        __syncthreads();
        float* pm = (float*)smraw;               // [2][128]
#pragma unroll
        for (int nf = 0; nf < 4; nf++) {
            float c0m = -FLT_MAX, c1m = -FLT_MAX;
#pragma unroll
            for (int mf = 0; mf < 2; mf++) {
                int col = c0 + warp_n * 32 + nf * 8 + 2 * (lane & 3);
                float b0v = bias[col], b1v = bias[col + 1];
                c0m = fmaxf(c0m, fmaxf(acc[mf][nf][0] + b0v, acc[mf][nf][2] + b0v));
                c1m = fmaxf(c1m, fmaxf(acc[mf][nf][1] + b1v, acc[mf][nf][3] + b1v));
            }
#pragma unroll
            for (int o = 4; o < 32; o <<= 1) {
                c0m = fmaxf(c0m, __shfl_xor_sync(0xFFFFFFFFu, c0m, o));
                c1m = fmaxf(c1m, __shfl_xor_sync(0xFFFFFFFFu, c1m, o));
            }
            if (lane < 4) {
                int cc = warp_n * 32 + nf * 8 + 2 * lane;
                pm[warp_m * 128 + cc]     = c0m;
                pm[warp_m * 128 + cc + 1] = c1m;
            }
        }
        __syncthreads();
        if (tid < 64) {
            int cc = tid * 2;
            float m0v = fmaxf(pm[cc],     pm[128 + cc]);
            float m1v = fmaxf(pm[cc + 1], pm[128 + cc + 1]);
            int b = m0 >> 10, part = (m0 >> 6) & (NPART - 1);
            *(float2*)(g_part + (size_t)(b * NPART + part) * C3OUT + c0 + cc)
                = make_float2(m0v, m1v);
        }
    }
}

// ---------------- 5. max pool final stage ----------------
__global__ void k_poolB(float* __restrict__ extra, int we) {
    int i = blockIdx.x * 256 + threadIdx.x;   // 8192
    float m = -FLT_MAX;
    int b = i >> 10, c = i & 1023;
#pragma unroll
    for (int part = 0; part < NPART; part++)
        m = fmaxf(m, g_part[(b * NPART + part) * C3OUT + c]);
    g_lat[i] = m;
    if (we) extra[i] = m;
}

// ---------------- 6. decoder MLP (16 cols x 16 K-slices per block) ----------
template <int RELU>
__global__ void __launch_bounds__(256) mlp8(
    const float* __restrict__ A, const float* __restrict__ W,
    const float* __restrict__ bias, float* __restrict__ Out,
    int K, int N)
{
    extern __shared__ float Ash[];
    __shared__ float red[256 * 8];
    int tid = threadIdx.x;
    for (int i = tid; i < 8 * K / 4; i += 256)
        ((float4*)Ash)[i] = ((const float4*)A)[i];
    __syncthreads();

    int col   = blockIdx.x * 16 + (tid & 15);
    int slice = tid >> 4;                 // 16 slices
    int kPer  = K >> 4;
    int k0    = slice * kPer;

    float acc[8];
#pragma unroll
    for (int bb = 0; bb < 8; bb++) acc[bb] = 0.f;

    for (int k = k0; k < k0 + kPer; k += 4) {
        float w0 = W[(size_t)(k + 0) * N + col];
        float w1 = W[(size_t)(k + 1) * N + col];
        float w2 = W[(size_t)(k + 2) * N + col];
        float w3 = W[(size_t)(k + 3) * N + col];
#pragma unroll
        for (int bb = 0; bb < 8; bb++) {
            float4 a4 = ((const float4*)(Ash + bb * K))[k >> 2];
            acc[bb] = fmaf(a4.x, w0, acc[bb]);
            acc[bb] = fmaf(a4.y, w1, acc[bb]);
            acc[bb] = fmaf(a4.z, w2, acc[bb]);
            acc[bb] = fmaf(a4.w, w3, acc[bb]);
        }
    }
#pragma unroll
    for (int bb = 0; bb < 8; bb++) red[tid * 8 + bb] = acc[bb];
    __syncthreads();
    if (tid < 16) {
        float bsv = bias[col];
#pragma unroll
        for (int bb = 0; bb < 8; bb++) {
            float v = bsv;
#pragma unroll
            for (int s = 0; s < 16; s++)
                v += red[(tid + s * 16) * 8 + bb];
            if (RELU) v = fmaxf(v, 0.f);
            Out[(size_t)bb * N + col] = v;
        }
    }
}

// ---------------- launch ----------------
extern "C" void kernel_launch(void* const* d_in, const int* in_sizes, int n_in,
                              void* d_out, int out_size) {
    const float* x    = (const float*)d_in[0];
    const int*   cats = (const int*)  d_in[1];
    const float* W1   = (const float*)d_in[2];
    const float* b1   = (const float*)d_in[3];
    const float* W2   = (const float*)d_in[4];
    const float* b2   = (const float*)d_in[5];
    const float* Wc1  = (const float*)d_in[6];
    const float* bc1  = (const float*)d_in[7];
    const float* Wc2  = (const float*)d_in[8];
    const float* bc2  = (const float*)d_in[9];
    const float* Wc3  = (const float*)d_in[10];
    const float* bc3  = (const float*)d_in[11];
    const float* Wd1  = (const float*)d_in[12];
    const float* bd1  = (const float*)d_in[13];
    const float* Wd2  = (const float*)d_in[14];
    const float* bd2  = (const float*)d_in[15];
    const float* Wd3  = (const float*)d_in[16];
    const float* bd3  = (const float*)d_in[17];
    float* out = (float*)d_out;

    cudaFuncSetAttribute(k_expert_mma, cudaFuncAttributeMaxDynamicSharedMemorySize, ESMEM);
    cudaFuncSetAttribute(mlp8<1>,  cudaFuncAttributeMaxDynamicSharedMemorySize, 65536);
    cudaFuncSetAttribute(mlp8<0>,  cudaFuncAttributeMaxDynamicSharedMemorySize, 65536);
    cudaFuncSetAttribute(gemm_mma<K0PAD, 1, 1>, cudaFuncAttributeMaxDynamicSharedMemorySize, GSMEM);
    cudaFuncSetAttribute(gemm_mma<C1OUT, 1, 1>, cudaFuncAttributeMaxDynamicSharedMemorySize, GSMEM);
    cudaFuncSetAttribute(gemm_mma<C2OUT, 0, 0>, cudaFuncAttributeMaxDynamicSharedMemorySize, GSMEM);

    h16 *p_a0h, *p_a0l, *p_a1h, *p_a1l, *p_a2h, *p_a2l;
    h16 *p_w1h, *p_w1l, *p_w2h, *p_w2l, *p_w3h, *p_w3l;
    float *p_lat, *p_d1, *p_d2;
    cudaGetSymbolAddress((void**)&p_a0h, g_a0hi);
    cudaGetSymbolAddress((void**)&p_a0l, g_a0lo);
    cudaGetSymbolAddress((void**)&p_a1h, g_a1hi);
    cudaGetSymbolAddress((void**)&p_a1l, g_a1lo);
    cudaGetSymbolAddress((void**)&p_a2h, g_a2hi);
    cudaGetSymbolAddress((void**)&p_a2l, g_a2lo);
    cudaGetSymbolAddress((void**)&p_w1h, g_w1hi);
    cudaGetSymbolAddress((void**)&p_w1l, g_w1lo);
    cudaGetSymbolAddress((void**)&p_w2h, g_w2hi);
    cudaGetSymbolAddress((void**)&p_w2l, g_w2lo);
    cudaGetSymbolAddress((void**)&p_w3h, g_w3hi);
    cudaGetSymbolAddress((void**)&p_w3l, g_w3lo);
    cudaGetSymbolAddress((void**)&p_lat, g_lat);
    cudaGetSymbolAddress((void**)&p_d1,  g_d1);
    cudaGetSymbolAddress((void**)&p_d2,  g_d2);

    // prep, build, expert, conv gemms (gemm1 lands in the ncu window)
    k_prep<<<PREP_NB, 256>>>(x, W1, W2, Wc1, Wc2, Wc3);
    k_build<<<1, 1024>>>(cats);
    k_expert_mma<<<MAXTILES, 256, ESMEM>>>(b1, b2);

    gemm_mma<K0PAD, 1, 1><<<dim3(128, C1OUT / 128), 256, GSMEM>>>(
        p_a0h, p_a0l, p_w1h, p_w1l, bc1, p_a1h, p_a1l, C1OUT);
    gemm_mma<C1OUT, 1, 1><<<dim3(128, C2OUT / 128), 256, GSMEM>>>(
        p_a1h, p_a1l, p_w2h, p_w2l, bc2, p_a2h, p_a2l, C2OUT);
    gemm_mma<C2OUT, 0, 0><<<dim3(128, C3OUT / 128), 256, GSMEM>>>(
        p_a2h, p_a2l, p_w3h, p_w3l, bc3, (h16*)0, (h16*)0, C3OUT);

    // max pool final + latent
    int write_extra = (out_size >= 65536 + 8192) ? 1 : 0;
    k_poolB<<<NPOINTS / 256, 256>>>(out + 65536, write_extra);

    // decoder MLP
    mlp8<1><<<DEC1 / 16, 256, 8 * DEC1 * 4>>>(p_lat, Wd1, bd1, p_d1, DEC1, DEC1);
    mlp8<1><<<DEC2 / 16, 256, 8 * DEC1 * 4>>>(p_d1,  Wd2, bd2, p_d2, DEC1, DEC2);
    mlp8<0><<<DEC3 / 16, 256, 8 * DEC2 * 4>>>(p_d2,  Wd3, bd3, out,  DEC2, DEC3);
}

// round 9
// speedup vs baseline: 1.0398x; 1.0398x over previous
#include <cuda_runtime.h>
#include <cuda_fp16.h>
#include <float.h>
#include <stdint.h>

// ---------------- problem constants ----------------
#define BATCH      8
#define NPTS       1024
#define NPOINTS    (BATCH * NPTS)        // 8192
#define HEADC      8
#define SHAPEC     256
#define XCH        (HEADC + SHAPEC)      // 264
#define NEXPERT    16
#define SC_HID     256
#define SC_OUT     128
#define K0PAD      160                   // 136 padded to 160
#define C1OUT      256
#define C2OUT      512
#define C3OUT      1024
#define DEC1       1024
#define DEC2       2048
#define DEC3       8192
#define ETILE      64
#define MAXTILES   (NPOINTS / ETILE + NEXPERT)   // 144
#define NPART      16                    // pool partials per batch

typedef __half h16;

// ---------------- scratch (device globals; no runtime alloc) ----------------
__device__ __align__(256) h16 g_xhi[NPOINTS * SHAPEC];
__device__ __align__(256) h16 g_xlo[NPOINTS * SHAPEC];
__device__ __align__(256) h16 g_a0hi[NPOINTS * K0PAD];
__device__ __align__(256) h16 g_a0lo[NPOINTS * K0PAD];
__device__ __align__(256) h16 g_a1hi[NPOINTS * C1OUT];
__device__ __align__(256) h16 g_a1lo[NPOINTS * C1OUT];
__device__ __align__(256) h16 g_a2hi[NPOINTS * C2OUT];
__device__ __align__(256) h16 g_a2lo[NPOINTS * C2OUT];
__device__ __align__(256) h16 g_w1hi[C1OUT * K0PAD];
__device__ __align__(256) h16 g_w1lo[C1OUT * K0PAD];
__device__ __align__(256) h16 g_w2hi[C2OUT * C1OUT];
__device__ __align__(256) h16 g_w2lo[C2OUT * C1OUT];
__device__ __align__(256) h16 g_w3hi[C3OUT * C2OUT];
__device__ __align__(256) h16 g_w3lo[C3OUT * C2OUT];
__device__ __align__(256) h16 g_e1hi[NEXPERT * SC_HID * SHAPEC];
__device__ __align__(256) h16 g_e1lo[NEXPERT * SC_HID * SHAPEC];
__device__ __align__(256) h16 g_e2hi[NEXPERT * SC_OUT * SC_HID];
__device__ __align__(256) h16 g_e2lo[NEXPERT * SC_OUT * SC_HID];
__device__ float g_part[BATCH * NPART * C3OUT];
__device__ float g_lat[BATCH * C3OUT];
__device__ float g_d1[BATCH * DEC1];
__device__ float g_d2[BATCH * DEC2];
__device__ int   g_idx[NPOINTS];
__device__ int   g_tileExpert[MAXTILES];
__device__ int   g_tileStart[MAXTILES];
__device__ int   g_tileLen[MAXTILES];
__device__ int   g_nTiles;

// ---------------- ptx helpers (sm_80-safe) ----------------
__device__ __forceinline__ uint32_t smem_u32(const void* p) {
    uint32_t a;
    asm("{ .reg .u64 t; cvta.to.shared.u64 t, %1; cvt.u32.u64 %0, t; }" : "=r"(a) : "l"(p));
    return a;
}
#define CP_ASYNC16(dst, src) \
    asm volatile("cp.async.cg.shared.global [%0], [%1], 16;" :: "r"(dst), "l"(src))
#define CP_COMMIT() asm volatile("cp.async.commit_group;" ::: "memory")
#define CP_WAIT0()  asm volatile("cp.async.wait_group 0;" ::: "memory")
#define CP_WAIT1()  asm volatile("cp.async.wait_group 1;" ::: "memory")

#define LDSM4(r, addr) \
    asm volatile("ldmatrix.sync.aligned.m8n8.x4.shared.b16 {%0,%1,%2,%3}, [%4];" \
        : "=r"((r)[0]), "=r"((r)[1]), "=r"((r)[2]), "=r"((r)[3]) : "r"(addr))

__device__ __forceinline__ void mma_f32(float* d, const uint32_t* a,
                                        uint32_t b0, uint32_t b1) {
    asm volatile(
        "mma.sync.aligned.m16n8k16.row.col.f32.f16.f16.f32 "
        "{%0,%1,%2,%3}, {%4,%5,%6,%7}, {%8,%9}, {%0,%1,%2,%3};"
        : "+f"(d[0]), "+f"(d[1]), "+f"(d[2]), "+f"(d[3])
        : "r"(a[0]), "r"(a[1]), "r"(a[2]), "r"(a[3]), "r"(b0), "r"(b1));
}

__device__ __forceinline__ void f16_split(float v, h16& h, h16& l) {
    h = __float2half_rn(v);
    l = __float2half_rn(v - __half2float(h));
}
__device__ __forceinline__ uint32_t pack2h(h16 a, h16 b) {
    __half2 t; t.x = a; t.y = b;
    return *(uint32_t*)&t;
}

// ---------------- 1. fused prep: transpose | tsplit | head | wsplit ---------
#define PREP_T1 2048
#define PREP_T2 3584
#define PREP_T3 4608
#define PREP_NB 7328
#define WS_NB1 160
#define WS_NB2 512

__global__ void __launch_bounds__(256) k_prep(
    const float* __restrict__ x,
    const float* __restrict__ W1, const float* __restrict__ W2,
    const float* __restrict__ Wc1, const float* __restrict__ Wc2,
    const float* __restrict__ Wc3)
{
    __shared__ float t[32][33];
    int bi = blockIdx.x;
    int tid = threadIdx.x;
    int tx = tid & 31, ty = tid >> 5;

    if (bi < PREP_T1) {
        int idx = bi;
        int cB = (idx & 7) * 32;
        int nB = ((idx >> 3) & 31) * 32;
        int b  = idx >> 8;
        const float* xb = x + (size_t)b * XCH * NPTS;
#pragma unroll
        for (int i = ty; i < 32; i += 8)
            t[i][tx] = xb[(size_t)(HEADC + cB + i) * NPTS + nB + tx];
        __syncthreads();
        size_t base = ((size_t)b * NPTS + nB) * SHAPEC + cB;
#pragma unroll
        for (int i = ty; i < 32; i += 8) {
            float v = t[tx][i];
            h16 h, l; f16_split(v, h, l);
            g_xhi[base + (size_t)i * SHAPEC + tx] = h;
            g_xlo[base + (size_t)i * SHAPEC + tx] = l;
        }
    } else if (bi < PREP_T2) {
        int r = bi - PREP_T1;
        const float* src; h16 *hi, *lo; int K, OUT, e, k0, o0;
        if (r < 1024) {
            e = r >> 6; int q = r & 63;
            k0 = (q & 7) * 32; o0 = (q >> 3) * 32;
            src = W1; hi = g_e1hi; lo = g_e1lo; K = SHAPEC; OUT = SC_HID;
        } else {
            r -= 1024;
            e = r >> 5; int q = r & 31;
            k0 = (q & 7) * 32; o0 = (q >> 3) * 32;
            src = W2; hi = g_e2hi; lo = g_e2lo; K = SC_HID; OUT = SC_OUT;
        }
        const float* s = src + (size_t)e * K * OUT;
#pragma unroll
        for (int i = ty; i < 32; i += 8)
            t[i][tx] = s[(size_t)(k0 + i) * OUT + o0 + tx];
        __syncthreads();
        size_t base = (size_t)e * OUT * K + (size_t)o0 * K + k0;
#pragma unroll
        for (int i = ty; i < 32; i += 8) {
            float v = t[tx][i];
            h16 h, l; f16_split(v, h, l);
            hi[base + (size_t)i * K + tx] = h;
            lo[base + (size_t)i * K + tx] = l;
        }
    } else if (bi < PREP_T3) {
        int i = (bi - PREP_T2) * 256 + tid;
        int p = i >> 5, s = i & 31;
        float v = 0.f;
        int col;
        if (s < 8) {
            int b = p >> 10, n = p & 1023;
            v = x[(size_t)b * XCH * NPTS + (size_t)s * NPTS + n];
            col = s;
        } else {
            col = 128 + s;
        }
        h16 h, l; f16_split(v, h, l);
        g_a0hi[(size_t)p * K0PAD + col] = h;
        g_a0lo[(size_t)p * K0PAD + col] = l;
    } else {
        int r = bi - PREP_T3;
        const float* w; h16 *hi, *lo; int Kin, Kpad, total, i;
        if (r < WS_NB1) {
            w = Wc1; hi = g_w1hi; lo = g_w1lo; Kin = 136; Kpad = K0PAD;
            total = C1OUT * K0PAD; i = r * 256 + tid;
        } else if (r < WS_NB1 + WS_NB2) {
            w = Wc2; hi = g_w2hi; lo = g_w2lo; Kin = C1OUT; Kpad = C1OUT;
            total = C2OUT * C1OUT; i = (r - WS_NB1) * 256 + tid;
        } else {
            w = Wc3; hi = g_w3hi; lo = g_w3lo; Kin = C2OUT; Kpad = C2OUT;
            total = C3OUT * C2OUT; i = (r - WS_NB1 - WS_NB2) * 256 + tid;
        }
        if (i >= total) return;
        int c = i / Kpad, k = i - c * Kpad;
        float v = (k < Kin) ? w[(size_t)c * Kin + k] : 0.f;
        h16 h, l; f16_split(v, h, l);
        hi[i] = h;
        lo[i] = l;
    }
}

// ---------------- 2. counting sort points by category (tiles of 64) ---------
__global__ void k_build(const int* __restrict__ cats) {
    __shared__ int cnt[NEXPERT];
    __shared__ int off[NEXPERT + 1];
    __shared__ int cur[NEXPERT];
    int tid = threadIdx.x;
    if (tid < NEXPERT) cnt[tid] = 0;
    __syncthreads();
    for (int i = tid; i < NPOINTS; i += blockDim.x) atomicAdd(&cnt[cats[i]], 1);
    __syncthreads();
    if (tid == 0) {
        int s = 0;
        for (int e = 0; e < NEXPERT; e++) { off[e] = s; s += cnt[e]; }
        off[NEXPERT] = s;
        int t = 0;
        for (int e = 0; e < NEXPERT; e++)
            for (int st = off[e]; st < off[e + 1]; st += ETILE) {
                g_tileExpert[t] = e;
                g_tileStart[t]  = st;
                g_tileLen[t]    = min(ETILE, off[e + 1] - st);
                t++;
            }
        g_nTiles = t;
    }
    __syncthreads();
    if (tid < NEXPERT) cur[tid] = off[tid];
    __syncthreads();
    for (int i = tid; i < NPOINTS; i += blockDim.x) {
        int pos = atomicAdd(&cur[cats[i]], 1);
        g_idx[pos] = i;
    }
}

// ---------------- 3. fused expert MLP on tensor cores (double-buffered) -----
#define ESM_A  0
#define ESM_B  20480
#define ESM_H  102400
#define ESMEM  184320

__global__ void __launch_bounds__(256) k_expert_mma(
    const float* __restrict__ b1g, const float* __restrict__ b2g)
{
    int t = blockIdx.x;
    if (t >= g_nTiles) return;
    int e = g_tileExpert[t], start = g_tileStart[t], len = g_tileLen[t];

    extern __shared__ char smraw[];
    __shared__ int pidx[ETILE];
    __shared__ int gidx[ETILE];

    int tid = threadIdx.x, lane = tid & 31, wid = tid >> 5;
    uint32_t sb = smem_u32(smraw);

    if (tid < ETILE) {
        int pi = (tid < len) ? g_idx[start + tid] : -1;
        pidx[tid] = pi;
        gidx[tid] = pi < 0 ? 0 : pi;
    }
    __syncthreads();

    const h16* w1h = g_e1hi + (size_t)e * SC_HID * SHAPEC;
    const h16* w1l = g_e1lo + (size_t)e * SC_HID * SHAPEC;
    const h16* w2h = g_e2hi + (size_t)e * SC_OUT * SC_HID;
    const h16* w2l = g_e2lo + (size_t)e * SC_OUT * SC_HID;

    auto loadS1 = [&](int ks, int st) {
#pragma unroll
        for (int r = 0; r < 2; r++) {
            int id = tid + r * 256;
            int half = id >> 8, idx = id & 255;
            int row = idx >> 2, ch = idx & 3;
            const h16* src = (half ? g_xlo : g_xhi)
                           + (size_t)gidx[row] * SHAPEC + ks * 32 + ch * 8;
            CP_ASYNC16(sb + ESM_A + st * 10240 + half * 5120 + (uint32_t)row * 80 + ch * 16, src);
        }
#pragma unroll
        for (int r = 0; r < 8; r++) {
            int id = tid + r * 256;
            int half = id >> 10, idx = id & 1023;
            int row = idx >> 2, ch = idx & 3;
            const h16* src = (half ? w1l : w1h)
                           + (size_t)row * SHAPEC + ks * 32 + ch * 8;
            CP_ASYNC16(sb + ESM_B + st * 40960 + half * 20480 + (uint32_t)row * 80 + ch * 16, src);
        }
        CP_COMMIT();
    };
    auto loadS2 = [&](int ks, int st) {
#pragma unroll
        for (int r = 0; r < 4; r++) {
            int id = tid + r * 256;
            int half = id >> 9, idx = id & 511;
            int row = idx >> 2, ch = idx & 3;
            const h16* src = (half ? w2l : w2h)
                           + (size_t)row * SC_HID + ks * 32 + ch * 8;
            CP_ASYNC16(sb + ESM_B + st * 20480 + half * 10240 + (uint32_t)row * 80 + ch * 16, src);
        }
        CP_COMMIT();
    };

    // ======== stage 1: h[64,256] = relu(A @ W1T + b1) ====
    {
        float acc[4][4][4];
#pragma unroll
        for (int a = 0; a < 4; a++)
#pragma unroll
            for (int b = 0; b < 4; b++)
#pragma unroll
                for (int c = 0; c < 4; c++) acc[a][b][c] = 0.f;

        uint32_t rowA = (uint32_t)(lane & 15) * 80 + (lane >> 4) * 16;
        uint32_t rowB = (uint32_t)(wid * 32 + (lane & 15)) * 80 + (lane >> 4) * 16;

        loadS1(0, 0);
        for (int ks = 0; ks < 8; ks++) {
            CP_WAIT0();
            __syncthreads();
            if (ks + 1 < 8) loadS1(ks + 1, (ks + 1) & 1);
            uint32_t sba = sb + ESM_A + (ks & 1) * 10240;
            uint32_t sbb = sb + ESM_B + (ks & 1) * 40960;
#pragma unroll
            for (int s = 0; s < 2; s++) {
                uint32_t a2[2][4][4], b2r[2][2][4];   // [hi/lo][frag][regs]
#pragma unroll
                for (int mf = 0; mf < 4; mf++) {
                    uint32_t ad = sba + rowA + (uint32_t)mf * (16 * 80) + s * 32;
                    LDSM4(a2[0][mf], ad);
                    LDSM4(a2[1][mf], ad + 5120);
                }
#pragma unroll
                for (int p = 0; p < 2; p++) {
                    uint32_t bd = sbb + rowB + (uint32_t)p * (16 * 80) + s * 32;
                    LDSM4(b2r[0][p], bd);
                    LDSM4(b2r[1][p], bd + 20480);
                }
                // term-major: HH, HL, LH — RAW distance 16 per accumulator
#pragma unroll
                for (int tt = 0; tt < 3; tt++) {
                    const int ai = (tt == 2) ? 1 : 0;
                    const int bi = (tt == 1) ? 1 : 0;
#pragma unroll
                    for (int mf = 0; mf < 4; mf++)
#pragma unroll
                        for (int nf = 0; nf < 4; nf++) {
                            int p = nf >> 1, sel = nf & 1;
                            mma_f32(acc[mf][nf], a2[ai][mf],
                                    b2r[bi][p][sel], b2r[bi][p][sel + 2]);
                        }
                }
            }
            __syncthreads();
        }

        loadS2(0, 0);

        const float* b1 = b1g + e * SC_HID;
#pragma unroll
        for (int mf = 0; mf < 4; mf++) {
            int row = mf * 16 + (lane >> 2);
#pragma unroll
            for (int nf = 0; nf < 4; nf++) {
                int col = wid * 32 + nf * 8 + 2 * (lane & 3);
                float b0v = b1[col], b1v = b1[col + 1];
                float v0 = fmaxf(acc[mf][nf][0] + b0v, 0.f);
                float v1 = fmaxf(acc[mf][nf][1] + b1v, 0.f);
                float v2 = fmaxf(acc[mf][nf][2] + b0v, 0.f);
                float v3 = fmaxf(acc[mf][nf][3] + b1v, 0.f);
                int ks = col >> 5, cw = col & 31;
                uint32_t off = (uint32_t)ks * 5120 + (uint32_t)row * 80 + cw * 2;
                h16 h0, l0, h1, l1;
                f16_split(v0, h0, l0); f16_split(v1, h1, l1);
                *(uint32_t*)(smraw + ESM_H + off)         = pack2h(h0, h1);
                *(uint32_t*)(smraw + ESM_H + 40960 + off) = pack2h(l0, l1);
                f16_split(v2, h0, l0); f16_split(v3, h1, l1);
                *(uint32_t*)(smraw + ESM_H + off + 8 * 80)         = pack2h(h0, h1);
                *(uint32_t*)(smraw + ESM_H + 40960 + off + 8 * 80) = pack2h(l0, l1);
            }
        }
    }
    __syncthreads();

    // ======== stage 2: o[64,128] = h @ W2T + b2 ====
    {
        int warp_m = wid & 1, warp_n = wid >> 1;
        float acc[2][4][4];
#pragma unroll
        for (int a = 0; a < 2; a++)
#pragma unroll
            for (int b = 0; b < 4; b++)
#pragma unroll
                for (int c = 0; c < 4; c++) acc[a][b][c] = 0.f;

        uint32_t rowA = (uint32_t)(warp_m * 32 + (lane & 15)) * 80 + (lane >> 4) * 16;
        uint32_t rowB = (uint32_t)(warp_n * 32 + (lane & 15)) * 80 + (lane >> 4) * 16;

        for (int ks = 0; ks < 8; ks++) {
            CP_WAIT0();
            __syncthreads();
            if (ks + 1 < 8) loadS2(ks + 1, (ks + 1) & 1);
            uint32_t hbase = sb + ESM_H + (uint32_t)ks * 5120;
            uint32_t sbb = sb + ESM_B + (ks & 1) * 20480;
#pragma unroll
            for (int s = 0; s < 2; s++) {
                uint32_t a2[2][2][4], b2r[2][2][4];
#pragma unroll
                for (int mf = 0; mf < 2; mf++) {
                    uint32_t ad = hbase + rowA + (uint32_t)mf * (16 * 80) + s * 32;
                    LDSM4(a2[0][mf], ad);
                    LDSM4(a2[1][mf], ad + 40960);
                }
#pragma unroll
                for (int p = 0; p < 2; p++) {
                    uint32_t bd = sbb + rowB + (uint32_t)p * (16 * 80) + s * 32;
                    LDSM4(b2r[0][p], bd);
                    LDSM4(b2r[1][p], bd + 10240);
                }
#pragma unroll
                for (int tt = 0; tt < 3; tt++) {
                    const int ai = (tt == 2) ? 1 : 0;
                    const int bi = (tt == 1) ? 1 : 0;
#pragma unroll
                    for (int mf = 0; mf < 2; mf++)
#pragma unroll
                        for (int nf = 0; nf < 4; nf++) {
                            int p = nf >> 1, sel = nf & 1;
                            mma_f32(acc[mf][nf], a2[ai][mf],
                                    b2r[bi][p][sel], b2r[bi][p][sel + 2]);
                        }
                }
            }
            __syncthreads();
        }

        const float* b2 = b2g + e * SC_OUT;
#pragma unroll
        for (int mf = 0; mf < 2; mf++) {
            int row = warp_m * 32 + mf * 16 + (lane >> 2);
#pragma unroll
            for (int nf = 0; nf < 4; nf++) {
                int col = warp_n * 32 + nf * 8 + 2 * (lane & 3);
                float b0v = b2[col], b1v = b2[col + 1];
                float v0 = acc[mf][nf][0] + b0v, v1 = acc[mf][nf][1] + b1v;
                float v2 = acc[mf][nf][2] + b0v, v3 = acc[mf][nf][3] + b1v;
                int pi0 = pidx[row], pi1 = pidx[row + 8];
                if (pi0 >= 0) {
                    h16 h0, l0, h1, l1;
                    f16_split(v0, h0, l0); f16_split(v1, h1, l1);
                    *(uint32_t*)(g_a0hi + (size_t)pi0 * K0PAD + HEADC + col) = pack2h(h0, h1);
                    *(uint32_t*)(g_a0lo + (size_t)pi0 * K0PAD + HEADC + col) = pack2h(l0, l1);
                }
                if (pi1 >= 0) {
                    h16 h0, l0, h1, l1;
                    f16_split(v2, h0, l0); f16_split(v3, h1, l1);
                    *(uint32_t*)(g_a0hi + (size_t)pi1 * K0PAD + HEADC + col) = pack2h(h0, h1);
                    *(uint32_t*)(g_a0lo + (size_t)pi1 * K0PAD + HEADC + col) = pack2h(l0, l1);
                }
            }
        }
    }
}

// ---------------- 4. f16 mma GEMM: 64x128 tiles, 3-stage ring, 1 sync/slab --
#define GSTG  30720
#define GSMEM (3 * GSTG)

template <int KTOT, int RELU, int SPLIT>
__global__ void __launch_bounds__(256, 2) gemm_mma(
    const h16* __restrict__ aHi, const h16* __restrict__ aLo,
    const h16* __restrict__ wHi, const h16* __restrict__ wLo,
    const float* __restrict__ bias,
    h16* __restrict__ oHi, h16* __restrict__ oLo, int KOUT)
{
    extern __shared__ char smraw[];
    const int NK = KTOT / 32;
    int tid = threadIdx.x, lane = tid & 31, wid = tid >> 5;
    int warp_m = wid & 1, warp_n = wid >> 1;     // 2 x 4 warps, warp tile 32x32
    int m0 = blockIdx.x * 64, c0 = blockIdx.y * 128;

    uint32_t smBase = smem_u32(smraw);
    uint32_t rowA = (uint32_t)(warp_m * 32 + (lane & 15)) * 80 + (lane >> 4) * 16;
    uint32_t rowB = (uint32_t)(warp_n * 32 + (lane & 15)) * 80 + (lane >> 4) * 16;

    float acc[2][4][4];
#pragma unroll
    for (int a = 0; a < 2; a++)
#pragma unroll
        for (int b = 0; b < 4; b++)
#pragma unroll
            for (int c = 0; c < 4; c++) acc[a][b][c] = 0.f;

    auto loadStage = [&](int ks, int st) {
        uint32_t sbs = smBase + st * GSTG;
#pragma unroll
        for (int i = 0; i < 2; i++) {
            int c = tid + i * 256;
            int half = c >> 8, idx = c & 255;
            int row = idx >> 2, ch = idx & 3;
            const h16* src = (half ? aLo : aHi) + (size_t)(m0 + row) * KTOT + ks * 32 + ch * 8;
            CP_ASYNC16(sbs + half * 5120 + (uint32_t)row * 80 + ch * 16, src);
        }
#pragma unroll
        for (int i = 0; i < 4; i++) {
            int c = tid + i * 256;
            int half = c >> 9, idx = c & 511;
            int row = idx >> 2, ch = idx & 3;
            const h16* src = (half ? wLo : wHi) + (size_t)(c0 + row) * KTOT + ks * 32 + ch * 8;
            CP_ASYNC16(sbs + 10240 + half * 10240 + (uint32_t)row * 80 + ch * 16, src);
        }
        CP_COMMIT();
    };

    loadStage(0, 0);
    if (NK > 1) loadStage(1, 1);
    for (int ks = 0; ks < NK; ks++) {
        if (ks < NK - 1) CP_WAIT1(); else CP_WAIT0();
        __syncthreads();                         // single barrier per slab
        if (ks + 2 < NK) loadStage(ks + 2, (ks + 2) % 3);

        uint32_t sbs = smBase + (ks % 3) * GSTG;
#pragma unroll
        for (int s = 0; s < 2; s++) {
            uint32_t a2[2][2][4], b2r[2][2][4];
#pragma unroll
            for (int mf = 0; mf < 2; mf++) {
                uint32_t ad = sbs + rowA + (uint32_t)mf * (16 * 80) + s * 32;
                LDSM4(a2[0][mf], ad);
                LDSM4(a2[1][mf], ad + 5120);
            }
#pragma unroll
            for (int p = 0; p < 2; p++) {
                uint32_t bd = sbs + 10240 + rowB + (uint32_t)p * (16 * 80) + s * 32;
                LDSM4(b2r[0][p], bd);
                LDSM4(b2r[1][p], bd + 10240);
            }
            // term-major: HH, HL, LH — RAW distance 8 per accumulator
#pragma unroll
            for (int tt = 0; tt < 3; tt++) {
                const int ai = (tt == 2) ? 1 : 0;
                const int bi = (tt == 1) ? 1 : 0;
#pragma unroll
                for (int mf = 0; mf < 2; mf++)
#pragma unroll
                    for (int nf = 0; nf < 4; nf++) {
                        int p = nf >> 1, sel = nf & 1;
                        mma_f32(acc[mf][nf], a2[ai][mf],
                                b2r[bi][p][sel], b2r[bi][p][sel + 2]);
                    }
            }
        }
    }

    if (SPLIT) {
#pragma unroll
        for (int mf = 0; mf < 2; mf++) {
            int row = m0 + warp_m * 32 + mf * 16 + (lane >> 2);
#pragma unroll
            for (int nf = 0; nf < 4; nf++) {
                int col = c0 + warp_n * 32 + nf * 8 + 2 * (lane & 3);
                float b0v = bias[col], b1v = bias[col + 1];
                float v0 = acc[mf][nf][0] + b0v, v1 = acc[mf][nf][1] + b1v;
                float v2 = acc[mf][nf][2] + b0v, v3 = acc[mf][nf][3] + b1v;
                if (RELU) {
                    v0 = fmaxf(v0, 0.f); v1 = fmaxf(v1, 0.f);
                    v2 = fmaxf(v2, 0.f); v3 = fmaxf(v3, 0.f);
                }
                h16 h0, l0, h1, l1;
                f16_split(v0, h0, l0); f16_split(v1, h1, l1);
                *(uint32_t*)(oHi + (size_t)row * KOUT + col) = pack2h(h0, h1);
                *(uint32_t*)(oLo + (size_t)row * KOUT + col) = pack2h(l0, l1);
                f16_split(v2, h0, l0); f16_split(v3, h1, l1);
                *(uint32_t*)(oHi + (size_t)(row + 8) * KOUT + col) = pack2h(h0, h1);
                *(uint32_t*)(oLo + (size_t)(row + 8) * KOUT + col) = pack2h(l0, l1);
            }
        }
    } else {
        // ---- fused max-pool epilogue: partial max over 64 rows ----
        __syncthreads();
        float* pm = (float*)smraw;               // [2][128]
#pragma unroll
        for (int nf = 0; nf < 4; nf++) {
            float c0m = -FLT_MAX, c1m = -FLT_MAX;
#pragma unroll
            for (int mf = 0; mf < 2; mf++) {
                int col = c0 + warp_n * 32 + nf * 8 + 2 * (lane & 3);
                float b0v = bias[col], b1v = bias[col + 1];
                c0m = fmaxf(c0m, fmaxf(acc[mf][nf][0] + b0v, acc[mf][nf][2] + b0v));
                c1m = fmaxf(c1m, fmaxf(acc[mf][nf][1] + b1v, acc[mf][nf][3] + b1v));
            }
#pragma unroll
            for (int o = 4; o < 32; o <<= 1) {
                c0m = fmaxf(c0m, __shfl_xor_sync(0xFFFFFFFFu, c0m, o));
                c1m = fmaxf(c1m, __shfl_xor_sync(0xFFFFFFFFu, c1m, o));
            }
            if (lane < 4) {
                int cc = warp_n * 32 + nf * 8 + 2 * lane;
                pm[warp_m * 128 + cc]     = c0m;
                pm[warp_m * 128 + cc + 1] = c1m;
            }
        }
        __syncthreads();
        if (tid < 64) {
            int cc = tid * 2;
            float m0v = fmaxf(pm[cc],     pm[128 + cc]);
            float m1v = fmaxf(pm[cc + 1], pm[128 + cc + 1]);
            int b = m0 >> 10, part = (m0 >> 6) & (NPART - 1);
            *(float2*)(g_part + (size_t)(b * NPART + part) * C3OUT + c0 + cc)
                = make_float2(m0v, m1v);
        }
    }
}

// ---------------- 5. max pool final stage ----------------
__global__ void k_poolB(float* __restrict__ extra, int we) {
    int i = blockIdx.x * 256 + threadIdx.x;   // 8192
    float m = -FLT_MAX;
    int b = i >> 10, c = i & 1023;
#pragma unroll
    for (int part = 0; part < NPART; part++)
        m = fmaxf(m, g_part[(b * NPART + part) * C3OUT + c]);
    g_lat[i] = m;
    if (we) extra[i] = m;
}

// ---------------- 6. decoder MLP (16 cols x 16 K-slices per block) ----------
template <int RELU>
__global__ void __launch_bounds__(256) mlp8(
    const float* __restrict__ A, const float* __restrict__ W,
    const float* __restrict__ bias, float* __restrict__ Out,
    int K, int N)
{
    extern __shared__ float Ash[];
    __shared__ float red[256 * 8];
    int tid = threadIdx.x;
    for (int i = tid; i < 8 * K / 4; i += 256)
        ((float4*)Ash)[i] = ((const float4*)A)[i];
    __syncthreads();

    int col   = blockIdx.x * 16 + (tid & 15);
    int slice = tid >> 4;
    int kPer  = K >> 4;
    int k0    = slice * kPer;

    float acc[8];
#pragma unroll
    for (int bb = 0; bb < 8; bb++) acc[bb] = 0.f;

    for (int k = k0; k < k0 + kPer; k += 4) {
        float w0 = W[(size_t)(k + 0) * N + col];
        float w1 = W[(size_t)(k + 1) * N + col];
        float w2 = W[(size_t)(k + 2) * N + col];
        float w3 = W[(size_t)(k + 3) * N + col];
#pragma unroll
        for (int bb = 0; bb < 8; bb++) {
            float4 a4 = ((const float4*)(Ash + bb * K))[k >> 2];
            acc[bb] = fmaf(a4.x, w0, acc[bb]);
            acc[bb] = fmaf(a4.y, w1, acc[bb]);
            acc[bb] = fmaf(a4.z, w2, acc[bb]);
            acc[bb] = fmaf(a4.w, w3, acc[bb]);
        }
    }
#pragma unroll
    for (int bb = 0; bb < 8; bb++) red[tid * 8 + bb] = acc[bb];
    __syncthreads();
    if (tid < 16) {
        float bsv = bias[col];
#pragma unroll
        for (int bb = 0; bb < 8; bb++) {
            float v = bsv;
#pragma unroll
            for (int s = 0; s < 16; s++)
                v += red[(tid + s * 16) * 8 + bb];
            if (RELU) v = fmaxf(v, 0.f);
            Out[(size_t)bb * N + col] = v;
        }
    }
}

// ---------------- launch ----------------
extern "C" void kernel_launch(void* const* d_in, const int* in_sizes, int n_in,
                              void* d_out, int out_size) {
    const float* x    = (const float*)d_in[0];
    const int*   cats = (const int*)  d_in[1];
    const float* W1   = (const float*)d_in[2];
    const float* b1   = (const float*)d_in[3];
    const float* W2   = (const float*)d_in[4];
    const float* b2   = (const float*)d_in[5];
    const float* Wc1  = (const float*)d_in[6];
    const float* bc1  = (const float*)d_in[7];
    const float* Wc2  = (const float*)d_in[8];
    const float* bc2  = (const float*)d_in[9];
    const float* Wc3  = (const float*)d_in[10];
    const float* bc3  = (const float*)d_in[11];
    const float* Wd1  = (const float*)d_in[12];
    const float* bd1  = (const float*)d_in[13];
    const float* Wd2  = (const float*)d_in[14];
    const float* bd2  = (const float*)d_in[15];
    const float* Wd3  = (const float*)d_in[16];
    const float* bd3  = (const float*)d_in[17];
    float* out = (float*)d_out;

    cudaFuncSetAttribute(k_expert_mma, cudaFuncAttributeMaxDynamicSharedMemorySize, ESMEM);
    cudaFuncSetAttribute(mlp8<1>,  cudaFuncAttributeMaxDynamicSharedMemorySize, 65536);
    cudaFuncSetAttribute(mlp8<0>,  cudaFuncAttributeMaxDynamicSharedMemorySize, 65536);
    cudaFuncSetAttribute(gemm_mma<K0PAD, 1, 1>, cudaFuncAttributeMaxDynamicSharedMemorySize, GSMEM);
    cudaFuncSetAttribute(gemm_mma<C1OUT, 1, 1>, cudaFuncAttributeMaxDynamicSharedMemorySize, GSMEM);
    cudaFuncSetAttribute(gemm_mma<C2OUT, 0, 0>, cudaFuncAttributeMaxDynamicSharedMemorySize, GSMEM);

    h16 *p_a0h, *p_a0l, *p_a1h, *p_a1l, *p_a2h, *p_a2l;
    h16 *p_w1h, *p_w1l, *p_w2h, *p_w2l, *p_w3h, *p_w3l;
    float *p_lat, *p_d1, *p_d2;
    cudaGetSymbolAddress((void**)&p_a0h, g_a0hi);
    cudaGetSymbolAddress((void**)&p_a0l, g_a0lo);
    cudaGetSymbolAddress((void**)&p_a1h, g_a1hi);
    cudaGetSymbolAddress((void**)&p_a1l, g_a1lo);
    cudaGetSymbolAddress((void**)&p_a2h, g_a2hi);
    cudaGetSymbolAddress((void**)&p_a2l, g_a2lo);
    cudaGetSymbolAddress((void**)&p_w1h, g_w1hi);
    cudaGetSymbolAddress((void**)&p_w1l, g_w1lo);
    cudaGetSymbolAddress((void**)&p_w2h, g_w2hi);
    cudaGetSymbolAddress((void**)&p_w2l, g_w2lo);
    cudaGetSymbolAddress((void**)&p_w3h, g_w3hi);
    cudaGetSymbolAddress((void**)&p_w3l, g_w3lo);
    cudaGetSymbolAddress((void**)&p_lat, g_lat);
    cudaGetSymbolAddress((void**)&p_d1,  g_d1);
    cudaGetSymbolAddress((void**)&p_d2,  g_d2);

    k_prep<<<PREP_NB, 256>>>(x, W1, W2, Wc1, Wc2, Wc3);
    k_build<<<1, 1024>>>(cats);
    k_expert_mma<<<MAXTILES, 256, ESMEM>>>(b1, b2);

    gemm_mma<K0PAD, 1, 1><<<dim3(128, C1OUT / 128), 256, GSMEM>>>(
        p_a0h, p_a0l, p_w1h, p_w1l, bc1, p_a1h, p_a1l, C1OUT);
    gemm_mma<C1OUT, 1, 1><<<dim3(128, C2OUT / 128), 256, GSMEM>>>(
        p_a1h, p_a1l, p_w2h, p_w2l, bc2, p_a2h, p_a2l, C2OUT);
    gemm_mma<C2OUT, 0, 0><<<dim3(128, C3OUT / 128), 256, GSMEM>>>(
        p_a2h, p_a2l, p_w3h, p_w3l, bc3, (h16*)0, (h16*)0, C3OUT);

    int write_extra = (out_size >= 65536 + 8192) ? 1 : 0;
    k_poolB<<<NPOINTS / 256, 256>>>(out + 65536, write_extra);

    mlp8<1><<<DEC1 / 16, 256, 8 * DEC1 * 4>>>(p_lat, Wd1, bd1, p_d1, DEC1, DEC1);
    mlp8<1><<<DEC2 / 16, 256, 8 * DEC1 * 4>>>(p_d1,  Wd2, bd2, p_d2, DEC1, DEC2);
    mlp8<0><<<DEC3 / 16, 256, 8 * DEC2 * 4>>>(p_d2,  Wd3, bd3, out,  DEC2, DEC3);
}

// round 10
// speedup vs baseline: 1.0729x; 1.0318x over previous
#include <cuda_runtime.h>
#include <cuda_fp16.h>
#include <float.h>
#include <stdint.h>

// ---------------- problem constants ----------------
#define BATCH      8
#define NPTS       1024
#define NPOINTS    (BATCH * NPTS)        // 8192
#define HEADC      8
#define SHAPEC     256
#define XCH        (HEADC + SHAPEC)      // 264
#define NEXPERT    16
#define SC_HID     256
#define SC_OUT     128
#define K0PAD      160                   // 136 padded to 160
#define C1OUT      256
#define C2OUT      512
#define C3OUT      1024
#define DEC1       1024
#define DEC2       2048
#define DEC3       8192
#define ETILE      64
#define MAXTILES   (NPOINTS / ETILE + NEXPERT)   // 144
#define NPART      16                    // pool partials per batch

typedef __half h16;

// ---------------- scratch (device globals; no runtime alloc) ----------------
__device__ __align__(256) h16 g_xhi[NPOINTS * SHAPEC];
__device__ __align__(256) h16 g_xlo[NPOINTS * SHAPEC];
__device__ __align__(256) h16 g_a0hi[NPOINTS * K0PAD];
__device__ __align__(256) h16 g_a0lo[NPOINTS * K0PAD];
__device__ __align__(256) h16 g_a1hi[NPOINTS * C1OUT];
__device__ __align__(256) h16 g_a1lo[NPOINTS * C1OUT];
__device__ __align__(256) h16 g_a2hi[NPOINTS * C2OUT];
__device__ __align__(256) h16 g_a2lo[NPOINTS * C2OUT];
__device__ __align__(256) h16 g_w1hi[C1OUT * K0PAD];
__device__ __align__(256) h16 g_w1lo[C1OUT * K0PAD];
__device__ __align__(256) h16 g_w2hi[C2OUT * C1OUT];
__device__ __align__(256) h16 g_w2lo[C2OUT * C1OUT];
__device__ __align__(256) h16 g_w3hi[C3OUT * C2OUT];
__device__ __align__(256) h16 g_w3lo[C3OUT * C2OUT];
__device__ __align__(256) h16 g_e1hi[NEXPERT * SC_HID * SHAPEC];
__device__ __align__(256) h16 g_e1lo[NEXPERT * SC_HID * SHAPEC];
__device__ __align__(256) h16 g_e2hi[NEXPERT * SC_OUT * SC_HID];
__device__ __align__(256) h16 g_e2lo[NEXPERT * SC_OUT * SC_HID];
__device__ float g_part[BATCH * NPART * C3OUT];
__device__ float g_lat[BATCH * C3OUT];
__device__ float g_d1[BATCH * DEC1];
__device__ float g_d2[BATCH * DEC2];
__device__ int   g_idx[NPOINTS];
__device__ int   g_tileExpert[MAXTILES];
__device__ int   g_tileStart[MAXTILES];
__device__ int   g_tileLen[MAXTILES];
__device__ int   g_nTiles;

// ---------------- ptx helpers (sm_80-safe) ----------------
__device__ __forceinline__ uint32_t smem_u32(const void* p) {
    uint32_t a;
    asm("{ .reg .u64 t; cvta.to.shared.u64 t, %1; cvt.u32.u64 %0, t; }" : "=r"(a) : "l"(p));
    return a;
}
#define CP_ASYNC16(dst, src) \
    asm volatile("cp.async.cg.shared.global [%0], [%1], 16;" :: "r"(dst), "l"(src))
#define CP_COMMIT() asm volatile("cp.async.commit_group;" ::: "memory")
#define CP_WAIT0()  asm volatile("cp.async.wait_group 0;" ::: "memory")
#define CP_WAIT1()  asm volatile("cp.async.wait_group 1;" ::: "memory")

#define LDSM4(r, addr) \
    asm volatile("ldmatrix.sync.aligned.m8n8.x4.shared.b16 {%0,%1,%2,%3}, [%4];" \
        : "=r"((r)[0]), "=r"((r)[1]), "=r"((r)[2]), "=r"((r)[3]) : "r"(addr))

__device__ __forceinline__ void mma_f32(float* d, const uint32_t* a,
                                        uint32_t b0, uint32_t b1) {
    asm volatile(
        "mma.sync.aligned.m16n8k16.row.col.f32.f16.f16.f32 "
        "{%0,%1,%2,%3}, {%4,%5,%6,%7}, {%8,%9}, {%0,%1,%2,%3};"
        : "+f"(d[0]), "+f"(d[1]), "+f"(d[2]), "+f"(d[3])
        : "r"(a[0]), "r"(a[1]), "r"(a[2]), "r"(a[3]), "r"(b0), "r"(b1));
}

__device__ __forceinline__ void f16_split(float v, h16& h, h16& l) {
    h = __float2half_rn(v);
    l = __float2half_rn(v - __half2float(h));
}
__device__ __forceinline__ uint32_t pack2h(h16 a, h16 b) {
    __half2 t; t.x = a; t.y = b;
    return *(uint32_t*)&t;
}

// ---------------- 1. fused prep: transpose | tsplit | head | wsplit ---------
#define PREP_T1 2048
#define PREP_T2 3584
#define PREP_T3 4608
#define PREP_NB 7328
#define WS_NB1 160
#define WS_NB2 512

__global__ void __launch_bounds__(256) k_prep(
    const float* __restrict__ x,
    const float* __restrict__ W1, const float* __restrict__ W2,
    const float* __restrict__ Wc1, const float* __restrict__ Wc2,
    const float* __restrict__ Wc3)
{
    __shared__ float t[32][33];
    int bi = blockIdx.x;
    int tid = threadIdx.x;
    int tx = tid & 31, ty = tid >> 5;

    if (bi < PREP_T1) {
        int idx = bi;
        int cB = (idx & 7) * 32;
        int nB = ((idx >> 3) & 31) * 32;
        int b  = idx >> 8;
        const float* xb = x + (size_t)b * XCH * NPTS;
#pragma unroll
        for (int i = ty; i < 32; i += 8)
            t[i][tx] = xb[(size_t)(HEADC + cB + i) * NPTS + nB + tx];
        __syncthreads();
        size_t base = ((size_t)b * NPTS + nB) * SHAPEC + cB;
#pragma unroll
        for (int i = ty; i < 32; i += 8) {
            float v = t[tx][i];
            h16 h, l; f16_split(v, h, l);
            g_xhi[base + (size_t)i * SHAPEC + tx] = h;
            g_xlo[base + (size_t)i * SHAPEC + tx] = l;
        }
    } else if (bi < PREP_T2) {
        int r = bi - PREP_T1;
        const float* src; h16 *hi, *lo; int K, OUT, e, k0, o0;
        if (r < 1024) {
            e = r >> 6; int q = r & 63;
            k0 = (q & 7) * 32; o0 = (q >> 3) * 32;
            src = W1; hi = g_e1hi; lo = g_e1lo; K = SHAPEC; OUT = SC_HID;
        } else {
            r -= 1024;
            e = r >> 5; int q = r & 31;
            k0 = (q & 7) * 32; o0 = (q >> 3) * 32;
            src = W2; hi = g_e2hi; lo = g_e2lo; K = SC_HID; OUT = SC_OUT;
        }
        const float* s = src + (size_t)e * K * OUT;
#pragma unroll
        for (int i = ty; i < 32; i += 8)
            t[i][tx] = s[(size_t)(k0 + i) * OUT + o0 + tx];
        __syncthreads();
        size_t base = (size_t)e * OUT * K + (size_t)o0 * K + k0;
#pragma unroll
        for (int i = ty; i < 32; i += 8) {
            float v = t[tx][i];
            h16 h, l; f16_split(v, h, l);
            hi[base + (size_t)i * K + tx] = h;
            lo[base + (size_t)i * K + tx] = l;
        }
    } else if (bi < PREP_T3) {
        int i = (bi - PREP_T2) * 256 + tid;
        int p = i >> 5, s = i & 31;
        float v = 0.f;
        int col;
        if (s < 8) {
            int b = p >> 10, n = p & 1023;
            v = x[(size_t)b * XCH * NPTS + (size_t)s * NPTS + n];
            col = s;
        } else {
            col = 128 + s;
        }
        h16 h, l; f16_split(v, h, l);
        g_a0hi[(size_t)p * K0PAD + col] = h;
        g_a0lo[(size_t)p * K0PAD + col] = l;
    } else {
        int r = bi - PREP_T3;
        const float* w; h16 *hi, *lo; int Kin, Kpad, total, i;
        if (r < WS_NB1) {
            w = Wc1; hi = g_w1hi; lo = g_w1lo; Kin = 136; Kpad = K0PAD;
            total = C1OUT * K0PAD; i = r * 256 + tid;
        } else if (r < WS_NB1 + WS_NB2) {
            w = Wc2; hi = g_w2hi; lo = g_w2lo; Kin = C1OUT; Kpad = C1OUT;
            total = C2OUT * C1OUT; i = (r - WS_NB1) * 256 + tid;
        } else {
            w = Wc3; hi = g_w3hi; lo = g_w3lo; Kin = C2OUT; Kpad = C2OUT;
            total = C3OUT * C2OUT; i = (r - WS_NB1 - WS_NB2) * 256 + tid;
        }
        if (i >= total) return;
        int c = i / Kpad, k = i - c * Kpad;
        float v = (k < Kin) ? w[(size_t)c * Kin + k] : 0.f;
        h16 h, l; f16_split(v, h, l);
        hi[i] = h;
        lo[i] = l;
    }
}

// ---------------- 2. counting sort points by category (tiles of 64) ---------
__global__ void k_build(const int* __restrict__ cats) {
    __shared__ int cnt[NEXPERT];
    __shared__ int off[NEXPERT + 1];
    __shared__ int cur[NEXPERT];
    int tid = threadIdx.x;
    if (tid < NEXPERT) cnt[tid] = 0;
    __syncthreads();
    for (int i = tid; i < NPOINTS; i += blockDim.x) atomicAdd(&cnt[cats[i]], 1);
    __syncthreads();
    if (tid == 0) {
        int s = 0;
        for (int e = 0; e < NEXPERT; e++) { off[e] = s; s += cnt[e]; }
        off[NEXPERT] = s;
        int t = 0;
        for (int e = 0; e < NEXPERT; e++)
            for (int st = off[e]; st < off[e + 1]; st += ETILE) {
                g_tileExpert[t] = e;
                g_tileStart[t]  = st;
                g_tileLen[t]    = min(ETILE, off[e + 1] - st);
                t++;
            }
        g_nTiles = t;
    }
    __syncthreads();
    if (tid < NEXPERT) cur[tid] = off[tid];
    __syncthreads();
    for (int i = tid; i < NPOINTS; i += blockDim.x) {
        int pos = atomicAdd(&cur[cats[i]], 1);
        g_idx[pos] = i;
    }
}

// ---------------- 3. fused expert MLP on tensor cores (double-buffered) -----
#define ESM_A  0
#define ESM_B  20480
#define ESM_H  102400
#define ESMEM  184320

__global__ void __launch_bounds__(256) k_expert_mma(
    const float* __restrict__ b1g, const float* __restrict__ b2g)
{
    int t = blockIdx.x;
    if (t >= g_nTiles) return;
    int e = g_tileExpert[t], start = g_tileStart[t], len = g_tileLen[t];

    extern __shared__ char smraw[];
    __shared__ int pidx[ETILE];
    __shared__ int gidx[ETILE];

    int tid = threadIdx.x, lane = tid & 31, wid = tid >> 5;
    uint32_t sb = smem_u32(smraw);

    if (tid < ETILE) {
        int pi = (tid < len) ? g_idx[start + tid] : -1;
        pidx[tid] = pi;
        gidx[tid] = pi < 0 ? 0 : pi;
    }
    __syncthreads();

    const h16* w1h = g_e1hi + (size_t)e * SC_HID * SHAPEC;
    const h16* w1l = g_e1lo + (size_t)e * SC_HID * SHAPEC;
    const h16* w2h = g_e2hi + (size_t)e * SC_OUT * SC_HID;
    const h16* w2l = g_e2lo + (size_t)e * SC_OUT * SC_HID;

    auto loadS1 = [&](int ks, int st) {
#pragma unroll
        for (int r = 0; r < 2; r++) {
            int id = tid + r * 256;
            int half = id >> 8, idx = id & 255;
            int row = idx >> 2, ch = idx & 3;
            const h16* src = (half ? g_xlo : g_xhi)
                           + (size_t)gidx[row] * SHAPEC + ks * 32 + ch * 8;
            CP_ASYNC16(sb + ESM_A + st * 10240 + half * 5120 + (uint32_t)row * 80 + ch * 16, src);
        }
#pragma unroll
        for (int r = 0; r < 8; r++) {
            int id = tid + r * 256;
            int half = id >> 10, idx = id & 1023;
            int row = idx >> 2, ch = idx & 3;
            const h16* src = (half ? w1l : w1h)
                           + (size_t)row * SHAPEC + ks * 32 + ch * 8;
            CP_ASYNC16(sb + ESM_B + st * 40960 + half * 20480 + (uint32_t)row * 80 + ch * 16, src);
        }
        CP_COMMIT();
    };
    auto loadS2 = [&](int ks, int st) {
#pragma unroll
        for (int r = 0; r < 4; r++) {
            int id = tid + r * 256;
            int half = id >> 9, idx = id & 511;
            int row = idx >> 2, ch = idx & 3;
            const h16* src = (half ? w2l : w2h)
                           + (size_t)row * SC_HID + ks * 32 + ch * 8;
            CP_ASYNC16(sb + ESM_B + st * 20480 + half * 10240 + (uint32_t)row * 80 + ch * 16, src);
        }
        CP_COMMIT();
    };

    // ======== stage 1: h[64,256] = relu(A @ W1T + b1) ====
    {
        float acc[4][4][4];
#pragma unroll
        for (int a = 0; a < 4; a++)
#pragma unroll
            for (int b = 0; b < 4; b++)
#pragma unroll
                for (int c = 0; c < 4; c++) acc[a][b][c] = 0.f;

        uint32_t rowA = (uint32_t)(lane & 15) * 80 + (lane >> 4) * 16;
        uint32_t rowB = (uint32_t)(wid * 32 + (lane & 15)) * 80 + (lane >> 4) * 16;

        loadS1(0, 0);
        for (int ks = 0; ks < 8; ks++) {
            CP_WAIT0();
            __syncthreads();
            if (ks + 1 < 8) loadS1(ks + 1, (ks + 1) & 1);
            uint32_t sba = sb + ESM_A + (ks & 1) * 10240;
            uint32_t sbb = sb + ESM_B + (ks & 1) * 40960;
#pragma unroll
            for (int s = 0; s < 2; s++) {
                uint32_t a2[2][4][4], b2r[2][2][4];
#pragma unroll
                for (int mf = 0; mf < 4; mf++) {
                    uint32_t ad = sba + rowA + (uint32_t)mf * (16 * 80) + s * 32;
                    LDSM4(a2[0][mf], ad);
                    LDSM4(a2[1][mf], ad + 5120);
                }
#pragma unroll
                for (int p = 0; p < 2; p++) {
                    uint32_t bd = sbb + rowB + (uint32_t)p * (16 * 80) + s * 32;
                    LDSM4(b2r[0][p], bd);
                    LDSM4(b2r[1][p], bd + 20480);
                }
#pragma unroll
                for (int tt = 0; tt < 3; tt++) {
                    const int ai = (tt == 2) ? 1 : 0;
                    const int bi = (tt == 1) ? 1 : 0;
#pragma unroll
                    for (int mf = 0; mf < 4; mf++)
#pragma unroll
                        for (int nf = 0; nf < 4; nf++) {
                            int p = nf >> 1, sel = nf & 1;
                            mma_f32(acc[mf][nf], a2[ai][mf],
                                    b2r[bi][p][sel], b2r[bi][p][sel + 2]);
                        }
                }
            }
            __syncthreads();
        }

        loadS2(0, 0);

        const float* b1 = b1g + e * SC_HID;
#pragma unroll
        for (int mf = 0; mf < 4; mf++) {
            int row = mf * 16 + (lane >> 2);
#pragma unroll
            for (int nf = 0; nf < 4; nf++) {
                int col = wid * 32 + nf * 8 + 2 * (lane & 3);
                float b0v = b1[col], b1v = b1[col + 1];
                float v0 = fmaxf(acc[mf][nf][0] + b0v, 0.f);
                float v1 = fmaxf(acc[mf][nf][1] + b1v, 0.f);
                float v2 = fmaxf(acc[mf][nf][2] + b0v, 0.f);
                float v3 = fmaxf(acc[mf][nf][3] + b1v, 0.f);
                int ks = col >> 5, cw = col & 31;
                uint32_t off = (uint32_t)ks * 5120 + (uint32_t)row * 80 + cw * 2;
                h16 h0, l0, h1, l1;
                f16_split(v0, h0, l0); f16_split(v1, h1, l1);
                *(uint32_t*)(smraw + ESM_H + off)         = pack2h(h0, h1);
                *(uint32_t*)(smraw + ESM_H + 40960 + off) = pack2h(l0, l1);
                f16_split(v2, h0, l0); f16_split(v3, h1, l1);
                *(uint32_t*)(smraw + ESM_H + off + 8 * 80)         = pack2h(h0, h1);
                *(uint32_t*)(smraw + ESM_H + 40960 + off + 8 * 80) = pack2h(l0, l1);
            }
        }
    }
    __syncthreads();

    // ======== stage 2: o[64,128] = h @ W2T + b2 ====
    {
        int warp_m = wid & 1, warp_n = wid >> 1;
        float acc[2][4][4];
#pragma unroll
        for (int a = 0; a < 2; a++)
#pragma unroll
            for (int b = 0; b < 4; b++)
#pragma unroll
                for (int c = 0; c < 4; c++) acc[a][b][c] = 0.f;

        uint32_t rowA = (uint32_t)(warp_m * 32 + (lane & 15)) * 80 + (lane >> 4) * 16;
        uint32_t rowB = (uint32_t)(warp_n * 32 + (lane & 15)) * 80 + (lane >> 4) * 16;

        for (int ks = 0; ks < 8; ks++) {
            CP_WAIT0();
            __syncthreads();
            if (ks + 1 < 8) loadS2(ks + 1, (ks + 1) & 1);
            uint32_t hbase = sb + ESM_H + (uint32_t)ks * 5120;
            uint32_t sbb = sb + ESM_B + (ks & 1) * 20480;
#pragma unroll
            for (int s = 0; s < 2; s++) {
                uint32_t a2[2][2][4], b2r[2][2][4];
#pragma unroll
                for (int mf = 0; mf < 2; mf++) {
                    uint32_t ad = hbase + rowA + (uint32_t)mf * (16 * 80) + s * 32;
                    LDSM4(a2[0][mf], ad);
                    LDSM4(a2[1][mf], ad + 40960);
                }
#pragma unroll
                for (int p = 0; p < 2; p++) {
                    uint32_t bd = sbb + rowB + (uint32_t)p * (16 * 80) + s * 32;
                    LDSM4(b2r[0][p], bd);
                    LDSM4(b2r[1][p], bd + 10240);
                }
#pragma unroll
                for (int tt = 0; tt < 3; tt++) {
                    const int ai = (tt == 2) ? 1 : 0;
                    const int bi = (tt == 1) ? 1 : 0;
#pragma unroll
                    for (int mf = 0; mf < 2; mf++)
#pragma unroll
                        for (int nf = 0; nf < 4; nf++) {
                            int p = nf >> 1, sel = nf & 1;
                            mma_f32(acc[mf][nf], a2[ai][mf],
                                    b2r[bi][p][sel], b2r[bi][p][sel + 2]);
                        }
                }
            }
            __syncthreads();
        }

        const float* b2 = b2g + e * SC_OUT;
#pragma unroll
        for (int mf = 0; mf < 2; mf++) {
            int row = warp_m * 32 + mf * 16 + (lane >> 2);
#pragma unroll
            for (int nf = 0; nf < 4; nf++) {
                int col = warp_n * 32 + nf * 8 + 2 * (lane & 3);
                float b0v = b2[col], b1v = b2[col + 1];
                float v0 = acc[mf][nf][0] + b0v, v1 = acc[mf][nf][1] + b1v;
                float v2 = acc[mf][nf][2] + b0v, v3 = acc[mf][nf][3] + b1v;
                int pi0 = pidx[row], pi1 = pidx[row + 8];
                if (pi0 >= 0) {
                    h16 h0, l0, h1, l1;
                    f16_split(v0, h0, l0); f16_split(v1, h1, l1);
                    *(uint32_t*)(g_a0hi + (size_t)pi0 * K0PAD + HEADC + col) = pack2h(h0, h1);
                    *(uint32_t*)(g_a0lo + (size_t)pi0 * K0PAD + HEADC + col) = pack2h(l0, l1);
                }
                if (pi1 >= 0) {
                    h16 h0, l0, h1, l1;
                    f16_split(v2, h0, l0); f16_split(v3, h1, l1);
                    *(uint32_t*)(g_a0hi + (size_t)pi1 * K0PAD + HEADC + col) = pack2h(h0, h1);
                    *(uint32_t*)(g_a0lo + (size_t)pi1 * K0PAD + HEADC + col) = pack2h(l0, l1);
                }
            }
        }
    }
}

// ---------------- 4. f16 mma GEMM: 64x128 tiles, TERMS-way split ------------
#define GSTG  30720
#define GSMEM (3 * GSTG)

template <int KTOT, int RELU, int SPLIT, int TERMS>
__global__ void __launch_bounds__(256, 2) gemm_mma(
    const h16* __restrict__ aHi, const h16* __restrict__ aLo,
    const h16* __restrict__ wHi, const h16* __restrict__ wLo,
    const float* __restrict__ bias,
    h16* __restrict__ oHi, h16* __restrict__ oLo, int KOUT)
{
    extern __shared__ char smraw[];
    const int NK = KTOT / 32;
    int tid = threadIdx.x, lane = tid & 31, wid = tid >> 5;
    int warp_m = wid & 1, warp_n = wid >> 1;     // 2 x 4 warps, warp tile 32x32
    int m0 = blockIdx.x * 64, c0 = blockIdx.y * 128;

    uint32_t smBase = smem_u32(smraw);
    uint32_t rowA = (uint32_t)(warp_m * 32 + (lane & 15)) * 80 + (lane >> 4) * 16;
    uint32_t rowB = (uint32_t)(warp_n * 32 + (lane & 15)) * 80 + (lane >> 4) * 16;

    float acc[2][4][4];
#pragma unroll
    for (int a = 0; a < 2; a++)
#pragma unroll
        for (int b = 0; b < 4; b++)
#pragma unroll
            for (int c = 0; c < 4; c++) acc[a][b][c] = 0.f;

    auto loadStage = [&](int ks, int st) {
        uint32_t sbs = smBase + st * GSTG;
#pragma unroll
        for (int i = 0; i < 2; i++) {
            int c = tid + i * 256;
            int half = c >> 8, idx = c & 255;
            int row = idx >> 2, ch = idx & 3;
            const h16* src = (half ? aLo : aHi) + (size_t)(m0 + row) * KTOT + ks * 32 + ch * 8;
            CP_ASYNC16(sbs + half * 5120 + (uint32_t)row * 80 + ch * 16, src);
        }
#pragma unroll
        for (int i = 0; i < 4; i++) {
            int c = tid + i * 256;
            int half = c >> 9, idx = c & 511;
            int row = idx >> 2, ch = idx & 3;
            const h16* src = (half ? wLo : wHi) + (size_t)(c0 + row) * KTOT + ks * 32 + ch * 8;
            CP_ASYNC16(sbs + 10240 + half * 10240 + (uint32_t)row * 80 + ch * 16, src);
        }
        CP_COMMIT();
    };

    loadStage(0, 0);
    if (NK > 1) loadStage(1, 1);
    for (int ks = 0; ks < NK; ks++) {
        if (ks < NK - 1) CP_WAIT1(); else CP_WAIT0();
        __syncthreads();
        if (ks + 2 < NK) loadStage(ks + 2, (ks + 2) % 3);

        uint32_t sbs = smBase + (ks % 3) * GSTG;
#pragma unroll
        for (int s = 0; s < 2; s++) {
            uint32_t a2[2][2][4], b2r[2][2][4];
#pragma unroll
            for (int mf = 0; mf < 2; mf++) {
                uint32_t ad = sbs + rowA + (uint32_t)mf * (16 * 80) + s * 32;
                LDSM4(a2[0][mf], ad);
                LDSM4(a2[1][mf], ad + 5120);
            }
#pragma unroll
            for (int p = 0; p < 2; p++) {
                uint32_t bd = sbs + 10240 + rowB + (uint32_t)p * (16 * 80) + s * 32;
                LDSM4(b2r[0][p], bd);
                LDSM4(b2r[1][p], bd + 10240);
            }
            // term-major: HH, HL[, LH]
#pragma unroll
            for (int tt = 0; tt < TERMS; tt++) {
                const int ai = (tt == 2) ? 1 : 0;
                const int bi = (tt == 1) ? 1 : 0;
#pragma unroll
                for (int mf = 0; mf < 2; mf++)
#pragma unroll
                    for (int nf = 0; nf < 4; nf++) {
                        int p = nf >> 1, sel = nf & 1;
                        mma_f32(acc[mf][nf], a2[ai][mf],
                                b2r[bi][p][sel], b2r[bi][p][sel + 2]);
                    }
            }
        }
    }

    if (SPLIT) {
#pragma unroll
        for (int mf = 0; mf < 2; mf++) {
            int row = m0 + warp_m * 32 + mf * 16 + (lane >> 2);
#pragma unroll
            for (int nf = 0; nf < 4; nf++) {
                int col = c0 + warp_n * 32 + nf * 8 + 2 * (lane & 3);
                float b0v = bias[col], b1v = bias[col + 1];
                float v0 = acc[mf][nf][0] + b0v, v1 = acc[mf][nf][1] + b1v;
                float v2 = acc[mf][nf][2] + b0v, v3 = acc[mf][nf][3] + b1v;
                if (RELU) {
                    v0 = fmaxf(v0, 0.f); v1 = fmaxf(v1, 0.f);
                    v2 = fmaxf(v2, 0.f); v3 = fmaxf(v3, 0.f);
                }
                h16 h0, l0, h1, l1;
                f16_split(v0, h0, l0); f16_split(v1, h1, l1);
                *(uint32_t*)(oHi + (size_t)row * KOUT + col) = pack2h(h0, h1);
                *(uint32_t*)(oLo + (size_t)row * KOUT + col) = pack2h(l0, l1);
                f16_split(v2, h0, l0); f16_split(v3, h1, l1);
                *(uint32_t*)(oHi + (size_t)(row + 8) * KOUT + col) = pack2h(h0, h1);
                *(uint32_t*)(oLo + (size_t)(row + 8) * KOUT + col) = pack2h(l0, l1);
            }
        }
    } else {
        // ---- fused max-pool epilogue: partial max over 64 rows ----
        __syncthreads();
        float* pm = (float*)smraw;               // [2][128]
#pragma unroll
        for (int nf = 0; nf < 4; nf++) {
            float c0m = -FLT_MAX, c1m = -FLT_MAX;
#pragma unroll
            for (int mf = 0; mf < 2; mf++) {
                int col = c0 + warp_n * 32 + nf * 8 + 2 * (lane & 3);
                float b0v = bias[col], b1v = bias[col + 1];
                c0m = fmaxf(c0m, fmaxf(acc[mf][nf][0] + b0v, acc[mf][nf][2] + b0v));
                c1m = fmaxf(c1m, fmaxf(acc[mf][nf][1] + b1v, acc[mf][nf][3] + b1v));
            }
#pragma unroll
            for (int o = 4; o < 32; o <<= 1) {
                c0m = fmaxf(c0m, __shfl_xor_sync(0xFFFFFFFFu, c0m, o));
                c1m = fmaxf(c1m, __shfl_xor_sync(0xFFFFFFFFu, c1m, o));
            }
            if (lane < 4) {
                int cc = warp_n * 32 + nf * 8 + 2 * lane;
                pm[warp_m * 128 + cc]     = c0m;
                pm[warp_m * 128 + cc + 1] = c1m;
            }
        }
        __syncthreads();
        if (tid < 64) {
            int cc = tid * 2;
            float m0v = fmaxf(pm[cc],     pm[128 + cc]);
            float m1v = fmaxf(pm[cc + 1], pm[128 + cc + 1]);
            int b = m0 >> 10, part = (m0 >> 6) & (NPART - 1);
            *(float2*)(g_part + (size_t)(b * NPART + part) * C3OUT + c0 + cc)
                = make_float2(m0v, m1v);
        }
    }
}

// ---------------- 5. max pool final stage ----------------
__global__ void k_poolB(float* __restrict__ extra, int we) {
    int i = blockIdx.x * 256 + threadIdx.x;   // 8192
    float m = -FLT_MAX;
    int b = i >> 10, c = i & 1023;
#pragma unroll
    for (int part = 0; part < NPART; part++)
        m = fmaxf(m, g_part[(b * NPART + part) * C3OUT + c]);
    g_lat[i] = m;
    if (we) extra[i] = m;
}

// ---------------- 6. decoder MLP (32 cols x 8 K-slices per block) -----------
template <int RELU>
__global__ void __launch_bounds__(256) mlp8(
    const float* __restrict__ A, const float* __restrict__ W,
    const float* __restrict__ bias, float* __restrict__ Out,
    int K, int N)
{
    extern __shared__ float Ash[];
    __shared__ float red[256 * 8];
    int tid = threadIdx.x;
    for (int i = tid; i < 8 * K / 4; i += 256)
        ((float4*)Ash)[i] = ((const float4*)A)[i];
    __syncthreads();

    int col   = blockIdx.x * 32 + (tid & 31);    // full 128B line per warp
    int slice = tid >> 5;                        // 8 slices
    int kPer  = K >> 3;
    int k0    = slice * kPer;

    float acc[8];
#pragma unroll
    for (int bb = 0; bb < 8; bb++) acc[bb] = 0.f;

    for (int k = k0; k < k0 + kPer; k += 4) {
        float w0 = W[(size_t)(k + 0) * N + col];
        float w1 = W[(size_t)(k + 1) * N + col];
        float w2 = W[(size_t)(k + 2) * N + col];
        float w3 = W[(size_t)(k + 3) * N + col];
#pragma unroll
        for (int bb = 0; bb < 8; bb++) {
            float4 a4 = ((const float4*)(Ash + bb * K))[k >> 2];
            acc[bb] = fmaf(a4.x, w0, acc[bb]);
            acc[bb] = fmaf(a4.y, w1, acc[bb]);
            acc[bb] = fmaf(a4.z, w2, acc[bb]);
            acc[bb] = fmaf(a4.w, w3, acc[bb]);
        }
    }
#pragma unroll
    for (int bb = 0; bb < 8; bb++) red[tid * 8 + bb] = acc[bb];
    __syncthreads();
    if (tid < 32) {
        float bsv = bias[col];
#pragma unroll
        for (int bb = 0; bb < 8; bb++) {
            float v = bsv;
#pragma unroll
            for (int s = 0; s < 8; s++)
                v += red[(tid + s * 32) * 8 + bb];
            if (RELU) v = fmaxf(v, 0.f);
            Out[(size_t)bb * N + col] = v;
        }
    }
}

// ---------------- launch ----------------
extern "C" void kernel_launch(void* const* d_in, const int* in_sizes, int n_in,
                              void* d_out, int out_size) {
    const float* x    = (const float*)d_in[0];
    const int*   cats = (const int*)  d_in[1];
    const float* W1   = (const float*)d_in[2];
    const float* b1   = (const float*)d_in[3];
    const float* W2   = (const float*)d_in[4];
    const float* b2   = (const float*)d_in[5];
    const float* Wc1  = (const float*)d_in[6];
    const float* bc1  = (const float*)d_in[7];
    const float* Wc2  = (const float*)d_in[8];
    const float* bc2  = (const float*)d_in[9];
    const float* Wc3  = (const float*)d_in[10];
    const float* bc3  = (const float*)d_in[11];
    const float* Wd1  = (const float*)d_in[12];
    const float* bd1  = (const float*)d_in[13];
    const float* Wd2  = (const float*)d_in[14];
    const float* bd2  = (const float*)d_in[15];
    const float* Wd3  = (const float*)d_in[16];
    const float* bd3  = (const float*)d_in[17];
    float* out = (float*)d_out;

    cudaFuncSetAttribute(k_expert_mma, cudaFuncAttributeMaxDynamicSharedMemorySize, ESMEM);
    cudaFuncSetAttribute(mlp8<1>,  cudaFuncAttributeMaxDynamicSharedMemorySize, 65536);
    cudaFuncSetAttribute(mlp8<0>,  cudaFuncAttributeMaxDynamicSharedMemorySize, 65536);
    cudaFuncSetAttribute(gemm_mma<K0PAD, 1, 1, 3>, cudaFuncAttributeMaxDynamicSharedMemorySize, GSMEM);
    cudaFuncSetAttribute(gemm_mma<C1OUT, 1, 1, 2>, cudaFuncAttributeMaxDynamicSharedMemorySize, GSMEM);
    cudaFuncSetAttribute(gemm_mma<C2OUT, 0, 0, 2>, cudaFuncAttributeMaxDynamicSharedMemorySize, GSMEM);

    h16 *p_a0h, *p_a0l, *p_a1h, *p_a1l, *p_a2h, *p_a2l;
    h16 *p_w1h, *p_w1l, *p_w2h, *p_w2l, *p_w3h, *p_w3l;
    float *p_lat, *p_d1, *p_d2;
    cudaGetSymbolAddress((void**)&p_a0h, g_a0hi);
    cudaGetSymbolAddress((void**)&p_a0l, g_a0lo);
    cudaGetSymbolAddress((void**)&p_a1h, g_a1hi);
    cudaGetSymbolAddress((void**)&p_a1l, g_a1lo);
    cudaGetSymbolAddress((void**)&p_a2h, g_a2hi);
    cudaGetSymbolAddress((void**)&p_a2l, g_a2lo);
    cudaGetSymbolAddress((void**)&p_w1h, g_w1hi);
    cudaGetSymbolAddress((void**)&p_w1l, g_w1lo);
    cudaGetSymbolAddress((void**)&p_w2h, g_w2hi);
    cudaGetSymbolAddress((void**)&p_w2l, g_w2lo);
    cudaGetSymbolAddress((void**)&p_w3h, g_w3hi);
    cudaGetSymbolAddress((void**)&p_w3l, g_w3lo);
    cudaGetSymbolAddress((void**)&p_lat, g_lat);
    cudaGetSymbolAddress((void**)&p_d1,  g_d1);
    cudaGetSymbolAddress((void**)&p_d2,  g_d2);

    k_prep<<<PREP_NB, 256>>>(x, W1, W2, Wc1, Wc2, Wc3);
    k_build<<<1, 1024>>>(cats);
    k_expert_mma<<<MAXTILES, 256, ESMEM>>>(b1, b2);

    gemm_mma<K0PAD, 1, 1, 3><<<dim3(128, C1OUT / 128), 256, GSMEM>>>(
        p_a0h, p_a0l, p_w1h, p_w1l, bc1, p_a1h, p_a1l, C1OUT);
    gemm_mma<C1OUT, 1, 1, 2><<<dim3(128, C2OUT / 128), 256, GSMEM>>>(
        p_a1h, p_a1l, p_w2h, p_w2l, bc2, p_a2h, p_a2l, C2OUT);
    gemm_mma<C2OUT, 0, 0, 2><<<dim3(128, C3OUT / 128), 256, GSMEM>>>(
        p_a2h, p_a2l, p_w3h, p_w3l, bc3, (h16*)0, (h16*)0, C3OUT);

    int write_extra = (out_size >= 65536 + 8192) ? 1 : 0;
    k_poolB<<<NPOINTS / 256, 256>>>(out + 65536, write_extra);

    mlp8<1><<<DEC1 / 32, 256, 8 * DEC1 * 4>>>(p_lat, Wd1, bd1, p_d1, DEC1, DEC1);
    mlp8<1><<<DEC2 / 32, 256, 8 * DEC1 * 4>>>(p_d1,  Wd2, bd2, p_d2, DEC1, DEC2);
    mlp8<0><<<DEC3 / 32, 256, 8 * DEC2 * 4>>>(p_d2,  Wd3, bd3, out,  DEC2, DEC3);
}

// round 11
// speedup vs baseline: 1.1655x; 1.0863x over previous
#include <cuda_runtime.h>
#include <cuda_fp16.h>
#include <float.h>
#include <stdint.h>

// ---------------- problem constants ----------------
#define BATCH      8
#define NPTS       1024
#define NPOINTS    (BATCH * NPTS)        // 8192
#define HEADC      8
#define SHAPEC     256
#define XCH        (HEADC + SHAPEC)      // 264
#define NEXPERT    16
#define SC_HID     256
#define SC_OUT     128
#define K0PAD      160                   // 136 padded to 160
#define C1OUT      256
#define C2OUT      512
#define C3OUT      1024
#define DEC1       1024
#define DEC2       2048
#define DEC3       8192
#define ETILE      64
#define MAXTILES   (NPOINTS / ETILE + NEXPERT)   // 144
#define NPART      8                     // pool partials per batch (1024/128)

typedef __half h16;

// ---------------- scratch (device globals; no runtime alloc) ----------------
__device__ __align__(256) h16 g_xhi[NPOINTS * SHAPEC];
__device__ __align__(256) h16 g_xlo[NPOINTS * SHAPEC];
__device__ __align__(256) h16 g_a0hi[NPOINTS * K0PAD];
__device__ __align__(256) h16 g_a0lo[NPOINTS * K0PAD];
__device__ __align__(256) h16 g_a1hi[NPOINTS * C1OUT];
__device__ __align__(256) h16 g_a2hi[NPOINTS * C2OUT];
__device__ __align__(256) h16 g_w1hi[C1OUT * K0PAD];
__device__ __align__(256) h16 g_w1lo[C1OUT * K0PAD];
__device__ __align__(256) h16 g_w2hi[C2OUT * C1OUT];
__device__ __align__(256) h16 g_w2lo[C2OUT * C1OUT];
__device__ __align__(256) h16 g_w3hi[C3OUT * C2OUT];
__device__ __align__(256) h16 g_w3lo[C3OUT * C2OUT];
__device__ __align__(256) h16 g_e1hi[NEXPERT * SC_HID * SHAPEC];
__device__ __align__(256) h16 g_e1lo[NEXPERT * SC_HID * SHAPEC];
__device__ __align__(256) h16 g_e2hi[NEXPERT * SC_OUT * SC_HID];
__device__ __align__(256) h16 g_e2lo[NEXPERT * SC_OUT * SC_HID];
__device__ float g_part[BATCH * NPART * C3OUT];
__device__ float g_lat[BATCH * C3OUT];
__device__ float g_d1[BATCH * DEC1];
__device__ float g_d2[BATCH * DEC2];
__device__ int   g_idx[NPOINTS];
__device__ int   g_tileExpert[MAXTILES];
__device__ int   g_tileStart[MAXTILES];
__device__ int   g_tileLen[MAXTILES];
__device__ int   g_nTiles;

// ---------------- ptx helpers (sm_80-safe) ----------------
__device__ __forceinline__ uint32_t smem_u32(const void* p) {
    uint32_t a;
    asm("{ .reg .u64 t; cvta.to.shared.u64 t, %1; cvt.u32.u64 %0, t; }" : "=r"(a) : "l"(p));
    return a;
}
#define CP_ASYNC16(dst, src) \
    asm volatile("cp.async.cg.shared.global [%0], [%1], 16;" :: "r"(dst), "l"(src))
#define CP_COMMIT() asm volatile("cp.async.commit_group;" ::: "memory")
#define CP_WAIT0()  asm volatile("cp.async.wait_group 0;" ::: "memory")
#define CP_WAIT1()  asm volatile("cp.async.wait_group 1;" ::: "memory")

#define LDSM4(r, addr) \
    asm volatile("ldmatrix.sync.aligned.m8n8.x4.shared.b16 {%0,%1,%2,%3}, [%4];" \
        : "=r"((r)[0]), "=r"((r)[1]), "=r"((r)[2]), "=r"((r)[3]) : "r"(addr))

__device__ __forceinline__ void mma_f32(float* d, const uint32_t* a,
                                        uint32_t b0, uint32_t b1) {
    asm volatile(
        "mma.sync.aligned.m16n8k16.row.col.f32.f16.f16.f32 "
        "{%0,%1,%2,%3}, {%4,%5,%6,%7}, {%8,%9}, {%0,%1,%2,%3};"
        : "+f"(d[0]), "+f"(d[1]), "+f"(d[2]), "+f"(d[3])
        : "r"(a[0]), "r"(a[1]), "r"(a[2]), "r"(a[3]), "r"(b0), "r"(b1));
}

__device__ __forceinline__ void f16_split(float v, h16& h, h16& l) {
    h = __float2half_rn(v);
    l = __float2half_rn(v - __half2float(h));
}
__device__ __forceinline__ uint32_t pack2h(h16 a, h16 b) {
    __half2 t; t.x = a; t.y = b;
    return *(uint32_t*)&t;
}

// ---------------- 1. fused prep: transpose | tsplit | head | wsplit ---------
#define PREP_T1 2048
#define PREP_T2 3584
#define PREP_T3 4608
#define PREP_NB 7328
#define WS_NB1 160
#define WS_NB2 512

__global__ void __launch_bounds__(256) k_prep(
    const float* __restrict__ x,
    const float* __restrict__ W1, const float* __restrict__ W2,
    const float* __restrict__ Wc1, const float* __restrict__ Wc2,
    const float* __restrict__ Wc3)
{
    __shared__ float t[32][33];
    int bi = blockIdx.x;
    int tid = threadIdx.x;
    int tx = tid & 31, ty = tid >> 5;

    if (bi < PREP_T1) {
        int idx = bi;
        int cB = (idx & 7) * 32;
        int nB = ((idx >> 3) & 31) * 32;
        int b  = idx >> 8;
        const float* xb = x + (size_t)b * XCH * NPTS;
#pragma unroll
        for (int i = ty; i < 32; i += 8)
            t[i][tx] = xb[(size_t)(HEADC + cB + i) * NPTS + nB + tx];
        __syncthreads();
        size_t base = ((size_t)b * NPTS + nB) * SHAPEC + cB;
#pragma unroll
        for (int i = ty; i < 32; i += 8) {
            float v = t[tx][i];
            h16 h, l; f16_split(v, h, l);
            g_xhi[base + (size_t)i * SHAPEC + tx] = h;
            g_xlo[base + (size_t)i * SHAPEC + tx] = l;
        }
    } else if (bi < PREP_T2) {
        int r = bi - PREP_T1;
        const float* src; h16 *hi, *lo; int K, OUT, e, k0, o0;
        if (r < 1024) {
            e = r >> 6; int q = r & 63;
            k0 = (q & 7) * 32; o0 = (q >> 3) * 32;
            src = W1; hi = g_e1hi; lo = g_e1lo; K = SHAPEC; OUT = SC_HID;
        } else {
            r -= 1024;
            e = r >> 5; int q = r & 31;
            k0 = (q & 7) * 32; o0 = (q >> 3) * 32;
            src = W2; hi = g_e2hi; lo = g_e2lo; K = SC_HID; OUT = SC_OUT;
        }
        const float* s = src + (size_t)e * K * OUT;
#pragma unroll
        for (int i = ty; i < 32; i += 8)
            t[i][tx] = s[(size_t)(k0 + i) * OUT + o0 + tx];
        __syncthreads();
        size_t base = (size_t)e * OUT * K + (size_t)o0 * K + k0;
#pragma unroll
        for (int i = ty; i < 32; i += 8) {
            float v = t[tx][i];
            h16 h, l; f16_split(v, h, l);
            hi[base + (size_t)i * K + tx] = h;
            lo[base + (size_t)i * K + tx] = l;
        }
    } else if (bi < PREP_T3) {
        int i = (bi - PREP_T2) * 256 + tid;
        int p = i >> 5, s = i & 31;
        float v = 0.f;
        int col;
        if (s < 8) {
            int b = p >> 10, n = p & 1023;
            v = x[(size_t)b * XCH * NPTS + (size_t)s * NPTS + n];
            col = s;
        } else {
            col = 128 + s;
        }
        h16 h, l; f16_split(v, h, l);
        g_a0hi[(size_t)p * K0PAD + col] = h;
        g_a0lo[(size_t)p * K0PAD + col] = l;
    } else {
        int r = bi - PREP_T3;
        const float* w; h16 *hi, *lo; int Kin, Kpad, total, i;
        if (r < WS_NB1) {
            w = Wc1; hi = g_w1hi; lo = g_w1lo; Kin = 136; Kpad = K0PAD;
            total = C1OUT * K0PAD; i = r * 256 + tid;
        } else if (r < WS_NB1 + WS_NB2) {
            w = Wc2; hi = g_w2hi; lo = g_w2lo; Kin = C1OUT; Kpad = C1OUT;
            total = C2OUT * C1OUT; i = (r - WS_NB1) * 256 + tid;
        } else {
            w = Wc3; hi = g_w3hi; lo = g_w3lo; Kin = C2OUT; Kpad = C2OUT;
            total = C3OUT * C2OUT; i = (r - WS_NB1 - WS_NB2) * 256 + tid;
        }
        if (i >= total) return;
        int c = i / Kpad, k = i - c * Kpad;
        float v = (k < Kin) ? w[(size_t)c * Kin + k] : 0.f;
        h16 h, l; f16_split(v, h, l);
        hi[i] = h;
        lo[i] = l;
    }
}

// ---------------- 2. counting sort points by category (tiles of 64) ---------
__global__ void k_build(const int* __restrict__ cats) {
    __shared__ int cnt[NEXPERT];
    __shared__ int off[NEXPERT + 1];
    __shared__ int cur[NEXPERT];
    int tid = threadIdx.x;
    if (tid < NEXPERT) cnt[tid] = 0;
    __syncthreads();
    for (int i = tid; i < NPOINTS; i += blockDim.x) atomicAdd(&cnt[cats[i]], 1);
    __syncthreads();
    if (tid == 0) {
        int s = 0;
        for (int e = 0; e < NEXPERT; e++) { off[e] = s; s += cnt[e]; }
        off[NEXPERT] = s;
        int t = 0;
        for (int e = 0; e < NEXPERT; e++)
            for (int st = off[e]; st < off[e + 1]; st += ETILE) {
                g_tileExpert[t] = e;
                g_tileStart[t]  = st;
                g_tileLen[t]    = min(ETILE, off[e + 1] - st);
                t++;
            }
        g_nTiles = t;
    }
    __syncthreads();
    if (tid < NEXPERT) cur[tid] = off[tid];
    __syncthreads();
    for (int i = tid; i < NPOINTS; i += blockDim.x) {
        int pos = atomicAdd(&cur[cats[i]], 1);
        g_idx[pos] = i;
    }
}

// ---------------- 3. fused expert MLP on tensor cores (double-buffered) -----
#define ESM_A  0
#define ESM_B  20480
#define ESM_H  102400
#define ESMEM  184320

__global__ void __launch_bounds__(256) k_expert_mma(
    const float* __restrict__ b1g, const float* __restrict__ b2g)
{
    int t = blockIdx.x;
    if (t >= g_nTiles) return;
    int e = g_tileExpert[t], start = g_tileStart[t], len = g_tileLen[t];

    extern __shared__ char smraw[];
    __shared__ int pidx[ETILE];
    __shared__ int gidx[ETILE];

    int tid = threadIdx.x, lane = tid & 31, wid = tid >> 5;
    uint32_t sb = smem_u32(smraw);

    if (tid < ETILE) {
        int pi = (tid < len) ? g_idx[start + tid] : -1;
        pidx[tid] = pi;
        gidx[tid] = pi < 0 ? 0 : pi;
    }
    __syncthreads();

    const h16* w1h = g_e1hi + (size_t)e * SC_HID * SHAPEC;
    const h16* w1l = g_e1lo + (size_t)e * SC_HID * SHAPEC;
    const h16* w2h = g_e2hi + (size_t)e * SC_OUT * SC_HID;
    const h16* w2l = g_e2lo + (size_t)e * SC_OUT * SC_HID;

    auto loadS1 = [&](int ks, int st) {
#pragma unroll
        for (int r = 0; r < 2; r++) {
            int id = tid + r * 256;
            int half = id >> 8, idx = id & 255;
            int row = idx >> 2, ch = idx & 3;
            const h16* src = (half ? g_xlo : g_xhi)
                           + (size_t)gidx[row] * SHAPEC + ks * 32 + ch * 8;
            CP_ASYNC16(sb + ESM_A + st * 10240 + half * 5120 + (uint32_t)row * 80 + ch * 16, src);
        }
#pragma unroll
        for (int r = 0; r < 8; r++) {
            int id = tid + r * 256;
            int half = id >> 10, idx = id & 1023;
            int row = idx >> 2, ch = idx & 3;
            const h16* src = (half ? w1l : w1h)
                           + (size_t)row * SHAPEC + ks * 32 + ch * 8;
            CP_ASYNC16(sb + ESM_B + st * 40960 + half * 20480 + (uint32_t)row * 80 + ch * 16, src);
        }
        CP_COMMIT();
    };
    auto loadS2 = [&](int ks, int st) {
#pragma unroll
        for (int r = 0; r < 4; r++) {
            int id = tid + r * 256;
            int half = id >> 9, idx = id & 511;
            int row = idx >> 2, ch = idx & 3;
            const h16* src = (half ? w2l : w2h)
                           + (size_t)row * SC_HID + ks * 32 + ch * 8;
            CP_ASYNC16(sb + ESM_B + st * 20480 + half * 10240 + (uint32_t)row * 80 + ch * 16, src);
        }
        CP_COMMIT();
    };

    // ======== stage 1: h[64,256] = relu(A @ W1T + b1) ====
    {
        float acc[4][4][4];
#pragma unroll
        for (int a = 0; a < 4; a++)
#pragma unroll
            for (int b = 0; b < 4; b++)
#pragma unroll
                for (int c = 0; c < 4; c++) acc[a][b][c] = 0.f;

        uint32_t rowA = (uint32_t)(lane & 15) * 80 + (lane >> 4) * 16;
        uint32_t rowB = (uint32_t)(wid * 32 + (lane & 15)) * 80 + (lane >> 4) * 16;

        loadS1(0, 0);
        for (int ks = 0; ks < 8; ks++) {
            CP_WAIT0();
            __syncthreads();
            if (ks + 1 < 8) loadS1(ks + 1, (ks + 1) & 1);
            uint32_t sba = sb + ESM_A + (ks & 1) * 10240;
            uint32_t sbb = sb + ESM_B + (ks & 1) * 40960;
#pragma unroll
            for (int s = 0; s < 2; s++) {
                uint32_t a2[2][4][4], b2r[2][2][4];
#pragma unroll
                for (int mf = 0; mf < 4; mf++) {
                    uint32_t ad = sba + rowA + (uint32_t)mf * (16 * 80) + s * 32;
                    LDSM4(a2[0][mf], ad);
                    LDSM4(a2[1][mf], ad + 5120);
                }
#pragma unroll
                for (int p = 0; p < 2; p++) {
                    uint32_t bd = sbb + rowB + (uint32_t)p * (16 * 80) + s * 32;
                    LDSM4(b2r[0][p], bd);
                    LDSM4(b2r[1][p], bd + 20480);
                }
#pragma unroll
                for (int tt = 0; tt < 3; tt++) {
                    const int ai = (tt == 2) ? 1 : 0;
                    const int bi = (tt == 1) ? 1 : 0;
#pragma unroll
                    for (int mf = 0; mf < 4; mf++)
#pragma unroll
                        for (int nf = 0; nf < 4; nf++) {
                            int p = nf >> 1, sel = nf & 1;
                            mma_f32(acc[mf][nf], a2[ai][mf],
                                    b2r[bi][p][sel], b2r[bi][p][sel + 2]);
                        }
                }
            }
            __syncthreads();
        }

        loadS2(0, 0);

        const float* b1 = b1g + e * SC_HID;
#pragma unroll
        for (int mf = 0; mf < 4; mf++) {
            int row = mf * 16 + (lane >> 2);
#pragma unroll
            for (int nf = 0; nf < 4; nf++) {
                int col = wid * 32 + nf * 8 + 2 * (lane & 3);
                float b0v = b1[col], b1v = b1[col + 1];
                float v0 = fmaxf(acc[mf][nf][0] + b0v, 0.f);
                float v1 = fmaxf(acc[mf][nf][1] + b1v, 0.f);
                float v2 = fmaxf(acc[mf][nf][2] + b0v, 0.f);
                float v3 = fmaxf(acc[mf][nf][3] + b1v, 0.f);
                int ks = col >> 5, cw = col & 31;
                uint32_t off = (uint32_t)ks * 5120 + (uint32_t)row * 80 + cw * 2;
                h16 h0, l0, h1, l1;
                f16_split(v0, h0, l0); f16_split(v1, h1, l1);
                *(uint32_t*)(smraw + ESM_H + off)         = pack2h(h0, h1);
                *(uint32_t*)(smraw + ESM_H + 40960 + off) = pack2h(l0, l1);
                f16_split(v2, h0, l0); f16_split(v3, h1, l1);
                *(uint32_t*)(smraw + ESM_H + off + 8 * 80)         = pack2h(h0, h1);
                *(uint32_t*)(smraw + ESM_H + 40960 + off + 8 * 80) = pack2h(l0, l1);
            }
        }
    }
    __syncthreads();

    // ======== stage 2: o[64,128] = h @ W2T + b2 ====
    {
        int warp_m = wid & 1, warp_n = wid >> 1;
        float acc[2][4][4];
#pragma unroll
        for (int a = 0; a < 2; a++)
#pragma unroll
            for (int b = 0; b < 4; b++)
#pragma unroll
                for (int c = 0; c < 4; c++) acc[a][b][c] = 0.f;

        uint32_t rowA = (uint32_t)(warp_m * 32 + (lane & 15)) * 80 + (lane >> 4) * 16;
        uint32_t rowB = (uint32_t)(warp_n * 32 + (lane & 15)) * 80 + (lane >> 4) * 16;

        for (int ks = 0; ks < 8; ks++) {
            CP_WAIT0();
            __syncthreads();
            if (ks + 1 < 8) loadS2(ks + 1, (ks + 1) & 1);
            uint32_t hbase = sb + ESM_H + (uint32_t)ks * 5120;
            uint32_t sbb = sb + ESM_B + (ks & 1) * 20480;
#pragma unroll
            for (int s = 0; s < 2; s++) {
                uint32_t a2[2][2][4], b2r[2][2][4];
#pragma unroll
                for (int mf = 0; mf < 2; mf++) {
                    uint32_t ad = hbase + rowA + (uint32_t)mf * (16 * 80) + s * 32;
                    LDSM4(a2[0][mf], ad);
                    LDSM4(a2[1][mf], ad + 40960);
                }
#pragma unroll
                for (int p = 0; p < 2; p++) {
                    uint32_t bd = sbb + rowB + (uint32_t)p * (16 * 80) + s * 32;
                    LDSM4(b2r[0][p], bd);
                    LDSM4(b2r[1][p], bd + 10240);
                }
#pragma unroll
                for (int tt = 0; tt < 3; tt++) {
                    const int ai = (tt == 2) ? 1 : 0;
                    const int bi = (tt == 1) ? 1 : 0;
#pragma unroll
                    for (int mf = 0; mf < 2; mf++)
#pragma unroll
                        for (int nf = 0; nf < 4; nf++) {
                            int p = nf >> 1, sel = nf & 1;
                            mma_f32(acc[mf][nf], a2[ai][mf],
                                    b2r[bi][p][sel], b2r[bi][p][sel + 2]);
                        }
                }
            }
            __syncthreads();
        }

        const float* b2 = b2g + e * SC_OUT;
#pragma unroll
        for (int mf = 0; mf < 2; mf++) {
            int row = warp_m * 32 + mf * 16 + (lane >> 2);
#pragma unroll
            for (int nf = 0; nf < 4; nf++) {
                int col = warp_n * 32 + nf * 8 + 2 * (lane & 3);
                float b0v = b2[col], b1v = b2[col + 1];
                float v0 = acc[mf][nf][0] + b0v, v1 = acc[mf][nf][1] + b1v;
                float v2 = acc[mf][nf][2] + b0v, v3 = acc[mf][nf][3] + b1v;
                int pi0 = pidx[row], pi1 = pidx[row + 8];
                if (pi0 >= 0) {
                    h16 h0, l0, h1, l1;
                    f16_split(v0, h0, l0); f16_split(v1, h1, l1);
                    *(uint32_t*)(g_a0hi + (size_t)pi0 * K0PAD + HEADC + col) = pack2h(h0, h1);
                    *(uint32_t*)(g_a0lo + (size_t)pi0 * K0PAD + HEADC + col) = pack2h(l0, l1);
                }
                if (pi1 >= 0) {
                    h16 h0, l0, h1, l1;
                    f16_split(v2, h0, l0); f16_split(v3, h1, l1);
                    *(uint32_t*)(g_a0hi + (size_t)pi1 * K0PAD + HEADC + col) = pack2h(h0, h1);
                    *(uint32_t*)(g_a0lo + (size_t)pi1 * K0PAD + HEADC + col) = pack2h(l0, l1);
                }
            }
        }
    }
}

// ---------------- 4. f16 mma GEMM: FR*32-row tiles, hi-only outputs ---------
// stage layout: A-hi [MTILE*80] (+A-lo for TERMS==3) | B-hi @10240 | B-lo @20480
#define GSTG  30720
#define GSMEM (3 * GSTG)

template <int KTOT, int RELU, int SPLIT, int TERMS, int FR>
__global__ void __launch_bounds__(256, 2) gemm_mma(
    const h16* __restrict__ aHi, const h16* __restrict__ aLo,
    const h16* __restrict__ wHi, const h16* __restrict__ wLo,
    const float* __restrict__ bias,
    h16* __restrict__ oHi, int KOUT)
{
    extern __shared__ char smraw[];
    const int NK = KTOT / 32;
    const int MTILE = FR * 32;
    int tid = threadIdx.x, lane = tid & 31, wid = tid >> 5;
    int warp_m = wid & 1, warp_n = wid >> 1;     // 2 x 4 warps
    int m0 = blockIdx.x * MTILE, c0 = blockIdx.y * 128;

    uint32_t smBase = smem_u32(smraw);
    uint32_t rowA = (uint32_t)(warp_m * (FR * 16) + (lane & 15)) * 80 + (lane >> 4) * 16;
    uint32_t rowB = (uint32_t)(warp_n * 32 + (lane & 15)) * 80 + (lane >> 4) * 16;

    float acc[FR][4][4];
#pragma unroll
    for (int a = 0; a < FR; a++)
#pragma unroll
        for (int b = 0; b < 4; b++)
#pragma unroll
            for (int c = 0; c < 4; c++) acc[a][b][c] = 0.f;

    auto loadStage = [&](int ks, int st) {
        uint32_t sbs = smBase + st * GSTG;
        // A: hi (and lo when TERMS==3); total 512 chunks either way
#pragma unroll
        for (int i = 0; i < 2; i++) {
            int c = tid + i * 256;
            if (TERMS == 3) {
                int half = c >> 8, idx = c & 255;
                int row = idx >> 2, ch = idx & 3;
                const h16* src = (half ? aLo : aHi)
                               + (size_t)(m0 + row) * KTOT + ks * 32 + ch * 8;
                CP_ASYNC16(sbs + half * (MTILE * 80) + (uint32_t)row * 80 + ch * 16, src);
            } else {
                int row = c >> 2, ch = c & 3;   // rows 0..MTILE-1 (MTILE=128)
                const h16* src = aHi + (size_t)(m0 + row) * KTOT + ks * 32 + ch * 8;
                CP_ASYNC16(sbs + (uint32_t)row * 80 + ch * 16, src);
            }
        }
        // B: hi+lo, 1024 chunks
#pragma unroll
        for (int i = 0; i < 4; i++) {
            int c = tid + i * 256;
            int half = c >> 9, idx = c & 511;
            int row = idx >> 2, ch = idx & 3;
            const h16* src = (half ? wLo : wHi) + (size_t)(c0 + row) * KTOT + ks * 32 + ch * 8;
            CP_ASYNC16(sbs + 10240 + half * 10240 + (uint32_t)row * 80 + ch * 16, src);
        }
        CP_COMMIT();
    };

    loadStage(0, 0);
    if (NK > 1) loadStage(1, 1);
    for (int ks = 0; ks < NK; ks++) {
        if (ks < NK - 1) CP_WAIT1(); else CP_WAIT0();
        __syncthreads();
        if (ks + 2 < NK) loadStage(ks + 2, (ks + 2) % 3);

        uint32_t sbs = smBase + (ks % 3) * GSTG;
#pragma unroll
        for (int s = 0; s < 2; s++) {
            uint32_t aH[FR][4], aL[FR][4], b2r[2][2][4];
#pragma unroll
            for (int mf = 0; mf < FR; mf++) {
                uint32_t ad = sbs + rowA + (uint32_t)mf * (16 * 80) + s * 32;
                LDSM4(aH[mf], ad);
                if (TERMS == 3) LDSM4(aL[mf], ad + MTILE * 80);
            }
#pragma unroll
            for (int p = 0; p < 2; p++) {
                uint32_t bd = sbs + 10240 + rowB + (uint32_t)p * (16 * 80) + s * 32;
                LDSM4(b2r[0][p], bd);
                LDSM4(b2r[1][p], bd + 10240);
            }
            // term-major: HH, HL[, LH]
#pragma unroll
            for (int tt = 0; tt < TERMS; tt++) {
                const int bi = (tt == 1) ? 1 : 0;
#pragma unroll
                for (int mf = 0; mf < FR; mf++)
#pragma unroll
                    for (int nf = 0; nf < 4; nf++) {
                        int p = nf >> 1, sel = nf & 1;
                        mma_f32(acc[mf][nf], (tt == 2) ? aL[mf] : aH[mf],
                                b2r[bi][p][sel], b2r[bi][p][sel + 2]);
                    }
            }
        }
    }

    if (SPLIT) {
        // ---- epilogue: +bias, relu, hi-only f16 store ----
#pragma unroll
        for (int mf = 0; mf < FR; mf++) {
            int row = m0 + warp_m * (FR * 16) + mf * 16 + (lane >> 2);
#pragma unroll
            for (int nf = 0; nf < 4; nf++) {
                int col = c0 + warp_n * 32 + nf * 8 + 2 * (lane & 3);
                float b0v = bias[col], b1v = bias[col + 1];
                float v0 = acc[mf][nf][0] + b0v, v1 = acc[mf][nf][1] + b1v;
                float v2 = acc[mf][nf][2] + b0v, v3 = acc[mf][nf][3] + b1v;
                if (RELU) {
                    v0 = fmaxf(v0, 0.f); v1 = fmaxf(v1, 0.f);
                    v2 = fmaxf(v2, 0.f); v3 = fmaxf(v3, 0.f);
                }
                *(uint32_t*)(oHi + (size_t)row * KOUT + col)
                    = pack2h(__float2half_rn(v0), __float2half_rn(v1));
                *(uint32_t*)(oHi + (size_t)(row + 8) * KOUT + col)
                    = pack2h(__float2half_rn(v2), __float2half_rn(v3));
            }
        }
    } else {
        // ---- fused max-pool epilogue: partial max over MTILE rows ----
        __syncthreads();
        float* pm = (float*)smraw;               // [2][128]
#pragma unroll
        for (int nf = 0; nf < 4; nf++) {
            float c0m = -FLT_MAX, c1m = -FLT_MAX;
#pragma unroll
            for (int mf = 0; mf < FR; mf++) {
                int col = c0 + warp_n * 32 + nf * 8 + 2 * (lane & 3);
                float b0v = bias[col], b1v = bias[col + 1];
                c0m = fmaxf(c0m, fmaxf(acc[mf][nf][0] + b0v, acc[mf][nf][2] + b0v));
                c1m = fmaxf(c1m, fmaxf(acc[mf][nf][1] + b1v, acc[mf][nf][3] + b1v));
            }
#pragma unroll
            for (int o = 4; o < 32; o <<= 1) {
                c0m = fmaxf(c0m, __shfl_xor_sync(0xFFFFFFFFu, c0m, o));
                c1m = fmaxf(c1m, __shfl_xor_sync(0xFFFFFFFFu, c1m, o));
            }
            if (lane < 4) {
                int cc = warp_n * 32 + nf * 8 + 2 * lane;
                pm[warp_m * 128 + cc]     = c0m;
                pm[warp_m * 128 + cc + 1] = c1m;
            }
        }
        __syncthreads();
        if (tid < 64) {
            int cc = tid * 2;
            float m0v = fmaxf(pm[cc],     pm[128 + cc]);
            float m1v = fmaxf(pm[cc + 1], pm[128 + cc + 1]);
            int b = m0 >> 10, part = (m0 >> 7) & (NPART - 1);
            *(float2*)(g_part + (size_t)(b * NPART + part) * C3OUT + c0 + cc)
                = make_float2(m0v, m1v);
        }
    }
}

// ---------------- 5. max pool final stage ----------------
__global__ void k_poolB(float* __restrict__ extra, int we) {
    int i = blockIdx.x * 256 + threadIdx.x;   // 8192
    float m = -FLT_MAX;
    int b = i >> 10, c = i & 1023;
#pragma unroll
    for (int part = 0; part < NPART; part++)
        m = fmaxf(m, g_part[(b * NPART + part) * C3OUT + c]);
    g_lat[i] = m;
    if (we) extra[i] = m;
}

// ---------------- 6. decoder MLP (32 cols x 8 K-slices per block) -----------
template <int RELU>
__global__ void __launch_bounds__(256) mlp8(
    const float* __restrict__ A, const float* __restrict__ W,
    const float* __restrict__ bias, float* __restrict__ Out,
    int K, int N)
{
    extern __shared__ float Ash[];
    __shared__ float red[256 * 8];
    int tid = threadIdx.x;
    for (int i = tid; i < 8 * K / 4; i += 256)
        ((float4*)Ash)[i] = ((const float4*)A)[i];
    __syncthreads();

    int col   = blockIdx.x * 32 + (tid & 31);
    int slice = tid >> 5;
    int kPer  = K >> 3;
    int k0    = slice * kPer;

    float acc[8];
#pragma unroll
    for (int bb = 0; bb < 8; bb++) acc[bb] = 0.f;

    for (int k = k0; k < k0 + kPer; k += 4) {
        float w0 = W[(size_t)(k + 0) * N + col];
        float w1 = W[(size_t)(k + 1) * N + col];
        float w2 = W[(size_t)(k + 2) * N + col];
        float w3 = W[(size_t)(k + 3) * N + col];
#pragma unroll
        for (int bb = 0; bb < 8; bb++) {
            float4 a4 = ((const float4*)(Ash + bb * K))[k >> 2];
            acc[bb] = fmaf(a4.x, w0, acc[bb]);
            acc[bb] = fmaf(a4.y, w1, acc[bb]);
            acc[bb] = fmaf(a4.z, w2, acc[bb]);
            acc[bb] = fmaf(a4.w, w3, acc[bb]);
        }
    }
#pragma unroll
    for (int bb = 0; bb < 8; bb++) red[tid * 8 + bb] = acc[bb];
    __syncthreads();
    if (tid < 32) {
        float bsv = bias[col];
#pragma unroll
        for (int bb = 0; bb < 8; bb++) {
            float v = bsv;
#pragma unroll
            for (int s = 0; s < 8; s++)
                v += red[(tid + s * 32) * 8 + bb];
            if (RELU) v = fmaxf(v, 0.f);
            Out[(size_t)bb * N + col] = v;
        }
    }
}

// ---------------- launch ----------------
extern "C" void kernel_launch(void* const* d_in, const int* in_sizes, int n_in,
                              void* d_out, int out_size) {
    const float* x    = (const float*)d_in[0];
    const int*   cats = (const int*)  d_in[1];
    const float* W1   = (const float*)d_in[2];
    const float* b1   = (const float*)d_in[3];
    const float* W2   = (const float*)d_in[4];
    const float* b2   = (const float*)d_in[5];
    const float* Wc1  = (const float*)d_in[6];
    const float* bc1  = (const float*)d_in[7];
    const float* Wc2  = (const float*)d_in[8];
    const float* bc2  = (const float*)d_in[9];
    const float* Wc3  = (const float*)d_in[10];
    const float* bc3  = (const float*)d_in[11];
    const float* Wd1  = (const float*)d_in[12];
    const float* bd1  = (const float*)d_in[13];
    const float* Wd2  = (const float*)d_in[14];
    const float* bd2  = (const float*)d_in[15];
    const float* Wd3  = (const float*)d_in[16];
    const float* bd3  = (const float*)d_in[17];
    float* out = (float*)d_out;

    cudaFuncSetAttribute(k_expert_mma, cudaFuncAttributeMaxDynamicSharedMemorySize, ESMEM);
    cudaFuncSetAttribute(mlp8<1>,  cudaFuncAttributeMaxDynamicSharedMemorySize, 65536);
    cudaFuncSetAttribute(mlp8<0>,  cudaFuncAttributeMaxDynamicSharedMemorySize, 65536);
    cudaFuncSetAttribute(gemm_mma<K0PAD, 1, 1, 3, 2>, cudaFuncAttributeMaxDynamicSharedMemorySize, GSMEM);
    cudaFuncSetAttribute(gemm_mma<C1OUT, 1, 1, 2, 4>, cudaFuncAttributeMaxDynamicSharedMemorySize, GSMEM);
    cudaFuncSetAttribute(gemm_mma<C2OUT, 0, 0, 2, 4>, cudaFuncAttributeMaxDynamicSharedMemorySize, GSMEM);

    h16 *p_a0h, *p_a0l, *p_a1h, *p_a2h;
    h16 *p_w1h, *p_w1l, *p_w2h, *p_w2l, *p_w3h, *p_w3l;
    float *p_lat, *p_d1, *p_d2;
    cudaGetSymbolAddress((void**)&p_a0h, g_a0hi);
    cudaGetSymbolAddress((void**)&p_a0l, g_a0lo);
    cudaGetSymbolAddress((void**)&p_a1h, g_a1hi);
    cudaGetSymbolAddress((void**)&p_a2h, g_a2hi);
    cudaGetSymbolAddress((void**)&p_w1h, g_w1hi);
    cudaGetSymbolAddress((void**)&p_w1l, g_w1lo);
    cudaGetSymbolAddress((void**)&p_w2h, g_w2hi);
    cudaGetSymbolAddress((void**)&p_w2l, g_w2lo);
    cudaGetSymbolAddress((void**)&p_w3h, g_w3hi);
    cudaGetSymbolAddress((void**)&p_w3l, g_w3lo);
    cudaGetSymbolAddress((void**)&p_lat, g_lat);
    cudaGetSymbolAddress((void**)&p_d1,  g_d1);
    cudaGetSymbolAddress((void**)&p_d2,  g_d2);

    k_prep<<<PREP_NB, 256>>>(x, W1, W2, Wc1, Wc2, Wc3);
    k_build<<<1, 1024>>>(cats);
    k_expert_mma<<<MAXTILES, 256, ESMEM>>>(b1, b2);

    // conv stack: gemm1 64-row tiles TERMS=3; gemm2/3 128-row tiles TERMS=2
    gemm_mma<K0PAD, 1, 1, 3, 2><<<dim3(128, C1OUT / 128), 256, GSMEM>>>(
        p_a0h, p_a0l, p_w1h, p_w1l, bc1, p_a1h, C1OUT);
    gemm_mma<C1OUT, 1, 1, 2, 4><<<dim3(64, C2OUT / 128), 256, GSMEM>>>(
        p_a1h, (h16*)0, p_w2h, p_w2l, bc2, p_a2h, C2OUT);
    gemm_mma<C2OUT, 0, 0, 2, 4><<<dim3(64, C3OUT / 128), 256, GSMEM>>>(
        p_a2h, (h16*)0, p_w3h, p_w3l, bc3, (h16*)0, C3OUT);

    int write_extra = (out_size >= 65536 + 8192) ? 1 : 0;
    k_poolB<<<NPOINTS / 256, 256>>>(out + 65536, write_extra);

    mlp8<1><<<DEC1 / 32, 256, 8 * DEC1 * 4>>>(p_lat, Wd1, bd1, p_d1, DEC1, DEC1);
    mlp8<1><<<DEC2 / 32, 256, 8 * DEC1 * 4>>>(p_d1,  Wd2, bd2, p_d2, DEC1, DEC2);
    mlp8<0><<<DEC3 / 32, 256, 8 * DEC2 * 4>>>(p_d2,  Wd3, bd3, out,  DEC2, DEC3);
}

// round 12
// speedup vs baseline: 1.2067x; 1.0354x over previous
#include <cuda_runtime.h>
#include <cuda_fp16.h>
#include <float.h>
#include <stdint.h>

// ---------------- problem constants ----------------
#define BATCH      8
#define NPTS       1024
#define NPOINTS    (BATCH * NPTS)        // 8192
#define HEADC      8
#define SHAPEC     256
#define XCH        (HEADC + SHAPEC)      // 264
#define NEXPERT    16
#define SC_HID     256
#define SC_OUT     128
#define K0PAD      160                   // 136 padded to 160
#define C1OUT      256
#define C2OUT      512
#define C3OUT      1024
#define DEC1       1024
#define DEC2       2048
#define DEC3       8192
#define ETILE      64
#define MAXTILES   (NPOINTS / ETILE + NEXPERT)   // 144
#define NPART      8                     // pool partials per batch (1024/128)

typedef __half h16;

// ---------------- scratch (device globals; no runtime alloc) ----------------
__device__ __align__(256) h16 g_xhi[NPOINTS * SHAPEC];
__device__ __align__(256) h16 g_a0hi[NPOINTS * K0PAD];
__device__ __align__(256) h16 g_a1hi[NPOINTS * C1OUT];
__device__ __align__(256) h16 g_a2hi[NPOINTS * C2OUT];
__device__ __align__(256) h16 g_w1hi[C1OUT * K0PAD];
__device__ __align__(256) h16 g_w1lo[C1OUT * K0PAD];
__device__ __align__(256) h16 g_w2hi[C2OUT * C1OUT];
__device__ __align__(256) h16 g_w2lo[C2OUT * C1OUT];
__device__ __align__(256) h16 g_w3hi[C3OUT * C2OUT];
__device__ __align__(256) h16 g_w3lo[C3OUT * C2OUT];
__device__ __align__(256) h16 g_e1hi[NEXPERT * SC_HID * SHAPEC];
__device__ __align__(256) h16 g_e1lo[NEXPERT * SC_HID * SHAPEC];
__device__ __align__(256) h16 g_e2hi[NEXPERT * SC_OUT * SC_HID];
__device__ __align__(256) h16 g_e2lo[NEXPERT * SC_OUT * SC_HID];
__device__ float g_part[BATCH * NPART * C3OUT];
__device__ float g_lat[BATCH * C3OUT];
__device__ float g_d1[BATCH * DEC1];
__device__ float g_d2[BATCH * DEC2];
__device__ int   g_idx[NPOINTS];
__device__ int   g_tileExpert[MAXTILES];
__device__ int   g_tileStart[MAXTILES];
__device__ int   g_tileLen[MAXTILES];
__device__ int   g_nTiles;

// ---------------- ptx helpers (sm_80-safe) ----------------
__device__ __forceinline__ uint32_t smem_u32(const void* p) {
    uint32_t a;
    asm("{ .reg .u64 t; cvta.to.shared.u64 t, %1; cvt.u32.u64 %0, t; }" : "=r"(a) : "l"(p));
    return a;
}
#define CP_ASYNC16(dst, src) \
    asm volatile("cp.async.cg.shared.global [%0], [%1], 16;" :: "r"(dst), "l"(src))
#define CP_COMMIT() asm volatile("cp.async.commit_group;" ::: "memory")
#define CP_WAIT0()  asm volatile("cp.async.wait_group 0;" ::: "memory")
#define CP_WAIT1()  asm volatile("cp.async.wait_group 1;" ::: "memory")

#define LDSM4(r, addr) \
    asm volatile("ldmatrix.sync.aligned.m8n8.x4.shared.b16 {%0,%1,%2,%3}, [%4];" \
        : "=r"((r)[0]), "=r"((r)[1]), "=r"((r)[2]), "=r"((r)[3]) : "r"(addr))

__device__ __forceinline__ void mma_f32(float* d, const uint32_t* a,
                                        uint32_t b0, uint32_t b1) {
    asm volatile(
        "mma.sync.aligned.m16n8k16.row.col.f32.f16.f16.f32 "
        "{%0,%1,%2,%3}, {%4,%5,%6,%7}, {%8,%9}, {%0,%1,%2,%3};"
        : "+f"(d[0]), "+f"(d[1]), "+f"(d[2]), "+f"(d[3])
        : "r"(a[0]), "r"(a[1]), "r"(a[2]), "r"(a[3]), "r"(b0), "r"(b1));
}

__device__ __forceinline__ void f16_split(float v, h16& h, h16& l) {
    h = __float2half_rn(v);
    l = __float2half_rn(v - __half2float(h));
}
__device__ __forceinline__ uint32_t pack2h(h16 a, h16 b) {
    __half2 t; t.x = a; t.y = b;
    return *(uint32_t*)&t;
}

// ---------------- 1. fused prep: transpose | tsplit | head | wsplit ---------
#define PREP_T1 2048
#define PREP_T2 3584
#define PREP_T3 4608
#define PREP_NB 7328
#define WS_NB1 160
#define WS_NB2 512

__global__ void __launch_bounds__(256) k_prep(
    const float* __restrict__ x,
    const float* __restrict__ W1, const float* __restrict__ W2,
    const float* __restrict__ Wc1, const float* __restrict__ Wc2,
    const float* __restrict__ Wc3)
{
    __shared__ float t[32][33];
    int bi = blockIdx.x;
    int tid = threadIdx.x;
    int tx = tid & 31, ty = tid >> 5;

    if (bi < PREP_T1) {
        // ---- transpose x shape feats -> g_xhi (hi only) ----
        int idx = bi;
        int cB = (idx & 7) * 32;
        int nB = ((idx >> 3) & 31) * 32;
        int b  = idx >> 8;
        const float* xb = x + (size_t)b * XCH * NPTS;
#pragma unroll
        for (int i = ty; i < 32; i += 8)
            t[i][tx] = xb[(size_t)(HEADC + cB + i) * NPTS + nB + tx];
        __syncthreads();
        size_t base = ((size_t)b * NPTS + nB) * SHAPEC + cB;
#pragma unroll
        for (int i = ty; i < 32; i += 8)
            g_xhi[base + (size_t)i * SHAPEC + tx] = __float2half_rn(t[tx][i]);
    } else if (bi < PREP_T2) {
        // ---- expert weight transpose + hi/lo split ----
        int r = bi - PREP_T1;
        const float* src; h16 *hi, *lo; int K, OUT, e, k0, o0;
        if (r < 1024) {
            e = r >> 6; int q = r & 63;
            k0 = (q & 7) * 32; o0 = (q >> 3) * 32;
            src = W1; hi = g_e1hi; lo = g_e1lo; K = SHAPEC; OUT = SC_HID;
        } else {
            r -= 1024;
            e = r >> 5; int q = r & 31;
            k0 = (q & 7) * 32; o0 = (q >> 3) * 32;
            src = W2; hi = g_e2hi; lo = g_e2lo; K = SC_HID; OUT = SC_OUT;
        }
        const float* s = src + (size_t)e * K * OUT;
#pragma unroll
        for (int i = ty; i < 32; i += 8)
            t[i][tx] = s[(size_t)(k0 + i) * OUT + o0 + tx];
        __syncthreads();
        size_t base = (size_t)e * OUT * K + (size_t)o0 * K + k0;
#pragma unroll
        for (int i = ty; i < 32; i += 8) {
            float v = t[tx][i];
            h16 h, l; f16_split(v, h, l);
            hi[base + (size_t)i * K + tx] = h;
            lo[base + (size_t)i * K + tx] = l;
        }
    } else if (bi < PREP_T3) {
        // ---- head channels + pad -> a0hi only ----
        int i = (bi - PREP_T2) * 256 + tid;
        int p = i >> 5, s = i & 31;
        float v = 0.f;
        int col;
        if (s < 8) {
            int b = p >> 10, n = p & 1023;
            v = x[(size_t)b * XCH * NPTS + (size_t)s * NPTS + n];
            col = s;
        } else {
            col = 128 + s;
        }
        g_a0hi[(size_t)p * K0PAD + col] = __float2half_rn(v);
    } else {
        // ---- conv weight hi/lo split+pad ----
        int r = bi - PREP_T3;
        const float* w; h16 *hi, *lo; int Kin, Kpad, total, i;
        if (r < WS_NB1) {
            w = Wc1; hi = g_w1hi; lo = g_w1lo; Kin = 136; Kpad = K0PAD;
            total = C1OUT * K0PAD; i = r * 256 + tid;
        } else if (r < WS_NB1 + WS_NB2) {
            w = Wc2; hi = g_w2hi; lo = g_w2lo; Kin = C1OUT; Kpad = C1OUT;
            total = C2OUT * C1OUT; i = (r - WS_NB1) * 256 + tid;
        } else {
            w = Wc3; hi = g_w3hi; lo = g_w3lo; Kin = C2OUT; Kpad = C2OUT;
            total = C3OUT * C2OUT; i = (r - WS_NB1 - WS_NB2) * 256 + tid;
        }
        if (i >= total) return;
        int c = i / Kpad, k = i - c * Kpad;
        float v = (k < Kin) ? w[(size_t)c * Kin + k] : 0.f;
        h16 h, l; f16_split(v, h, l);
        hi[i] = h;
        lo[i] = l;
    }
}

// ---------------- 2. counting sort points by category (tiles of 64) ---------
__global__ void k_build(const int* __restrict__ cats) {
    __shared__ int cnt[NEXPERT];
    __shared__ int off[NEXPERT + 1];
    __shared__ int cur[NEXPERT];
    int tid = threadIdx.x;
    if (tid < NEXPERT) cnt[tid] = 0;
    __syncthreads();
    for (int i = tid; i < NPOINTS; i += blockDim.x) atomicAdd(&cnt[cats[i]], 1);
    __syncthreads();
    if (tid == 0) {
        int s = 0;
        for (int e = 0; e < NEXPERT; e++) { off[e] = s; s += cnt[e]; }
        off[NEXPERT] = s;
        int t = 0;
        for (int e = 0; e < NEXPERT; e++)
            for (int st = off[e]; st < off[e + 1]; st += ETILE) {
                g_tileExpert[t] = e;
                g_tileStart[t]  = st;
                g_tileLen[t]    = min(ETILE, off[e + 1] - st);
                t++;
            }
        g_nTiles = t;
    }
    __syncthreads();
    if (tid < NEXPERT) cur[tid] = off[tid];
    __syncthreads();
    for (int i = tid; i < NPOINTS; i += blockDim.x) {
        int pos = atomicAdd(&cur[cats[i]], 1);
        g_idx[pos] = i;
    }
}

// ---------------- 3. fused expert MLP (TERMS=2, hi-only activations) --------
// smem: A 2x5120 @0; B 2x40960 @10240; H 40960 @92160 -> 133120 B
#define ESM_A  0
#define ESM_B  10240
#define ESM_H  92160
#define ESMEM  133120

__global__ void __launch_bounds__(256) k_expert_mma(
    const float* __restrict__ b1g, const float* __restrict__ b2g)
{
    int t = blockIdx.x;
    if (t >= g_nTiles) return;
    int e = g_tileExpert[t], start = g_tileStart[t], len = g_tileLen[t];

    extern __shared__ char smraw[];
    __shared__ int pidx[ETILE];
    __shared__ int gidx[ETILE];

    int tid = threadIdx.x, lane = tid & 31, wid = tid >> 5;
    uint32_t sb = smem_u32(smraw);

    if (tid < ETILE) {
        int pi = (tid < len) ? g_idx[start + tid] : -1;
        pidx[tid] = pi;
        gidx[tid] = pi < 0 ? 0 : pi;
    }
    __syncthreads();

    const h16* w1h = g_e1hi + (size_t)e * SC_HID * SHAPEC;
    const h16* w1l = g_e1lo + (size_t)e * SC_HID * SHAPEC;
    const h16* w2h = g_e2hi + (size_t)e * SC_OUT * SC_HID;
    const h16* w2l = g_e2lo + (size_t)e * SC_OUT * SC_HID;

    auto loadS1 = [&](int ks, int st) {
        // A-hi: 256 chunks (64 rows x 4)
        {
            int row = tid >> 2, ch = tid & 3;
            const h16* src = g_xhi + (size_t)gidx[row] * SHAPEC + ks * 32 + ch * 8;
            CP_ASYNC16(sb + ESM_A + st * 5120 + (uint32_t)row * 80 + ch * 16, src);
        }
        // B hi+lo: 2048 chunks
#pragma unroll
        for (int r = 0; r < 8; r++) {
            int id = tid + r * 256;
            int half = id >> 10, idx = id & 1023;
            int row = idx >> 2, ch = idx & 3;
            const h16* src = (half ? w1l : w1h)
                           + (size_t)row * SHAPEC + ks * 32 + ch * 8;
            CP_ASYNC16(sb + ESM_B + st * 40960 + half * 20480 + (uint32_t)row * 80 + ch * 16, src);
        }
        CP_COMMIT();
    };
    auto loadS2 = [&](int ks, int st) {
        // B hi+lo: 1024 chunks
#pragma unroll
        for (int r = 0; r < 4; r++) {
            int id = tid + r * 256;
            int half = id >> 9, idx = id & 511;
            int row = idx >> 2, ch = idx & 3;
            const h16* src = (half ? w2l : w2h)
                           + (size_t)row * SC_HID + ks * 32 + ch * 8;
            CP_ASYNC16(sb + ESM_B + st * 20480 + half * 10240 + (uint32_t)row * 80 + ch * 16, src);
        }
        CP_COMMIT();
    };

    // ======== stage 1: h[64,256] = relu(A @ W1T + b1), TERMS=2 ====
    {
        float acc[4][4][4];
#pragma unroll
        for (int a = 0; a < 4; a++)
#pragma unroll
            for (int b = 0; b < 4; b++)
#pragma unroll
                for (int c = 0; c < 4; c++) acc[a][b][c] = 0.f;

        uint32_t rowA = (uint32_t)(lane & 15) * 80 + (lane >> 4) * 16;
        uint32_t rowB = (uint32_t)(wid * 32 + (lane & 15)) * 80 + (lane >> 4) * 16;

        loadS1(0, 0);
        for (int ks = 0; ks < 8; ks++) {
            CP_WAIT0();
            __syncthreads();
            if (ks + 1 < 8) loadS1(ks + 1, (ks + 1) & 1);
            uint32_t sba = sb + ESM_A + (ks & 1) * 5120;
            uint32_t sbb = sb + ESM_B + (ks & 1) * 40960;
#pragma unroll
            for (int s = 0; s < 2; s++) {
                uint32_t aH[4][4], b2r[2][2][4];
#pragma unroll
                for (int mf = 0; mf < 4; mf++) {
                    uint32_t ad = sba + rowA + (uint32_t)mf * (16 * 80) + s * 32;
                    LDSM4(aH[mf], ad);
                }
#pragma unroll
                for (int p = 0; p < 2; p++) {
                    uint32_t bd = sbb + rowB + (uint32_t)p * (16 * 80) + s * 32;
                    LDSM4(b2r[0][p], bd);
                    LDSM4(b2r[1][p], bd + 20480);
                }
#pragma unroll
                for (int tt = 0; tt < 2; tt++)
#pragma unroll
                    for (int mf = 0; mf < 4; mf++)
#pragma unroll
                        for (int nf = 0; nf < 4; nf++) {
                            int p = nf >> 1, sel = nf & 1;
                            mma_f32(acc[mf][nf], aH[mf],
                                    b2r[tt][p][sel], b2r[tt][p][sel + 2]);
                        }
            }
            __syncthreads();
        }

        loadS2(0, 0);

        // epilogue1: +b1, relu, hi-only -> smem H
        const float* b1 = b1g + e * SC_HID;
#pragma unroll
        for (int mf = 0; mf < 4; mf++) {
            int row = mf * 16 + (lane >> 2);
#pragma unroll
            for (int nf = 0; nf < 4; nf++) {
                int col = wid * 32 + nf * 8 + 2 * (lane & 3);
                float b0v = b1[col], b1v = b1[col + 1];
                float v0 = fmaxf(acc[mf][nf][0] + b0v, 0.f);
                float v1 = fmaxf(acc[mf][nf][1] + b1v, 0.f);
                float v2 = fmaxf(acc[mf][nf][2] + b0v, 0.f);
                float v3 = fmaxf(acc[mf][nf][3] + b1v, 0.f);
                int ks = col >> 5, cw = col & 31;
                uint32_t off = (uint32_t)ks * 5120 + (uint32_t)row * 80 + cw * 2;
                *(uint32_t*)(smraw + ESM_H + off)
                    = pack2h(__float2half_rn(v0), __float2half_rn(v1));
                *(uint32_t*)(smraw + ESM_H + off + 8 * 80)
                    = pack2h(__float2half_rn(v2), __float2half_rn(v3));
            }
        }
    }
    __syncthreads();

    // ======== stage 2: o[64,128] = h @ W2T + b2, TERMS=2 ====
    {
        int warp_m = wid & 1, warp_n = wid >> 1;
        float acc[2][4][4];
#pragma unroll
        for (int a = 0; a < 2; a++)
#pragma unroll
            for (int b = 0; b < 4; b++)
#pragma unroll
                for (int c = 0; c < 4; c++) acc[a][b][c] = 0.f;

        uint32_t rowA = (uint32_t)(warp_m * 32 + (lane & 15)) * 80 + (lane >> 4) * 16;
        uint32_t rowB = (uint32_t)(warp_n * 32 + (lane & 15)) * 80 + (lane >> 4) * 16;

        for (int ks = 0; ks < 8; ks++) {
            CP_WAIT0();
            __syncthreads();
            if (ks + 1 < 8) loadS2(ks + 1, (ks + 1) & 1);
            uint32_t hbase = sb + ESM_H + (uint32_t)ks * 5120;
            uint32_t sbb = sb + ESM_B + (ks & 1) * 20480;
#pragma unroll
            for (int s = 0; s < 2; s++) {
                uint32_t aH[2][4], b2r[2][2][4];
#pragma unroll
                for (int mf = 0; mf < 2; mf++) {
                    uint32_t ad = hbase + rowA + (uint32_t)mf * (16 * 80) + s * 32;
                    LDSM4(aH[mf], ad);
                }
#pragma unroll
                for (int p = 0; p < 2; p++) {
                    uint32_t bd = sbb + rowB + (uint32_t)p * (16 * 80) + s * 32;
                    LDSM4(b2r[0][p], bd);
                    LDSM4(b2r[1][p], bd + 10240);
                }
#pragma unroll
                for (int tt = 0; tt < 2; tt++)
#pragma unroll
                    for (int mf = 0; mf < 2; mf++)
#pragma unroll
                        for (int nf = 0; nf < 4; nf++) {
                            int p = nf >> 1, sel = nf & 1;
                            mma_f32(acc[mf][nf], aH[mf],
                                    b2r[tt][p][sel], b2r[tt][p][sel + 2]);
                        }
            }
            __syncthreads();
        }

        // epilogue2: +b2, hi-only scatter to g_a0hi
        const float* b2 = b2g + e * SC_OUT;
#pragma unroll
        for (int mf = 0; mf < 2; mf++) {
            int row = warp_m * 32 + mf * 16 + (lane >> 2);
#pragma unroll
            for (int nf = 0; nf < 4; nf++) {
                int col = warp_n * 32 + nf * 8 + 2 * (lane & 3);
                float b0v = b2[col], b1v = b2[col + 1];
                float v0 = acc[mf][nf][0] + b0v, v1 = acc[mf][nf][1] + b1v;
                float v2 = acc[mf][nf][2] + b0v, v3 = acc[mf][nf][3] + b1v;
                int pi0 = pidx[row], pi1 = pidx[row + 8];
                if (pi0 >= 0)
                    *(uint32_t*)(g_a0hi + (size_t)pi0 * K0PAD + HEADC + col)
                        = pack2h(__float2half_rn(v0), __float2half_rn(v1));
                if (pi1 >= 0)
                    *(uint32_t*)(g_a0hi + (size_t)pi1 * K0PAD + HEADC + col)
                        = pack2h(__float2half_rn(v2), __float2half_rn(v3));
            }
        }
    }
}

// ---------------- 4. f16 mma GEMM: TERMS=2, A-hi only, FR*32-row tiles ------
// stage: A-hi [MTILE*80] | B-hi | B-lo (each 10240)
template <int KTOT, int RELU, int SPLIT, int FR>
__global__ void __launch_bounds__(256, 2) gemm_mma(
    const h16* __restrict__ aHi,
    const h16* __restrict__ wHi, const h16* __restrict__ wLo,
    const float* __restrict__ bias,
    h16* __restrict__ oHi, int KOUT)
{
    extern __shared__ char smraw[];
    const int NK = KTOT / 32;
    const int MTILE = FR * 32;
    const int ASZ = MTILE * 80;
    const int STG = ASZ + 20480;
    int tid = threadIdx.x, lane = tid & 31, wid = tid >> 5;
    int warp_m = wid & 1, warp_n = wid >> 1;     // 2 x 4 warps
    int m0 = blockIdx.x * MTILE, c0 = blockIdx.y * 128;

    uint32_t smBase = smem_u32(smraw);
    uint32_t rowA = (uint32_t)(warp_m * (FR * 16) + (lane & 15)) * 80 + (lane >> 4) * 16;
    uint32_t rowB = (uint32_t)(warp_n * 32 + (lane & 15)) * 80 + (lane >> 4) * 16;

    float acc[FR][4][4];
#pragma unroll
    for (int a = 0; a < FR; a++)
#pragma unroll
        for (int b = 0; b < 4; b++)
#pragma unroll
            for (int c = 0; c < 4; c++) acc[a][b][c] = 0.f;

    auto loadStage = [&](int ks, int st) {
        uint32_t sbs = smBase + st * STG;
        // A-hi: MTILE*4 chunks
#pragma unroll
        for (int i = 0; i < MTILE * 4; i += 256) {
            int c = tid + i;
            int row = c >> 2, ch = c & 3;
            const h16* src = aHi + (size_t)(m0 + row) * KTOT + ks * 32 + ch * 8;
            CP_ASYNC16(sbs + (uint32_t)row * 80 + ch * 16, src);
        }
        // B hi+lo: 1024 chunks
#pragma unroll
        for (int i = 0; i < 4; i++) {
            int c = tid + i * 256;
            int half = c >> 9, idx = c & 511;
            int row = idx >> 2, ch = idx & 3;
            const h16* src = (half ? wLo : wHi) + (size_t)(c0 + row) * KTOT + ks * 32 + ch * 8;
            CP_ASYNC16(sbs + ASZ + half * 10240 + (uint32_t)row * 80 + ch * 16, src);
        }
        CP_COMMIT();
    };

    loadStage(0, 0);
    if (NK > 1) loadStage(1, 1);
    for (int ks = 0; ks < NK; ks++) {
        if (ks < NK - 1) CP_WAIT1(); else CP_WAIT0();
        __syncthreads();
        if (ks + 2 < NK) loadStage(ks + 2, (ks + 2) % 3);

        uint32_t sbs = smBase + (ks % 3) * STG;
#pragma unroll
        for (int s = 0; s < 2; s++) {
            uint32_t aH[FR][4], b2r[2][2][4];
#pragma unroll
            for (int mf = 0; mf < FR; mf++) {
                uint32_t ad = sbs + rowA + (uint32_t)mf * (16 * 80) + s * 32;
                LDSM4(aH[mf], ad);
            }
#pragma unroll
            for (int p = 0; p < 2; p++) {
                uint32_t bd = sbs + ASZ + rowB + (uint32_t)p * (16 * 80) + s * 32;
                LDSM4(b2r[0][p], bd);
                LDSM4(b2r[1][p], bd + 10240);
            }
            // term-major: HH then HL
#pragma unroll
            for (int tt = 0; tt < 2; tt++)
#pragma unroll
                for (int mf = 0; mf < FR; mf++)
#pragma unroll
                    for (int nf = 0; nf < 4; nf++) {
                        int p = nf >> 1, sel = nf & 1;
                        mma_f32(acc[mf][nf], aH[mf],
                                b2r[tt][p][sel], b2r[tt][p][sel + 2]);
                    }
        }
    }

    if (SPLIT) {
        // ---- epilogue: +bias, relu, hi-only f16 store ----
#pragma unroll
        for (int mf = 0; mf < FR; mf++) {
            int row = m0 + warp_m * (FR * 16) + mf * 16 + (lane >> 2);
#pragma unroll
            for (int nf = 0; nf < 4; nf++) {
                int col = c0 + warp_n * 32 + nf * 8 + 2 * (lane & 3);
                float b0v = bias[col], b1v = bias[col + 1];
                float v0 = acc[mf][nf][0] + b0v, v1 = acc[mf][nf][1] + b1v;
                float v2 = acc[mf][nf][2] + b0v, v3 = acc[mf][nf][3] + b1v;
                if (RELU) {
                    v0 = fmaxf(v0, 0.f); v1 = fmaxf(v1, 0.f);
                    v2 = fmaxf(v2, 0.f); v3 = fmaxf(v3, 0.f);
                }
                *(uint32_t*)(oHi + (size_t)row * KOUT + col)
                    = pack2h(__float2half_rn(v0), __float2half_rn(v1));
                *(uint32_t*)(oHi + (size_t)(row + 8) * KOUT + col)
                    = pack2h(__float2half_rn(v2), __float2half_rn(v3));
            }
        }
    } else {
        // ---- fused max-pool epilogue: partial max over MTILE rows ----
        __syncthreads();
        float* pm = (float*)smraw;               // [2][128]
#pragma unroll
        for (int nf = 0; nf < 4; nf++) {
            float c0m = -FLT_MAX, c1m = -FLT_MAX;
#pragma unroll
            for (int mf = 0; mf < FR; mf++) {
                int col = c0 + warp_n * 32 + nf * 8 + 2 * (lane & 3);
                float b0v = bias[col], b1v = bias[col + 1];
                c0m = fmaxf(c0m, fmaxf(acc[mf][nf][0] + b0v, acc[mf][nf][2] + b0v));
                c1m = fmaxf(c1m, fmaxf(acc[mf][nf][1] + b1v, acc[mf][nf][3] + b1v));
            }
#pragma unroll
            for (int o = 4; o < 32; o <<= 1) {
                c0m = fmaxf(c0m, __shfl_xor_sync(0xFFFFFFFFu, c0m, o));
                c1m = fmaxf(c1m, __shfl_xor_sync(0xFFFFFFFFu, c1m, o));
            }
            if (lane < 4) {
                int cc = warp_n * 32 + nf * 8 + 2 * lane;
                pm[warp_m * 128 + cc]     = c0m;
                pm[warp_m * 128 + cc + 1] = c1m;
            }
        }
        __syncthreads();
        if (tid < 64) {
            int cc = tid * 2;
            float m0v = fmaxf(pm[cc],     pm[128 + cc]);
            float m1v = fmaxf(pm[cc + 1], pm[128 + cc + 1]);
            int b = m0 >> 10, part = (m0 >> 7) & (NPART - 1);
            *(float2*)(g_part + (size_t)(b * NPART + part) * C3OUT + c0 + cc)
                = make_float2(m0v, m1v);
        }
    }
}

// ---------------- 5. max pool final stage ----------------
__global__ void k_poolB(float* __restrict__ extra, int we) {
    int i = blockIdx.x * 256 + threadIdx.x;   // 8192
    float m = -FLT_MAX;
    int b = i >> 10, c = i & 1023;
#pragma unroll
    for (int part = 0; part < NPART; part++)
        m = fmaxf(m, g_part[(b * NPART + part) * C3OUT + c]);
    g_lat[i] = m;
    if (we) extra[i] = m;
}

// ---------------- 6. decoder MLP (32 cols x 8 K-slices per block) -----------
template <int RELU>
__global__ void __launch_bounds__(256) mlp8(
    const float* __restrict__ A, const float* __restrict__ W,
    const float* __restrict__ bias, float* __restrict__ Out,
    int K, int N)
{
    extern __shared__ float Ash[];
    __shared__ float red[256 * 8];
    int tid = threadIdx.x;
    for (int i = tid; i < 8 * K / 4; i += 256)
        ((float4*)Ash)[i] = ((const float4*)A)[i];
    __syncthreads();

    int col   = blockIdx.x * 32 + (tid & 31);
    int slice = tid >> 5;
    int kPer  = K >> 3;
    int k0    = slice * kPer;

    float acc[8];
#pragma unroll
    for (int bb = 0; bb < 8; bb++) acc[bb] = 0.f;

    for (int k = k0; k < k0 + kPer; k += 4) {
        float w0 = W[(size_t)(k + 0) * N + col];
        float w1 = W[(size_t)(k + 1) * N + col];
        float w2 = W[(size_t)(k + 2) * N + col];
        float w3 = W[(size_t)(k + 3) * N + col];
#pragma unroll
        for (int bb = 0; bb < 8; bb++) {
            float4 a4 = ((const float4*)(Ash + bb * K))[k >> 2];
            acc[bb] = fmaf(a4.x, w0, acc[bb]);
            acc[bb] = fmaf(a4.y, w1, acc[bb]);
            acc[bb] = fmaf(a4.z, w2, acc[bb]);
            acc[bb] = fmaf(a4.w, w3, acc[bb]);
        }
    }
#pragma unroll
    for (int bb = 0; bb < 8; bb++) red[tid * 8 + bb] = acc[bb];
    __syncthreads();
    if (tid < 32) {
        float bsv = bias[col];
#pragma unroll
        for (int bb = 0; bb < 8; bb++) {
            float v = bsv;
#pragma unroll
            for (int s = 0; s < 8; s++)
                v += red[(tid + s * 32) * 8 + bb];
            if (RELU) v = fmaxf(v, 0.f);
            Out[(size_t)bb * N + col] = v;
        }
    }
}

// ---------------- launch ----------------
extern "C" void kernel_launch(void* const* d_in, const int* in_sizes, int n_in,
                              void* d_out, int out_size) {
    const float* x    = (const float*)d_in[0];
    const int*   cats = (const int*)  d_in[1];
    const float* W1   = (const float*)d_in[2];
    const float* b1   = (const float*)d_in[3];
    const float* W2   = (const float*)d_in[4];
    const float* b2   = (const float*)d_in[5];
    const float* Wc1  = (const float*)d_in[6];
    const float* bc1  = (const float*)d_in[7];
    const float* Wc2  = (const float*)d_in[8];
    const float* bc2  = (const float*)d_in[9];
    const float* Wc3  = (const float*)d_in[10];
    const float* bc3  = (const float*)d_in[11];
    const float* Wd1  = (const float*)d_in[12];
    const float* bd1  = (const float*)d_in[13];
    const float* Wd2  = (const float*)d_in[14];
    const float* bd2  = (const float*)d_in[15];
    const float* Wd3  = (const float*)d_in[16];
    const float* bd3  = (const float*)d_in[17];
    float* out = (float*)d_out;

    const int GS1 = 3 * (64 * 80 + 20480);    // FR=2 stages
    const int GS4 = 3 * (128 * 80 + 20480);   // FR=4 stages

    cudaFuncSetAttribute(k_expert_mma, cudaFuncAttributeMaxDynamicSharedMemorySize, ESMEM);
    cudaFuncSetAttribute(mlp8<1>,  cudaFuncAttributeMaxDynamicSharedMemorySize, 65536);
    cudaFuncSetAttribute(mlp8<0>,  cudaFuncAttributeMaxDynamicSharedMemorySize, 65536);
    cudaFuncSetAttribute(gemm_mma<K0PAD, 1, 1, 2>, cudaFuncAttributeMaxDynamicSharedMemorySize, GS1);
    cudaFuncSetAttribute(gemm_mma<C1OUT, 1, 1, 4>, cudaFuncAttributeMaxDynamicSharedMemorySize, GS4);
    cudaFuncSetAttribute(gemm_mma<C2OUT, 0, 0, 4>, cudaFuncAttributeMaxDynamicSharedMemorySize, GS4);

    h16 *p_a0h, *p_a1h, *p_a2h;
    h16 *p_w1h, *p_w1l, *p_w2h, *p_w2l, *p_w3h, *p_w3l;
    float *p_lat, *p_d1, *p_d2;
    cudaGetSymbolAddress((void**)&p_a0h, g_a0hi);
    cudaGetSymbolAddress((void**)&p_a1h, g_a1hi);
    cudaGetSymbolAddress((void**)&p_a2h, g_a2hi);
    cudaGetSymbolAddress((void**)&p_w1h, g_w1hi);
    cudaGetSymbolAddress((void**)&p_w1l, g_w1lo);
    cudaGetSymbolAddress((void**)&p_w2h, g_w2hi);
    cudaGetSymbolAddress((void**)&p_w2l, g_w2lo);
    cudaGetSymbolAddress((void**)&p_w3h, g_w3hi);
    cudaGetSymbolAddress((void**)&p_w3l, g_w3lo);
    cudaGetSymbolAddress((void**)&p_lat, g_lat);
    cudaGetSymbolAddress((void**)&p_d1,  g_d1);
    cudaGetSymbolAddress((void**)&p_d2,  g_d2);

    k_prep<<<PREP_NB, 256>>>(x, W1, W2, Wc1, Wc2, Wc3);
    k_build<<<1, 1024>>>(cats);
    k_expert_mma<<<MAXTILES, 256, ESMEM>>>(b1, b2);

    // conv stack: all TERMS=2; gemm1 64-row tiles, gemm2/3 128-row tiles
    gemm_mma<K0PAD, 1, 1, 2><<<dim3(128, C1OUT / 128), 256, GS1>>>(
        p_a0h, p_w1h, p_w1l, bc1, p_a1h, C1OUT);
    gemm_mma<C1OUT, 1, 1, 4><<<dim3(64, C2OUT / 128), 256, GS4>>>(
        p_a1h, p_w2h, p_w2l, bc2, p_a2h, C2OUT);
    gemm_mma<C2OUT, 0, 0, 4><<<dim3(64, C3OUT / 128), 256, GS4>>>(
        p_a2h, p_w3h, p_w3l, bc3, (h16*)0, C3OUT);

    int write_extra = (out_size >= 65536 + 8192) ? 1 : 0;
    k_poolB<<<NPOINTS / 256, 256>>>(out + 65536, write_extra);

    mlp8<1><<<DEC1 / 32, 256, 8 * DEC1 * 4>>>(p_lat, Wd1, bd1, p_d1, DEC1, DEC1);
    mlp8<1><<<DEC2 / 32, 256, 8 * DEC1 * 4>>>(p_d1,  Wd2, bd2, p_d2, DEC1, DEC2);
    mlp8<0><<<DEC3 / 32, 256, 8 * DEC2 * 4>>>(p_d2,  Wd3, bd3, out,  DEC2, DEC3);
}

// round 13
// speedup vs baseline: 1.4241x; 1.1802x over previous
#include <cuda_runtime.h>
#include <cuda_fp16.h>
#include <float.h>
#include <stdint.h>

// ---------------- problem constants ----------------
#define BATCH      8
#define NPTS       1024
#define NPOINTS    (BATCH * NPTS)        // 8192
#define HEADC      8
#define SHAPEC     256
#define XCH        (HEADC + SHAPEC)      // 264
#define NEXPERT    16
#define SC_HID     256
#define SC_OUT     128
#define K0PAD      160                   // 136 padded to 160
#define C1OUT      256
#define C2OUT      512
#define C3OUT      1024
#define DEC1       1024
#define DEC2       2048
#define DEC3       8192
#define ETILE      64
#define MAXTILES   (NPOINTS / ETILE + NEXPERT)   // 144
#define NPART      8                     // pool partials per batch (1024/128)

typedef __half h16;

// ---------------- scratch (device globals; no runtime alloc) ----------------
__device__ __align__(256) h16 g_xhi[NPOINTS * SHAPEC];
__device__ __align__(256) h16 g_a0hi[NPOINTS * K0PAD];
__device__ __align__(256) h16 g_a1hi[NPOINTS * C1OUT];
__device__ __align__(256) h16 g_a2hi[NPOINTS * C2OUT];
__device__ __align__(256) h16 g_w1hi[C1OUT * K0PAD];
__device__ __align__(256) h16 g_w1lo[C1OUT * K0PAD];
__device__ __align__(256) h16 g_w2hi[C2OUT * C1OUT];
__device__ __align__(256) h16 g_w3hi[C3OUT * C2OUT];
__device__ __align__(256) h16 g_e1hi[NEXPERT * SC_HID * SHAPEC];
__device__ __align__(256) h16 g_e1lo[NEXPERT * SC_HID * SHAPEC];
__device__ __align__(256) h16 g_e2hi[NEXPERT * SC_OUT * SC_HID];
__device__ __align__(256) h16 g_e2lo[NEXPERT * SC_OUT * SC_HID];
__device__ float g_part[BATCH * NPART * C3OUT];
__device__ float g_lat[BATCH * C3OUT];
__device__ float g_d1[BATCH * DEC1];
__device__ float g_d2[BATCH * DEC2];
__device__ int   g_idx[NPOINTS];
__device__ int   g_tileExpert[MAXTILES];
__device__ int   g_tileStart[MAXTILES];
__device__ int   g_tileLen[MAXTILES];
__device__ int   g_nTiles;

// ---------------- ptx helpers (sm_80-safe) ----------------
__device__ __forceinline__ uint32_t smem_u32(const void* p) {
    uint32_t a;
    asm("{ .reg .u64 t; cvta.to.shared.u64 t, %1; cvt.u32.u64 %0, t; }" : "=r"(a) : "l"(p));
    return a;
}
#define CP_ASYNC16(dst, src) \
    asm volatile("cp.async.cg.shared.global [%0], [%1], 16;" :: "r"(dst), "l"(src))
#define CP_COMMIT() asm volatile("cp.async.commit_group;" ::: "memory")
#define CP_WAIT0()  asm volatile("cp.async.wait_group 0;" ::: "memory")
#define CP_WAIT1()  asm volatile("cp.async.wait_group 1;" ::: "memory")

#define LDSM4(r, addr) \
    asm volatile("ldmatrix.sync.aligned.m8n8.x4.shared.b16 {%0,%1,%2,%3}, [%4];" \
        : "=r"((r)[0]), "=r"((r)[1]), "=r"((r)[2]), "=r"((r)[3]) : "r"(addr))

__device__ __forceinline__ void mma_f32(float* d, const uint32_t* a,
                                        uint32_t b0, uint32_t b1) {
    asm volatile(
        "mma.sync.aligned.m16n8k16.row.col.f32.f16.f16.f32 "
        "{%0,%1,%2,%3}, {%4,%5,%6,%7}, {%8,%9}, {%0,%1,%2,%3};"
        : "+f"(d[0]), "+f"(d[1]), "+f"(d[2]), "+f"(d[3])
        : "r"(a[0]), "r"(a[1]), "r"(a[2]), "r"(a[3]), "r"(b0), "r"(b1));
}

__device__ __forceinline__ void f16_split(float v, h16& h, h16& l) {
    h = __float2half_rn(v);
    l = __float2half_rn(v - __half2float(h));
}
__device__ __forceinline__ uint32_t pack2h(h16 a, h16 b) {
    __half2 t; t.x = a; t.y = b;
    return *(uint32_t*)&t;
}

// ---------------- 1. fused prep: transpose | tsplit | head | wsplit ---------
#define PREP_T1 2048
#define PREP_T2 3584
#define PREP_T3 4608
#define PREP_NB 7328
#define WS_NB1 160
#define WS_NB2 512

__global__ void __launch_bounds__(256) k_prep(
    const float* __restrict__ x,
    const float* __restrict__ W1, const float* __restrict__ W2,
    const float* __restrict__ Wc1, const float* __restrict__ Wc2,
    const float* __restrict__ Wc3)
{
    __shared__ float t[32][33];
    int bi = blockIdx.x;
    int tid = threadIdx.x;
    int tx = tid & 31, ty = tid >> 5;

    if (bi < PREP_T1) {
        // ---- transpose x shape feats -> g_xhi (hi only) ----
        int idx = bi;
        int cB = (idx & 7) * 32;
        int nB = ((idx >> 3) & 31) * 32;
        int b  = idx >> 8;
        const float* xb = x + (size_t)b * XCH * NPTS;
#pragma unroll
        for (int i = ty; i < 32; i += 8)
            t[i][tx] = xb[(size_t)(HEADC + cB + i) * NPTS + nB + tx];
        __syncthreads();
        size_t base = ((size_t)b * NPTS + nB) * SHAPEC + cB;
#pragma unroll
        for (int i = ty; i < 32; i += 8)
            g_xhi[base + (size_t)i * SHAPEC + tx] = __float2half_rn(t[tx][i]);
    } else if (bi < PREP_T2) {
        // ---- expert weight transpose + hi/lo split ----
        int r = bi - PREP_T1;
        const float* src; h16 *hi, *lo; int K, OUT, e, k0, o0;
        if (r < 1024) {
            e = r >> 6; int q = r & 63;
            k0 = (q & 7) * 32; o0 = (q >> 3) * 32;
            src = W1; hi = g_e1hi; lo = g_e1lo; K = SHAPEC; OUT = SC_HID;
        } else {
            r -= 1024;
            e = r >> 5; int q = r & 31;
            k0 = (q & 7) * 32; o0 = (q >> 3) * 32;
            src = W2; hi = g_e2hi; lo = g_e2lo; K = SC_HID; OUT = SC_OUT;
        }
        const float* s = src + (size_t)e * K * OUT;
#pragma unroll
        for (int i = ty; i < 32; i += 8)
            t[i][tx] = s[(size_t)(k0 + i) * OUT + o0 + tx];
        __syncthreads();
        size_t base = (size_t)e * OUT * K + (size_t)o0 * K + k0;
#pragma unroll
        for (int i = ty; i < 32; i += 8) {
            float v = t[tx][i];
            h16 h, l; f16_split(v, h, l);
            hi[base + (size_t)i * K + tx] = h;
            lo[base + (size_t)i * K + tx] = l;
        }
    } else if (bi < PREP_T3) {
        // ---- head channels + pad -> a0hi only ----
        int i = (bi - PREP_T2) * 256 + tid;
        int p = i >> 5, s = i & 31;
        float v = 0.f;
        int col;
        if (s < 8) {
            int b = p >> 10, n = p & 1023;
            v = x[(size_t)b * XCH * NPTS + (size_t)s * NPTS + n];
            col = s;
        } else {
            col = 128 + s;
        }
        g_a0hi[(size_t)p * K0PAD + col] = __float2half_rn(v);
    } else {
        // ---- conv weight split: Wc1 hi+lo; Wc2/Wc3 hi only ----
        int r = bi - PREP_T3;
        const float* w; h16 *hi, *lo; int Kin, Kpad, total, i;
        if (r < WS_NB1) {
            w = Wc1; hi = g_w1hi; lo = g_w1lo; Kin = 136; Kpad = K0PAD;
            total = C1OUT * K0PAD; i = r * 256 + tid;
        } else if (r < WS_NB1 + WS_NB2) {
            w = Wc2; hi = g_w2hi; lo = 0; Kin = C1OUT; Kpad = C1OUT;
            total = C2OUT * C1OUT; i = (r - WS_NB1) * 256 + tid;
        } else {
            w = Wc3; hi = g_w3hi; lo = 0; Kin = C2OUT; Kpad = C2OUT;
            total = C3OUT * C2OUT; i = (r - WS_NB1 - WS_NB2) * 256 + tid;
        }
        if (i >= total) return;
        int c = i / Kpad, k = i - c * Kpad;
        float v = (k < Kin) ? w[(size_t)c * Kin + k] : 0.f;
        if (lo) {
            h16 h, l; f16_split(v, h, l);
            hi[i] = h;
            lo[i] = l;
        } else {
            hi[i] = __float2half_rn(v);
        }
    }
}

// ---------------- 2. counting sort points by category (tiles of 64) ---------
__global__ void k_build(const int* __restrict__ cats) {
    __shared__ int cnt[NEXPERT];
    __shared__ int off[NEXPERT + 1];
    __shared__ int cur[NEXPERT];
    int tid = threadIdx.x;
    if (tid < NEXPERT) cnt[tid] = 0;
    __syncthreads();
    for (int i = tid; i < NPOINTS; i += blockDim.x) atomicAdd(&cnt[cats[i]], 1);
    __syncthreads();
    if (tid == 0) {
        int s = 0;
        for (int e = 0; e < NEXPERT; e++) { off[e] = s; s += cnt[e]; }
        off[NEXPERT] = s;
        int t = 0;
        for (int e = 0; e < NEXPERT; e++)
            for (int st = off[e]; st < off[e + 1]; st += ETILE) {
                g_tileExpert[t] = e;
                g_tileStart[t]  = st;
                g_tileLen[t]    = min(ETILE, off[e + 1] - st);
                t++;
            }
        g_nTiles = t;
    }
    __syncthreads();
    if (tid < NEXPERT) cur[tid] = off[tid];
    __syncthreads();
    for (int i = tid; i < NPOINTS; i += blockDim.x) {
        int pos = atomicAdd(&cur[cats[i]], 1);
        g_idx[pos] = i;
    }
}

// ---------------- 3. fused expert MLP (TERMS=2, hi-only activations) --------
// smem: A 2x5120 @0; B 2x40960 @10240; H 40960 @92160 -> 133120 B
#define ESM_A  0
#define ESM_B  10240
#define ESM_H  92160
#define ESMEM  133120

__global__ void __launch_bounds__(256) k_expert_mma(
    const float* __restrict__ b1g, const float* __restrict__ b2g)
{
    int t = blockIdx.x;
    if (t >= g_nTiles) return;
    int e = g_tileExpert[t], start = g_tileStart[t], len = g_tileLen[t];

    extern __shared__ char smraw[];
    __shared__ int pidx[ETILE];
    __shared__ int gidx[ETILE];

    int tid = threadIdx.x, lane = tid & 31, wid = tid >> 5;
    uint32_t sb = smem_u32(smraw);

    if (tid < ETILE) {
        int pi = (tid < len) ? g_idx[start + tid] : -1;
        pidx[tid] = pi;
        gidx[tid] = pi < 0 ? 0 : pi;
    }
    __syncthreads();

    const h16* w1h = g_e1hi + (size_t)e * SC_HID * SHAPEC;
    const h16* w1l = g_e1lo + (size_t)e * SC_HID * SHAPEC;
    const h16* w2h = g_e2hi + (size_t)e * SC_OUT * SC_HID;
    const h16* w2l = g_e2lo + (size_t)e * SC_OUT * SC_HID;

    auto loadS1 = [&](int ks, int st) {
        {
            int row = tid >> 2, ch = tid & 3;
            const h16* src = g_xhi + (size_t)gidx[row] * SHAPEC + ks * 32 + ch * 8;
            CP_ASYNC16(sb + ESM_A + st * 5120 + (uint32_t)row * 80 + ch * 16, src);
        }
#pragma unroll
        for (int r = 0; r < 8; r++) {
            int id = tid + r * 256;
            int half = id >> 10, idx = id & 1023;
            int row = idx >> 2, ch = idx & 3;
            const h16* src = (half ? w1l : w1h)
                           + (size_t)row * SHAPEC + ks * 32 + ch * 8;
            CP_ASYNC16(sb + ESM_B + st * 40960 + half * 20480 + (uint32_t)row * 80 + ch * 16, src);
        }
        CP_COMMIT();
    };
    auto loadS2 = [&](int ks, int st) {
#pragma unroll
        for (int r = 0; r < 4; r++) {
            int id = tid + r * 256;
            int half = id >> 9, idx = id & 511;
            int row = idx >> 2, ch = idx & 3;
            const h16* src = (half ? w2l : w2h)
                           + (size_t)row * SC_HID + ks * 32 + ch * 8;
            CP_ASYNC16(sb + ESM_B + st * 20480 + half * 10240 + (uint32_t)row * 80 + ch * 16, src);
        }
        CP_COMMIT();
    };

    // ======== stage 1: h[64,256] = relu(A @ W1T + b1), TERMS=2 ====
    {
        float acc[4][4][4];
#pragma unroll
        for (int a = 0; a < 4; a++)
#pragma unroll
            for (int b = 0; b < 4; b++)
#pragma unroll
                for (int c = 0; c < 4; c++) acc[a][b][c] = 0.f;

        uint32_t rowA = (uint32_t)(lane & 15) * 80 + (lane >> 4) * 16;
        uint32_t rowB = (uint32_t)(wid * 32 + (lane & 15)) * 80 + (lane >> 4) * 16;

        loadS1(0, 0);
        for (int ks = 0; ks < 8; ks++) {
            CP_WAIT0();
            __syncthreads();
            if (ks + 1 < 8) loadS1(ks + 1, (ks + 1) & 1);
            uint32_t sba = sb + ESM_A + (ks & 1) * 5120;
            uint32_t sbb = sb + ESM_B + (ks & 1) * 40960;
#pragma unroll
            for (int s = 0; s < 2; s++) {
                uint32_t aH[4][4], b2r[2][2][4];
#pragma unroll
                for (int mf = 0; mf < 4; mf++) {
                    uint32_t ad = sba + rowA + (uint32_t)mf * (16 * 80) + s * 32;
                    LDSM4(aH[mf], ad);
                }
#pragma unroll
                for (int p = 0; p < 2; p++) {
                    uint32_t bd = sbb + rowB + (uint32_t)p * (16 * 80) + s * 32;
                    LDSM4(b2r[0][p], bd);
                    LDSM4(b2r[1][p], bd + 20480);
                }
#pragma unroll
                for (int tt = 0; tt < 2; tt++)
#pragma unroll
                    for (int mf = 0; mf < 4; mf++)
#pragma unroll
                        for (int nf = 0; nf < 4; nf++) {
                            int p = nf >> 1, sel = nf & 1;
                            mma_f32(acc[mf][nf], aH[mf],
                                    b2r[tt][p][sel], b2r[tt][p][sel + 2]);
                        }
            }
            __syncthreads();
        }

        loadS2(0, 0);

        const float* b1 = b1g + e * SC_HID;
#pragma unroll
        for (int mf = 0; mf < 4; mf++) {
            int row = mf * 16 + (lane >> 2);
#pragma unroll
            for (int nf = 0; nf < 4; nf++) {
                int col = wid * 32 + nf * 8 + 2 * (lane & 3);
                float b0v = b1[col], b1v = b1[col + 1];
                float v0 = fmaxf(acc[mf][nf][0] + b0v, 0.f);
                float v1 = fmaxf(acc[mf][nf][1] + b1v, 0.f);
                float v2 = fmaxf(acc[mf][nf][2] + b0v, 0.f);
                float v3 = fmaxf(acc[mf][nf][3] + b1v, 0.f);
                int ks = col >> 5, cw = col & 31;
                uint32_t off = (uint32_t)ks * 5120 + (uint32_t)row * 80 + cw * 2;
                *(uint32_t*)(smraw + ESM_H + off)
                    = pack2h(__float2half_rn(v0), __float2half_rn(v1));
                *(uint32_t*)(smraw + ESM_H + off + 8 * 80)
                    = pack2h(__float2half_rn(v2), __float2half_rn(v3));
            }
        }
    }
    __syncthreads();

    // ======== stage 2: o[64,128] = h @ W2T + b2, TERMS=2 ====
    {
        int warp_m = wid & 1, warp_n = wid >> 1;
        float acc[2][4][4];
#pragma unroll
        for (int a = 0; a < 2; a++)
#pragma unroll
            for (int b = 0; b < 4; b++)
#pragma unroll
                for (int c = 0; c < 4; c++) acc[a][b][c] = 0.f;

        uint32_t rowA = (uint32_t)(warp_m * 32 + (lane & 15)) * 80 + (lane >> 4) * 16;
        uint32_t rowB = (uint32_t)(warp_n * 32 + (lane & 15)) * 80 + (lane >> 4) * 16;

        for (int ks = 0; ks < 8; ks++) {
            CP_WAIT0();
            __syncthreads();
            if (ks + 1 < 8) loadS2(ks + 1, (ks + 1) & 1);
            uint32_t hbase = sb + ESM_H + (uint32_t)ks * 5120;
            uint32_t sbb = sb + ESM_B + (ks & 1) * 20480;
#pragma unroll
            for (int s = 0; s < 2; s++) {
                uint32_t aH[2][4], b2r[2][2][4];
#pragma unroll
                for (int mf = 0; mf < 2; mf++) {
                    uint32_t ad = hbase + rowA + (uint32_t)mf * (16 * 80) + s * 32;
                    LDSM4(aH[mf], ad);
                }
#pragma unroll
                for (int p = 0; p < 2; p++) {
                    uint32_t bd = sbb + rowB + (uint32_t)p * (16 * 80) + s * 32;
                    LDSM4(b2r[0][p], bd);
                    LDSM4(b2r[1][p], bd + 10240);
                }
#pragma unroll
                for (int tt = 0; tt < 2; tt++)
#pragma unroll
                    for (int mf = 0; mf < 2; mf++)
#pragma unroll
                        for (int nf = 0; nf < 4; nf++) {
                            int p = nf >> 1, sel = nf & 1;
                            mma_f32(acc[mf][nf], aH[mf],
                                    b2r[tt][p][sel], b2r[tt][p][sel + 2]);
                        }
            }
            __syncthreads();
        }

        const float* b2 = b2g + e * SC_OUT;
#pragma unroll
        for (int mf = 0; mf < 2; mf++) {
            int row = warp_m * 32 + mf * 16 + (lane >> 2);
#pragma unroll
            for (int nf = 0; nf < 4; nf++) {
                int col = warp_n * 32 + nf * 8 + 2 * (lane & 3);
                float b0v = b2[col], b1v = b2[col + 1];
                float v0 = acc[mf][nf][0] + b0v, v1 = acc[mf][nf][1] + b1v;
                float v2 = acc[mf][nf][2] + b0v, v3 = acc[mf][nf][3] + b1v;
                int pi0 = pidx[row], pi1 = pidx[row + 8];
                if (pi0 >= 0)
                    *(uint32_t*)(g_a0hi + (size_t)pi0 * K0PAD + HEADC + col)
                        = pack2h(__float2half_rn(v0), __float2half_rn(v1));
                if (pi1 >= 0)
                    *(uint32_t*)(g_a0hi + (size_t)pi1 * K0PAD + HEADC + col)
                        = pack2h(__float2half_rn(v2), __float2half_rn(v3));
            }
        }
    }
}

// ---------------- 4. f16 mma GEMM: A-hi only, TERMS in {1,2}, FR*32 rows ----
// stage: A-hi [MTILE*80] | B-hi [10240] | B-lo [10240 if TERMS==2]
template <int KTOT, int RELU, int SPLIT, int FR, int TERMS>
__global__ void __launch_bounds__(256, 2) gemm_mma(
    const h16* __restrict__ aHi,
    const h16* __restrict__ wHi, const h16* __restrict__ wLo,
    const float* __restrict__ bias,
    h16* __restrict__ oHi, int KOUT)
{
    extern __shared__ char smraw[];
    const int NK = KTOT / 32;
    const int MTILE = FR * 32;
    const int ASZ = MTILE * 80;
    const int STG = ASZ + TERMS * 10240;
    int tid = threadIdx.x, lane = tid & 31, wid = tid >> 5;
    int warp_m = wid & 1, warp_n = wid >> 1;     // 2 x 4 warps
    int m0 = blockIdx.x * MTILE, c0 = blockIdx.y * 128;

    uint32_t smBase = smem_u32(smraw);
    uint32_t rowA = (uint32_t)(warp_m * (FR * 16) + (lane & 15)) * 80 + (lane >> 4) * 16;
    uint32_t rowB = (uint32_t)(warp_n * 32 + (lane & 15)) * 80 + (lane >> 4) * 16;

    float acc[FR][4][4];
#pragma unroll
    for (int a = 0; a < FR; a++)
#pragma unroll
        for (int b = 0; b < 4; b++)
#pragma unroll
            for (int c = 0; c < 4; c++) acc[a][b][c] = 0.f;

    auto loadStage = [&](int ks, int st) {
        uint32_t sbs = smBase + st * STG;
        // A-hi: MTILE*4 chunks
#pragma unroll
        for (int i = 0; i < MTILE * 4; i += 256) {
            int c = tid + i;
            int row = c >> 2, ch = c & 3;
            const h16* src = aHi + (size_t)(m0 + row) * KTOT + ks * 32 + ch * 8;
            CP_ASYNC16(sbs + (uint32_t)row * 80 + ch * 16, src);
        }
        // B: 512*TERMS chunks
#pragma unroll
        for (int i = 0; i < 2 * TERMS; i++) {
            int c = tid + i * 256;
            int half = c >> 9, idx = c & 511;
            int row = idx >> 2, ch = idx & 3;
            const h16* src = (half ? wLo : wHi) + (size_t)(c0 + row) * KTOT + ks * 32 + ch * 8;
            CP_ASYNC16(sbs + ASZ + half * 10240 + (uint32_t)row * 80 + ch * 16, src);
        }
        CP_COMMIT();
    };

    loadStage(0, 0);
    if (NK > 1) loadStage(1, 1);
    for (int ks = 0; ks < NK; ks++) {
        if (ks < NK - 1) CP_WAIT1(); else CP_WAIT0();
        __syncthreads();
        if (ks + 2 < NK) loadStage(ks + 2, (ks + 2) % 3);

        uint32_t sbs = smBase + (ks % 3) * STG;
#pragma unroll
        for (int s = 0; s < 2; s++) {
            uint32_t aH[FR][4], b2r[2][2][4];
#pragma unroll
            for (int mf = 0; mf < FR; mf++) {
                uint32_t ad = sbs + rowA + (uint32_t)mf * (16 * 80) + s * 32;
                LDSM4(aH[mf], ad);
            }
#pragma unroll
            for (int p = 0; p < 2; p++) {
                uint32_t bd = sbs + ASZ + rowB + (uint32_t)p * (16 * 80) + s * 32;
                LDSM4(b2r[0][p], bd);
                if (TERMS == 2) LDSM4(b2r[1][p], bd + 10240);
            }
#pragma unroll
            for (int tt = 0; tt < TERMS; tt++)
#pragma unroll
                for (int mf = 0; mf < FR; mf++)
#pragma unroll
                    for (int nf = 0; nf < 4; nf++) {
                        int p = nf >> 1, sel = nf & 1;
                        mma_f32(acc[mf][nf], aH[mf],
                                b2r[tt][p][sel], b2r[tt][p][sel + 2]);
                    }
        }
    }

    if (SPLIT) {
        // ---- epilogue: +bias, relu, hi-only f16 store ----
#pragma unroll
        for (int mf = 0; mf < FR; mf++) {
            int row = m0 + warp_m * (FR * 16) + mf * 16 + (lane >> 2);
#pragma unroll
            for (int nf = 0; nf < 4; nf++) {
                int col = c0 + warp_n * 32 + nf * 8 + 2 * (lane & 3);
                float b0v = bias[col], b1v = bias[col + 1];
                float v0 = acc[mf][nf][0] + b0v, v1 = acc[mf][nf][1] + b1v;
                float v2 = acc[mf][nf][2] + b0v, v3 = acc[mf][nf][3] + b1v;
                if (RELU) {
                    v0 = fmaxf(v0, 0.f); v1 = fmaxf(v1, 0.f);
                    v2 = fmaxf(v2, 0.f); v3 = fmaxf(v3, 0.f);
                }
                *(uint32_t*)(oHi + (size_t)row * KOUT + col)
                    = pack2h(__float2half_rn(v0), __float2half_rn(v1));
                *(uint32_t*)(oHi + (size_t)(row + 8) * KOUT + col)
                    = pack2h(__float2half_rn(v2), __float2half_rn(v3));
            }
        }
    } else {
        // ---- fused max-pool epilogue: partial max over MTILE rows ----
        __syncthreads();
        float* pm = (float*)smraw;               // [2][128]
#pragma unroll
        for (int nf = 0; nf < 4; nf++) {
            float c0m = -FLT_MAX, c1m = -FLT_MAX;
#pragma unroll
            for (int mf = 0; mf < FR; mf++) {
                int col = c0 + warp_n * 32 + nf * 8 + 2 * (lane & 3);
                float b0v = bias[col], b1v = bias[col + 1];
                c0m = fmaxf(c0m, fmaxf(acc[mf][nf][0] + b0v, acc[mf][nf][2] + b0v));
                c1m = fmaxf(c1m, fmaxf(acc[mf][nf][1] + b1v, acc[mf][nf][3] + b1v));
            }
#pragma unroll
            for (int o = 4; o < 32; o <<= 1) {
                c0m = fmaxf(c0m, __shfl_xor_sync(0xFFFFFFFFu, c0m, o));
                c1m = fmaxf(c1m, __shfl_xor_sync(0xFFFFFFFFu, c1m, o));
            }
            if (lane < 4) {
                int cc = warp_n * 32 + nf * 8 + 2 * lane;
                pm[warp_m * 128 + cc]     = c0m;
                pm[warp_m * 128 + cc + 1] = c1m;
            }
        }
        __syncthreads();
        if (tid < 64) {
            int cc = tid * 2;
            float m0v = fmaxf(pm[cc],     pm[128 + cc]);
            float m1v = fmaxf(pm[cc + 1], pm[128 + cc + 1]);
            int b = m0 >> 10, part = (m0 >> 7) & (NPART - 1);
            *(float2*)(g_part + (size_t)(b * NPART + part) * C3OUT + c0 + cc)
                = make_float2(m0v, m1v);
        }
    }
}

// ---------------- 5. max pool final stage ----------------
__global__ void k_poolB(float* __restrict__ extra, int we) {
    int i = blockIdx.x * 256 + threadIdx.x;   // 8192
    float m = -FLT_MAX;
    int b = i >> 10, c = i & 1023;
#pragma unroll
    for (int part = 0; part < NPART; part++)
        m = fmaxf(m, g_part[(b * NPART + part) * C3OUT + c]);
    g_lat[i] = m;
    if (we) extra[i] = m;
}

// ---------------- 6. decoder MLP (32 cols x 8 K-slices per block) -----------
template <int RELU>
__global__ void __launch_bounds__(256) mlp8(
    const float* __restrict__ A, const float* __restrict__ W,
    const float* __restrict__ bias, float* __restrict__ Out,
    int K, int N)
{
    extern __shared__ float Ash[];
    __shared__ float red[256 * 8];
    int tid = threadIdx.x;
    for (int i = tid; i < 8 * K / 4; i += 256)
        ((float4*)Ash)[i] = ((const float4*)A)[i];
    __syncthreads();

    int col   = blockIdx.x * 32 + (tid & 31);
    int slice = tid >> 5;
    int kPer  = K >> 3;
    int k0    = slice * kPer;

    float acc[8];
#pragma unroll
    for (int bb = 0; bb < 8; bb++) acc[bb] = 0.f;

    for (int k = k0; k < k0 + kPer; k += 4) {
        float w0 = W[(size_t)(k + 0) * N + col];
        float w1 = W[(size_t)(k + 1) * N + col];
        float w2 = W[(size_t)(k + 2) * N + col];
        float w3 = W[(size_t)(k + 3) * N + col];
#pragma unroll
        for (int bb = 0; bb < 8; bb++) {
            float4 a4 = ((const float4*)(Ash + bb * K))[k >> 2];
            acc[bb] = fmaf(a4.x, w0, acc[bb]);
            acc[bb] = fmaf(a4.y, w1, acc[bb]);
            acc[bb] = fmaf(a4.z, w2, acc[bb]);
            acc[bb] = fmaf(a4.w, w3, acc[bb]);
        }
    }
#pragma unroll
    for (int bb = 0; bb < 8; bb++) red[tid * 8 + bb] = acc[bb];
    __syncthreads();
    if (tid < 32) {
        float bsv = bias[col];
#pragma unroll
        for (int bb = 0; bb < 8; bb++) {
            float v = bsv;
#pragma unroll
            for (int s = 0; s < 8; s++)
                v += red[(tid + s * 32) * 8 + bb];
            if (RELU) v = fmaxf(v, 0.f);
            Out[(size_t)bb * N + col] = v;
        }
    }
}

// ---------------- launch ----------------
extern "C" void kernel_launch(void* const* d_in, const int* in_sizes, int n_in,
                              void* d_out, int out_size) {
    const float* x    = (const float*)d_in[0];
    const int*   cats = (const int*)  d_in[1];
    const float* W1   = (const float*)d_in[2];
    const float* b1   = (const float*)d_in[3];
    const float* W2   = (const float*)d_in[4];
    const float* b2   = (const float*)d_in[5];
    const float* Wc1  = (const float*)d_in[6];
    const float* bc1  = (const float*)d_in[7];
    const float* Wc2  = (const float*)d_in[8];
    const float* bc2  = (const float*)d_in[9];
    const float* Wc3  = (const float*)d_in[10];
    const float* bc3  = (const float*)d_in[11];
    const float* Wd1  = (const float*)d_in[12];
    const float* bd1  = (const float*)d_in[13];
    const float* Wd2  = (const float*)d_in[14];
    const float* bd2  = (const float*)d_in[15];
    const float* Wd3  = (const float*)d_in[16];
    const float* bd3  = (const float*)d_in[17];
    float* out = (float*)d_out;

    const int GS1 = 3 * (64 * 80 + 2 * 10240);   // FR=2, TERMS=2
    const int GS4 = 3 * (128 * 80 + 10240);      // FR=4, TERMS=1

    cudaFuncSetAttribute(k_expert_mma, cudaFuncAttributeMaxDynamicSharedMemorySize, ESMEM);
    cudaFuncSetAttribute(mlp8<1>,  cudaFuncAttributeMaxDynamicSharedMemorySize, 65536);
    cudaFuncSetAttribute(mlp8<0>,  cudaFuncAttributeMaxDynamicSharedMemorySize, 65536);
    cudaFuncSetAttribute(gemm_mma<K0PAD, 1, 1, 2, 2>, cudaFuncAttributeMaxDynamicSharedMemorySize, GS1);
    cudaFuncSetAttribute(gemm_mma<C1OUT, 1, 1, 4, 1>, cudaFuncAttributeMaxDynamicSharedMemorySize, GS4);
    cudaFuncSetAttribute(gemm_mma<C2OUT, 0, 0, 4, 1>, cudaFuncAttributeMaxDynamicSharedMemorySize, GS4);

    h16 *p_a0h, *p_a1h, *p_a2h;
    h16 *p_w1h, *p_w1l, *p_w2h, *p_w3h;
    float *p_lat, *p_d1, *p_d2;
    cudaGetSymbolAddress((void**)&p_a0h, g_a0hi);
    cudaGetSymbolAddress((void**)&p_a1h, g_a1hi);
    cudaGetSymbolAddress((void**)&p_a2h, g_a2hi);
    cudaGetSymbolAddress((void**)&p_w1h, g_w1hi);
    cudaGetSymbolAddress((void**)&p_w1l, g_w1lo);
    cudaGetSymbolAddress((void**)&p_w2h, g_w2hi);
    cudaGetSymbolAddress((void**)&p_w3h, g_w3hi);
    cudaGetSymbolAddress((void**)&p_lat, g_lat);
    cudaGetSymbolAddress((void**)&p_d1,  g_d1);
    cudaGetSymbolAddress((void**)&p_d2,  g_d2);

    k_prep<<<PREP_NB, 256>>>(x, W1, W2, Wc1, Wc2, Wc3);
    k_build<<<1, 1024>>>(cats);
    k_expert_mma<<<MAXTILES, 256, ESMEM>>>(b1, b2);

    // conv stack: gemm1 TERMS=2 FR=2; gemm2/3 TERMS=1 FR=4
    gemm_mma<K0PAD, 1, 1, 2, 2><<<dim3(128, C1OUT / 128), 256, GS1>>>(
        p_a0h, p_w1h, p_w1l, bc1, p_a1h, C1OUT);
    gemm_mma<C1OUT, 1, 1, 4, 1><<<dim3(64, C2OUT / 128), 256, GS4>>>(
        p_a1h, p_w2h, (h16*)0, bc2, p_a2h, C2OUT);
    gemm_mma<C2OUT, 0, 0, 4, 1><<<dim3(64, C3OUT / 128), 256, GS4>>>(
        p_a2h, p_w3h, (h16*)0, bc3, (h16*)0, C3OUT);

    int write_extra = (out_size >= 65536 + 8192) ? 1 : 0;
    k_poolB<<<NPOINTS / 256, 256>>>(out + 65536, write_extra);

    mlp8<1><<<DEC1 / 32, 256, 8 * DEC1 * 4>>>(p_lat, Wd1, bd1, p_d1, DEC1, DEC1);
    mlp8<1><<<DEC2 / 32, 256, 8 * DEC1 * 4>>>(p_d1,  Wd2, bd2, p_d2, DEC1, DEC2);
    mlp8<0><<<DEC3 / 32, 256, 8 * DEC2 * 4>>>(p_d2,  Wd3, bd3, out,  DEC2, DEC3);
}

// round 14
// speedup vs baseline: 1.8353x; 1.2887x over previous
#include <cuda_runtime.h>
#include <cuda_fp16.h>
#include <float.h>
#include <stdint.h>

// ---------------- problem constants ----------------
#define BATCH      8
#define NPTS       1024
#define NPOINTS    (BATCH * NPTS)        // 8192
#define HEADC      8
#define SHAPEC     256
#define XCH        (HEADC + SHAPEC)      // 264
#define NEXPERT    16
#define SC_HID     256
#define SC_OUT     128
#define K0PAD      160                   // 136 padded to 160
#define C1OUT      256
#define C2OUT      512
#define C3OUT      1024
#define DEC1       1024
#define DEC2       2048
#define DEC3       8192
#define ETILE      64
#define MAXTILES   (NPOINTS / ETILE + NEXPERT)   // 144
#define NPART      8                     // pool partials per batch (1024/128)

typedef __half h16;

// ---------------- scratch (device globals; no runtime alloc) ----------------
__device__ __align__(256) h16 g_xhi[NPOINTS * SHAPEC];
__device__ __align__(256) h16 g_a0hi[NPOINTS * K0PAD];
__device__ __align__(256) h16 g_a1hi[NPOINTS * C1OUT];
__device__ __align__(256) h16 g_a2hi[NPOINTS * C2OUT];
__device__ __align__(256) h16 g_w1hi[C1OUT * K0PAD];
__device__ __align__(256) h16 g_w2hi[C2OUT * C1OUT];
__device__ __align__(256) h16 g_w3hi[C3OUT * C2OUT];
__device__ __align__(256) h16 g_e1hi[NEXPERT * SC_HID * SHAPEC];
__device__ __align__(256) h16 g_e2hi[NEXPERT * SC_OUT * SC_HID];
__device__ float g_part[BATCH * NPART * C3OUT];
__device__ float g_lat[BATCH * C3OUT];
__device__ float g_d1[BATCH * DEC1];
__device__ float g_d2[BATCH * DEC2];
__device__ int   g_idx[NPOINTS];
__device__ int   g_tileExpert[MAXTILES];
__device__ int   g_tileStart[MAXTILES];
__device__ int   g_tileLen[MAXTILES];
__device__ int   g_nTiles;

// ---------------- ptx helpers (sm_80-safe) ----------------
__device__ __forceinline__ uint32_t smem_u32(const void* p) {
    uint32_t a;
    asm("{ .reg .u64 t; cvta.to.shared.u64 t, %1; cvt.u32.u64 %0, t; }" : "=r"(a) : "l"(p));
    return a;
}
#define CP_ASYNC16(dst, src) \
    asm volatile("cp.async.cg.shared.global [%0], [%1], 16;" :: "r"(dst), "l"(src))
#define CP_COMMIT() asm volatile("cp.async.commit_group;" ::: "memory")
#define CP_WAIT0()  asm volatile("cp.async.wait_group 0;" ::: "memory")
#define CP_WAIT1()  asm volatile("cp.async.wait_group 1;" ::: "memory")

#define LDSM4(r, addr) \
    asm volatile("ldmatrix.sync.aligned.m8n8.x4.shared.b16 {%0,%1,%2,%3}, [%4];" \
        : "=r"((r)[0]), "=r"((r)[1]), "=r"((r)[2]), "=r"((r)[3]) : "r"(addr))

__device__ __forceinline__ void mma_f32(float* d, const uint32_t* a,
                                        uint32_t b0, uint32_t b1) {
    asm volatile(
        "mma.sync.aligned.m16n8k16.row.col.f32.f16.f16.f32 "
        "{%0,%1,%2,%3}, {%4,%5,%6,%7}, {%8,%9}, {%0,%1,%2,%3};"
        : "+f"(d[0]), "+f"(d[1]), "+f"(d[2]), "+f"(d[3])
        : "r"(a[0]), "r"(a[1]), "r"(a[2]), "r"(a[3]), "r"(b0), "r"(b1));
}

__device__ __forceinline__ uint32_t pack2h(h16 a, h16 b) {
    __half2 t; t.x = a; t.y = b;
    return *(uint32_t*)&t;
}

// ---------------- 1. fused prep: transpose | tsplit | head | wsplit ---------
#define PREP_T1 2048
#define PREP_T2 3584
#define PREP_T3 4608
#define PREP_NB 7328
#define WS_NB1 160
#define WS_NB2 512

__global__ void __launch_bounds__(256) k_prep(
    const float* __restrict__ x,
    const float* __restrict__ W1, const float* __restrict__ W2,
    const float* __restrict__ Wc1, const float* __restrict__ Wc2,
    const float* __restrict__ Wc3)
{
    __shared__ float t[32][33];
    int bi = blockIdx.x;
    int tid = threadIdx.x;
    int tx = tid & 31, ty = tid >> 5;

    if (bi < PREP_T1) {
        // ---- transpose x shape feats -> g_xhi ----
        int idx = bi;
        int cB = (idx & 7) * 32;
        int nB = ((idx >> 3) & 31) * 32;
        int b  = idx >> 8;
        const float* xb = x + (size_t)b * XCH * NPTS;
#pragma unroll
        for (int i = ty; i < 32; i += 8)
            t[i][tx] = xb[(size_t)(HEADC + cB + i) * NPTS + nB + tx];
        __syncthreads();
        size_t base = ((size_t)b * NPTS + nB) * SHAPEC + cB;
#pragma unroll
        for (int i = ty; i < 32; i += 8)
            g_xhi[base + (size_t)i * SHAPEC + tx] = __float2half_rn(t[tx][i]);
    } else if (bi < PREP_T2) {
        // ---- expert weight transpose (hi only) ----
        int r = bi - PREP_T1;
        const float* src; h16 *hi; int K, OUT, e, k0, o0;
        if (r < 1024) {
            e = r >> 6; int q = r & 63;
            k0 = (q & 7) * 32; o0 = (q >> 3) * 32;
            src = W1; hi = g_e1hi; K = SHAPEC; OUT = SC_HID;
        } else {
            r -= 1024;
            e = r >> 5; int q = r & 31;
            k0 = (q & 7) * 32; o0 = (q >> 3) * 32;
            src = W2; hi = g_e2hi; K = SC_HID; OUT = SC_OUT;
        }
        const float* s = src + (size_t)e * K * OUT;
#pragma unroll
        for (int i = ty; i < 32; i += 8)
            t[i][tx] = s[(size_t)(k0 + i) * OUT + o0 + tx];
        __syncthreads();
        size_t base = (size_t)e * OUT * K + (size_t)o0 * K + k0;
#pragma unroll
        for (int i = ty; i < 32; i += 8)
            hi[base + (size_t)i * K + tx] = __float2half_rn(t[tx][i]);
    } else if (bi < PREP_T3) {
        // ---- head channels + pad -> a0hi ----
        int i = (bi - PREP_T2) * 256 + tid;
        int p = i >> 5, s = i & 31;
        float v = 0.f;
        int col;
        if (s < 8) {
            int b = p >> 10, n = p & 1023;
            v = x[(size_t)b * XCH * NPTS + (size_t)s * NPTS + n];
            col = s;
        } else {
            col = 128 + s;
        }
        g_a0hi[(size_t)p * K0PAD + col] = __float2half_rn(v);
    } else {
        // ---- conv weight convert (hi only) ----
        int r = bi - PREP_T3;
        const float* w; h16* hi; int Kin, Kpad, total, i;
        if (r < WS_NB1) {
            w = Wc1; hi = g_w1hi; Kin = 136; Kpad = K0PAD;
            total = C1OUT * K0PAD; i = r * 256 + tid;
        } else if (r < WS_NB1 + WS_NB2) {
            w = Wc2; hi = g_w2hi; Kin = C1OUT; Kpad = C1OUT;
            total = C2OUT * C1OUT; i = (r - WS_NB1) * 256 + tid;
        } else {
            w = Wc3; hi = g_w3hi; Kin = C2OUT; Kpad = C2OUT;
            total = C3OUT * C2OUT; i = (r - WS_NB1 - WS_NB2) * 256 + tid;
        }
        if (i >= total) return;
        int c = i / Kpad, k = i - c * Kpad;
        float v = (k < Kin) ? w[(size_t)c * Kin + k] : 0.f;
        hi[i] = __float2half_rn(v);
    }
}

// ---------------- 2. counting sort points by category (tiles of 64) ---------
__global__ void k_build(const int* __restrict__ cats) {
    __shared__ int cnt[NEXPERT];
    __shared__ int off[NEXPERT + 1];
    __shared__ int cur[NEXPERT];
    int tid = threadIdx.x;
    if (tid < NEXPERT) cnt[tid] = 0;
    __syncthreads();
    for (int i = tid; i < NPOINTS; i += blockDim.x) atomicAdd(&cnt[cats[i]], 1);
    __syncthreads();
    if (tid == 0) {
        int s = 0;
        for (int e = 0; e < NEXPERT; e++) { off[e] = s; s += cnt[e]; }
        off[NEXPERT] = s;
        int t = 0;
        for (int e = 0; e < NEXPERT; e++)
            for (int st = off[e]; st < off[e + 1]; st += ETILE) {
                g_tileExpert[t] = e;
                g_tileStart[t]  = st;
                g_tileLen[t]    = min(ETILE, off[e + 1] - st);
                t++;
            }
        g_nTiles = t;
    }
    __syncthreads();
    if (tid < NEXPERT) cur[tid] = off[tid];
    __syncthreads();
    for (int i = tid; i < NPOINTS; i += blockDim.x) {
        int pos = atomicAdd(&cur[cats[i]], 1);
        g_idx[pos] = i;
    }
}

// ---------------- 3. fused expert MLP (TERMS=1, hi-only) ----------------
// smem: A 2x5120 @0; B 2x20480 @10240; H 40960 @51200 -> 92160 B
#define ESM_A  0
#define ESM_B  10240
#define ESM_H  51200
#define ESMEM  92160

__global__ void __launch_bounds__(256) k_expert_mma(
    const float* __restrict__ b1g, const float* __restrict__ b2g)
{
    int t = blockIdx.x;
    if (t >= g_nTiles) return;
    int e = g_tileExpert[t], start = g_tileStart[t], len = g_tileLen[t];

    extern __shared__ char smraw[];
    __shared__ int pidx[ETILE];
    __shared__ int gidx[ETILE];

    int tid = threadIdx.x, lane = tid & 31, wid = tid >> 5;
    uint32_t sb = smem_u32(smraw);

    if (tid < ETILE) {
        int pi = (tid < len) ? g_idx[start + tid] : -1;
        pidx[tid] = pi;
        gidx[tid] = pi < 0 ? 0 : pi;
    }
    __syncthreads();

    const h16* w1h = g_e1hi + (size_t)e * SC_HID * SHAPEC;
    const h16* w2h = g_e2hi + (size_t)e * SC_OUT * SC_HID;

    auto loadS1 = [&](int ks, int st) {
        {
            int row = tid >> 2, ch = tid & 3;
            const h16* src = g_xhi + (size_t)gidx[row] * SHAPEC + ks * 32 + ch * 8;
            CP_ASYNC16(sb + ESM_A + st * 5120 + (uint32_t)row * 80 + ch * 16, src);
        }
#pragma unroll
        for (int r = 0; r < 4; r++) {
            int id = tid + r * 256;               // 0..1023: 256 rows x 4
            int row = id >> 2, ch = id & 3;
            const h16* src = w1h + (size_t)row * SHAPEC + ks * 32 + ch * 8;
            CP_ASYNC16(sb + ESM_B + st * 20480 + (uint32_t)row * 80 + ch * 16, src);
        }
        CP_COMMIT();
    };
    auto loadS2 = [&](int ks, int st) {
#pragma unroll
        for (int r = 0; r < 2; r++) {
            int id = tid + r * 256;               // 0..511: 128 rows x 4
            int row = id >> 2, ch = id & 3;
            const h16* src = w2h + (size_t)row * SC_HID + ks * 32 + ch * 8;
            CP_ASYNC16(sb + ESM_B + st * 10240 + (uint32_t)row * 80 + ch * 16, src);
        }
        CP_COMMIT();
    };

    // ======== stage 1: h[64,256] = relu(A @ W1T + b1) ====
    {
        float acc[4][4][4];
#pragma unroll
        for (int a = 0; a < 4; a++)
#pragma unroll
            for (int b = 0; b < 4; b++)
#pragma unroll
                for (int c = 0; c < 4; c++) acc[a][b][c] = 0.f;

        uint32_t rowA = (uint32_t)(lane & 15) * 80 + (lane >> 4) * 16;
        uint32_t rowB = (uint32_t)(wid * 32 + (lane & 15)) * 80 + (lane >> 4) * 16;

        loadS1(0, 0);
        for (int ks = 0; ks < 8; ks++) {
            CP_WAIT0();
            __syncthreads();
            if (ks + 1 < 8) loadS1(ks + 1, (ks + 1) & 1);
            uint32_t sba = sb + ESM_A + (ks & 1) * 5120;
            uint32_t sbb = sb + ESM_B + (ks & 1) * 20480;
#pragma unroll
            for (int s = 0; s < 2; s++) {
                uint32_t aH[4][4], bH[2][4];
#pragma unroll
                for (int mf = 0; mf < 4; mf++) {
                    uint32_t ad = sba + rowA + (uint32_t)mf * (16 * 80) + s * 32;
                    LDSM4(aH[mf], ad);
                }
#pragma unroll
                for (int p = 0; p < 2; p++) {
                    uint32_t bd = sbb + rowB + (uint32_t)p * (16 * 80) + s * 32;
                    LDSM4(bH[p], bd);
                }
#pragma unroll
                for (int mf = 0; mf < 4; mf++)
#pragma unroll
                    for (int nf = 0; nf < 4; nf++) {
                        int p = nf >> 1, sel = nf & 1;
                        mma_f32(acc[mf][nf], aH[mf], bH[p][sel], bH[p][sel + 2]);
                    }
            }
            __syncthreads();
        }

        loadS2(0, 0);

        const float* b1 = b1g + e * SC_HID;
#pragma unroll
        for (int mf = 0; mf < 4; mf++) {
            int row = mf * 16 + (lane >> 2);
#pragma unroll
            for (int nf = 0; nf < 4; nf++) {
                int col = wid * 32 + nf * 8 + 2 * (lane & 3);
                float b0v = b1[col], b1v = b1[col + 1];
                float v0 = fmaxf(acc[mf][nf][0] + b0v, 0.f);
                float v1 = fmaxf(acc[mf][nf][1] + b1v, 0.f);
                float v2 = fmaxf(acc[mf][nf][2] + b0v, 0.f);
                float v3 = fmaxf(acc[mf][nf][3] + b1v, 0.f);
                int ks = col >> 5, cw = col & 31;
                uint32_t off = (uint32_t)ks * 5120 + (uint32_t)row * 80 + cw * 2;
                *(uint32_t*)(smraw + ESM_H + off)
                    = pack2h(__float2half_rn(v0), __float2half_rn(v1));
                *(uint32_t*)(smraw + ESM_H + off + 8 * 80)
                    = pack2h(__float2half_rn(v2), __float2half_rn(v3));
            }
        }
    }
    __syncthreads();

    // ======== stage 2: o[64,128] = h @ W2T + b2 ====
    {
        int warp_m = wid & 1, warp_n = wid >> 1;
        float acc[2][4][4];
#pragma unroll
        for (int a = 0; a < 2; a++)
#pragma unroll
            for (int b = 0; b < 4; b++)
#pragma unroll
                for (int c = 0; c < 4; c++) acc[a][b][c] = 0.f;

        uint32_t rowA = (uint32_t)(warp_m * 32 + (lane & 15)) * 80 + (lane >> 4) * 16;
        uint32_t rowB = (uint32_t)(warp_n * 32 + (lane & 15)) * 80 + (lane >> 4) * 16;

        for (int ks = 0; ks < 8; ks++) {
            CP_WAIT0();
            __syncthreads();
            if (ks + 1 < 8) loadS2(ks + 1, (ks + 1) & 1);
            uint32_t hbase = sb + ESM_H + (uint32_t)ks * 5120;
            uint32_t sbb = sb + ESM_B + (ks & 1) * 10240;
#pragma unroll
            for (int s = 0; s < 2; s++) {
                uint32_t aH[2][4], bH[2][4];
#pragma unroll
                for (int mf = 0; mf < 2; mf++) {
                    uint32_t ad = hbase + rowA + (uint32_t)mf * (16 * 80) + s * 32;
                    LDSM4(aH[mf], ad);
                }
#pragma unroll
                for (int p = 0; p < 2; p++) {
                    uint32_t bd = sbb + rowB + (uint32_t)p * (16 * 80) + s * 32;
                    LDSM4(bH[p], bd);
                }
#pragma unroll
                for (int mf = 0; mf < 2; mf++)
#pragma unroll
                    for (int nf = 0; nf < 4; nf++) {
                        int p = nf >> 1, sel = nf & 1;
                        mma_f32(acc[mf][nf], aH[mf], bH[p][sel], bH[p][sel + 2]);
                    }
            }
            __syncthreads();
        }

        const float* b2 = b2g + e * SC_OUT;
#pragma unroll
        for (int mf = 0; mf < 2; mf++) {
            int row = warp_m * 32 + mf * 16 + (lane >> 2);
#pragma unroll
            for (int nf = 0; nf < 4; nf++) {
                int col = warp_n * 32 + nf * 8 + 2 * (lane & 3);
                float b0v = b2[col], b1v = b2[col + 1];
                float v0 = acc[mf][nf][0] + b0v, v1 = acc[mf][nf][1] + b1v;
                float v2 = acc[mf][nf][2] + b0v, v3 = acc[mf][nf][3] + b1v;
                int pi0 = pidx[row], pi1 = pidx[row + 8];
                if (pi0 >= 0)
                    *(uint32_t*)(g_a0hi + (size_t)pi0 * K0PAD + HEADC + col)
                        = pack2h(__float2half_rn(v0), __float2half_rn(v1));
                if (pi1 >= 0)
                    *(uint32_t*)(g_a0hi + (size_t)pi1 * K0PAD + HEADC + col)
                        = pack2h(__float2half_rn(v2), __float2half_rn(v3));
            }
        }
    }
}

// ---------------- 4. f16 mma GEMM: hi-only, FR*32-row tiles ----------------
// stage: A-hi [MTILE*80] | B-hi [10240]
template <int KTOT, int RELU, int SPLIT, int FR>
__global__ void __launch_bounds__(256, 2) gemm_mma(
    const h16* __restrict__ aHi, const h16* __restrict__ wHi,
    const float* __restrict__ bias,
    h16* __restrict__ oHi, int KOUT)
{
    extern __shared__ char smraw[];
    const int NK = KTOT / 32;
    const int MTILE = FR * 32;
    const int ASZ = MTILE * 80;
    const int STG = ASZ + 10240;
    int tid = threadIdx.x, lane = tid & 31, wid = tid >> 5;
    int warp_m = wid & 1, warp_n = wid >> 1;     // 2 x 4 warps
    int m0 = blockIdx.x * MTILE, c0 = blockIdx.y * 128;

    uint32_t smBase = smem_u32(smraw);
    uint32_t rowA = (uint32_t)(warp_m * (FR * 16) + (lane & 15)) * 80 + (lane >> 4) * 16;
    uint32_t rowB = (uint32_t)(warp_n * 32 + (lane & 15)) * 80 + (lane >> 4) * 16;

    float acc[FR][4][4];
#pragma unroll
    for (int a = 0; a < FR; a++)
#pragma unroll
        for (int b = 0; b < 4; b++)
#pragma unroll
            for (int c = 0; c < 4; c++) acc[a][b][c] = 0.f;

    auto loadStage = [&](int ks, int st) {
        uint32_t sbs = smBase + st * STG;
#pragma unroll
        for (int i = 0; i < MTILE * 4; i += 256) {
            int c = tid + i;
            int row = c >> 2, ch = c & 3;
            const h16* src = aHi + (size_t)(m0 + row) * KTOT + ks * 32 + ch * 8;
            CP_ASYNC16(sbs + (uint32_t)row * 80 + ch * 16, src);
        }
#pragma unroll
        for (int i = 0; i < 2; i++) {
            int c = tid + i * 256;                // 0..511: 128 rows x 4
            int row = c >> 2, ch = c & 3;
            const h16* src = wHi + (size_t)(c0 + row) * KTOT + ks * 32 + ch * 8;
            CP_ASYNC16(sbs + ASZ + (uint32_t)row * 80 + ch * 16, src);
        }
        CP_COMMIT();
    };

    loadStage(0, 0);
    if (NK > 1) loadStage(1, 1);
    for (int ks = 0; ks < NK; ks++) {
        if (ks < NK - 1) CP_WAIT1(); else CP_WAIT0();
        __syncthreads();
        if (ks + 2 < NK) loadStage(ks + 2, (ks + 2) % 3);

        uint32_t sbs = smBase + (ks % 3) * STG;
#pragma unroll
        for (int s = 0; s < 2; s++) {
            uint32_t aH[FR][4], bH[2][4];
#pragma unroll
            for (int mf = 0; mf < FR; mf++) {
                uint32_t ad = sbs + rowA + (uint32_t)mf * (16 * 80) + s * 32;
                LDSM4(aH[mf], ad);
            }
#pragma unroll
            for (int p = 0; p < 2; p++) {
                uint32_t bd = sbs + ASZ + rowB + (uint32_t)p * (16 * 80) + s * 32;
                LDSM4(bH[p], bd);
            }
#pragma unroll
            for (int mf = 0; mf < FR; mf++)
#pragma unroll
                for (int nf = 0; nf < 4; nf++) {
                    int p = nf >> 1, sel = nf & 1;
                    mma_f32(acc[mf][nf], aH[mf], bH[p][sel], bH[p][sel + 2]);
                }
        }
    }

    if (SPLIT) {
        // ---- epilogue: +bias, relu, hi f16 store ----
#pragma unroll
        for (int mf = 0; mf < FR; mf++) {
            int row = m0 + warp_m * (FR * 16) + mf * 16 + (lane >> 2);
#pragma unroll
            for (int nf = 0; nf < 4; nf++) {
                int col = c0 + warp_n * 32 + nf * 8 + 2 * (lane & 3);
                float b0v = bias[col], b1v = bias[col + 1];
                float v0 = acc[mf][nf][0] + b0v, v1 = acc[mf][nf][1] + b1v;
                float v2 = acc[mf][nf][2] + b0v, v3 = acc[mf][nf][3] + b1v;
                if (RELU) {
                    v0 = fmaxf(v0, 0.f); v1 = fmaxf(v1, 0.f);
                    v2 = fmaxf(v2, 0.f); v3 = fmaxf(v3, 0.f);
                }
                *(uint32_t*)(oHi + (size_t)row * KOUT + col)
                    = pack2h(__float2half_rn(v0), __float2half_rn(v1));
                *(uint32_t*)(oHi + (size_t)(row + 8) * KOUT + col)
                    = pack2h(__float2half_rn(v2), __float2half_rn(v3));
            }
        }
    } else {
        // ---- fused max-pool epilogue: partial max over MTILE rows ----
        __syncthreads();
        float* pm = (float*)smraw;               // [2][128]
#pragma unroll
        for (int nf = 0; nf < 4; nf++) {
            float c0m = -FLT_MAX, c1m = -FLT_MAX;
#pragma unroll
            for (int mf = 0; mf < FR; mf++) {
                int col = c0 + warp_n * 32 + nf * 8 + 2 * (lane & 3);
                float b0v = bias[col], b1v = bias[col + 1];
                c0m = fmaxf(c0m, fmaxf(acc[mf][nf][0] + b0v, acc[mf][nf][2] + b0v));
                c1m = fmaxf(c1m, fmaxf(acc[mf][nf][1] + b1v, acc[mf][nf][3] + b1v));
            }
#pragma unroll
            for (int o = 4; o < 32; o <<= 1) {
                c0m = fmaxf(c0m, __shfl_xor_sync(0xFFFFFFFFu, c0m, o));
                c1m = fmaxf(c1m, __shfl_xor_sync(0xFFFFFFFFu, c1m, o));
            }
            if (lane < 4) {
                int cc = warp_n * 32 + nf * 8 + 2 * lane;
                pm[warp_m * 128 + cc]     = c0m;
                pm[warp_m * 128 + cc + 1] = c1m;
            }
        }
        __syncthreads();
        if (tid < 64) {
            int cc = tid * 2;
            float m0v = fmaxf(pm[cc],     pm[128 + cc]);
            float m1v = fmaxf(pm[cc + 1], pm[128 + cc + 1]);
            int b = m0 >> 10, part = (m0 >> 7) & (NPART - 1);
            *(float2*)(g_part + (size_t)(b * NPART + part) * C3OUT + c0 + cc)
                = make_float2(m0v, m1v);
        }
    }
}

// ---------------- 5. max pool final stage ----------------
__global__ void k_poolB(float* __restrict__ extra, int we) {
    int i = blockIdx.x * 256 + threadIdx.x;   // 8192
    float m = -FLT_MAX;
    int b = i >> 10, c = i & 1023;
#pragma unroll
    for (int part = 0; part < NPART; part++)
        m = fmaxf(m, g_part[(b * NPART + part) * C3OUT + c]);
    g_lat[i] = m;
    if (we) extra[i] = m;
}

// ---------------- 6. decoder MLP (32 cols x 8 K-slices, k-step 8) -----------
template <int RELU>
__global__ void __launch_bounds__(256) mlp8(
    const float* __restrict__ A, const float* __restrict__ W,
    const float* __restrict__ bias, float* __restrict__ Out,
    int K, int N)
{
    extern __shared__ float Ash[];
    __shared__ float red[256 * 8];
    int tid = threadIdx.x;
    for (int i = tid; i < 8 * K / 4; i += 256)
        ((float4*)Ash)[i] = ((const float4*)A)[i];
    __syncthreads();

    int col   = blockIdx.x * 32 + (tid & 31);
    int slice = tid >> 5;
    int kPer  = K >> 3;
    int k0    = slice * kPer;

    float acc[8];
#pragma unroll
    for (int bb = 0; bb < 8; bb++) acc[bb] = 0.f;

    for (int k = k0; k < k0 + kPer; k += 8) {
        float w[8];
#pragma unroll
        for (int j = 0; j < 8; j++)
            w[j] = W[(size_t)(k + j) * N + col];
#pragma unroll
        for (int bb = 0; bb < 8; bb++) {
            const float4* a4p = (const float4*)(Ash + bb * K + k);
            float4 a0 = a4p[0], a1 = a4p[1];
            acc[bb] = fmaf(a0.x, w[0], acc[bb]);
            acc[bb] = fmaf(a0.y, w[1], acc[bb]);
            acc[bb] = fmaf(a0.z, w[2], acc[bb]);
            acc[bb] = fmaf(a0.w, w[3], acc[bb]);
            acc[bb] = fmaf(a1.x, w[4], acc[bb]);
            acc[bb] = fmaf(a1.y, w[5], acc[bb]);
            acc[bb] = fmaf(a1.z, w[6], acc[bb]);
            acc[bb] = fmaf(a1.w, w[7], acc[bb]);
        }
    }
#pragma unroll
    for (int bb = 0; bb < 8; bb++) red[tid * 8 + bb] = acc[bb];
    __syncthreads();
    if (tid < 32) {
        float bsv = bias[col];
#pragma unroll
        for (int bb = 0; bb < 8; bb++) {
            float v = bsv;
#pragma unroll
            for (int s = 0; s < 8; s++)
                v += red[(tid + s * 32) * 8 + bb];
            if (RELU) v = fmaxf(v, 0.f);
            Out[(size_t)bb * N + col] = v;
        }
    }
}

// ---------------- launch ----------------
extern "C" void kernel_launch(void* const* d_in, const int* in_sizes, int n_in,
                              void* d_out, int out_size) {
    const float* x    = (const float*)d_in[0];
    const int*   cats = (const int*)  d_in[1];
    const float* W1   = (const float*)d_in[2];
    const float* b1   = (const float*)d_in[3];
    const float* W2   = (const float*)d_in[4];
    const float* b2   = (const float*)d_in[5];
    const float* Wc1  = (const float*)d_in[6];
    const float* bc1  = (const float*)d_in[7];
    const float* Wc2  = (const float*)d_in[8];
    const float* bc2  = (const float*)d_in[9];
    const float* Wc3  = (const float*)d_in[10];
    const float* bc3  = (const float*)d_in[11];
    const float* Wd1  = (const float*)d_in[12];
    const float* bd1  = (const float*)d_in[13];
    const float* Wd2  = (const float*)d_in[14];
    const float* bd2  = (const float*)d_in[15];
    const float* Wd3  = (const float*)d_in[16];
    const float* bd3  = (const float*)d_in[17];
    float* out = (float*)d_out;

    const int GS2 = 3 * (64 * 80 + 10240);    // FR=2 stages (15360 each)
    const int GS4 = 3 * (128 * 80 + 10240);   // FR=4 stages (20480 each)

    cudaFuncSetAttribute(k_expert_mma, cudaFuncAttributeMaxDynamicSharedMemorySize, ESMEM);
    cudaFuncSetAttribute(mlp8<1>,  cudaFuncAttributeMaxDynamicSharedMemorySize, 65536);
    cudaFuncSetAttribute(mlp8<0>,  cudaFuncAttributeMaxDynamicSharedMemorySize, 65536);
    cudaFuncSetAttribute(gemm_mma<K0PAD, 1, 1, 2>, cudaFuncAttributeMaxDynamicSharedMemorySize, GS2);
    cudaFuncSetAttribute(gemm_mma<C1OUT, 1, 1, 4>, cudaFuncAttributeMaxDynamicSharedMemorySize, GS4);
    cudaFuncSetAttribute(gemm_mma<C2OUT, 0, 0, 4>, cudaFuncAttributeMaxDynamicSharedMemorySize, GS4);

    h16 *p_a0h, *p_a1h, *p_a2h, *p_w1h, *p_w2h, *p_w3h;
    float *p_lat, *p_d1, *p_d2;
    cudaGetSymbolAddress((void**)&p_a0h, g_a0hi);
    cudaGetSymbolAddress((void**)&p_a1h, g_a1hi);
    cudaGetSymbolAddress((void**)&p_a2h, g_a2hi);
    cudaGetSymbolAddress((void**)&p_w1h, g_w1hi);
    cudaGetSymbolAddress((void**)&p_w2h, g_w2hi);
    cudaGetSymbolAddress((void**)&p_w3h, g_w3hi);
    cudaGetSymbolAddress((void**)&p_lat, g_lat);
    cudaGetSymbolAddress((void**)&p_d1,  g_d1);
    cudaGetSymbolAddress((void**)&p_d2,  g_d2);

    k_prep<<<PREP_NB, 256>>>(x, W1, W2, Wc1, Wc2, Wc3);
    k_build<<<1, 1024>>>(cats);
    k_expert_mma<<<MAXTILES, 256, ESMEM>>>(b1, b2);

    // conv stack: all hi-only (TERMS=1); gemm1 FR=2, gemm2/3 FR=4
    gemm_mma<K0PAD, 1, 1, 2><<<dim3(128, C1OUT / 128), 256, GS2>>>(
        p_a0h, p_w1h, bc1, p_a1h, C1OUT);
    gemm_mma<C1OUT, 1, 1, 4><<<dim3(64, C2OUT / 128), 256, GS4>>>(
        p_a1h, p_w2h, bc2, p_a2h, C2OUT);
    gemm_mma<C2OUT, 0, 0, 4><<<dim3(64, C3OUT / 128), 256, GS4>>>(
        p_a2h, p_w3h, bc3, (h16*)0, C3OUT);

    int write_extra = (out_size >= 65536 + 8192) ? 1 : 0;
    k_poolB<<<NPOINTS / 256, 256>>>(out + 65536, write_extra);

    mlp8<1><<<DEC1 / 32, 256, 8 * DEC1 * 4>>>(p_lat, Wd1, bd1, p_d1, DEC1, DEC1);
    mlp8<1><<<DEC2 / 32, 256, 8 * DEC1 * 4>>>(p_d1,  Wd2, bd2, p_d2, DEC1, DEC2);
    mlp8<0><<<DEC3 / 32, 256, 8 * DEC2 * 4>>>(p_d2,  Wd3, bd3, out,  DEC2, DEC3);
}

// round 15
// speedup vs baseline: 1.8571x; 1.0119x over previous
#include <cuda_runtime.h>
#include <cuda_fp16.h>
#include <float.h>
#include <stdint.h>

// ---------------- problem constants ----------------
#define BATCH      8
#define NPTS       1024
#define NPOINTS    (BATCH * NPTS)        // 8192
#define HEADC      8
#define SHAPEC     256
#define XCH        (HEADC + SHAPEC)      // 264
#define NEXPERT    16
#define SC_HID     256
#define SC_OUT     128
#define K0PAD      160                   // 136 padded to 160
#define C1OUT      256
#define C2OUT      512
#define C3OUT      1024
#define DEC1       1024
#define DEC2       2048
#define DEC3       8192
#define ETILE      64
#define MAXTILES   (NPOINTS / ETILE + NEXPERT)   // 144
#define NPART      8                     // pool partials per batch (1024/128)

typedef __half h16;

// ---------------- scratch (device globals; no runtime alloc) ----------------
__device__ __align__(256) h16 g_xhi[NPOINTS * SHAPEC];
__device__ __align__(256) h16 g_a0hi[NPOINTS * K0PAD];
__device__ __align__(256) h16 g_a1hi[NPOINTS * C1OUT];
__device__ __align__(256) h16 g_a2hi[NPOINTS * C2OUT];
__device__ __align__(256) h16 g_w1hi[C1OUT * K0PAD];
__device__ __align__(256) h16 g_w2hi[C2OUT * C1OUT];
__device__ __align__(256) h16 g_w3hi[C3OUT * C2OUT];
__device__ __align__(256) h16 g_e1hi[NEXPERT * SC_HID * SHAPEC];
__device__ __align__(256) h16 g_e2hi[NEXPERT * SC_OUT * SC_HID];
__device__ float g_part[BATCH * NPART * C3OUT];
__device__ float g_d1[BATCH * DEC1];
__device__ float g_d2[BATCH * DEC2];
__device__ int   g_idx[NPOINTS];
__device__ int   g_tileExpert[MAXTILES];
__device__ int   g_tileStart[MAXTILES];
__device__ int   g_tileLen[MAXTILES];
__device__ int   g_nTiles;

// ---------------- ptx helpers (sm_80-safe) ----------------
__device__ __forceinline__ uint32_t smem_u32(const void* p) {
    uint32_t a;
    asm("{ .reg .u64 t; cvta.to.shared.u64 t, %1; cvt.u32.u64 %0, t; }" : "=r"(a) : "l"(p));
    return a;
}
#define CP_ASYNC16(dst, src) \
    asm volatile("cp.async.cg.shared.global [%0], [%1], 16;" :: "r"(dst), "l"(src))
#define CP_COMMIT() asm volatile("cp.async.commit_group;" ::: "memory")
#define CP_WAIT0()  asm volatile("cp.async.wait_group 0;" ::: "memory")
#define CP_WAIT1()  asm volatile("cp.async.wait_group 1;" ::: "memory")

#define LDSM4(r, addr) \
    asm volatile("ldmatrix.sync.aligned.m8n8.x4.shared.b16 {%0,%1,%2,%3}, [%4];" \
        : "=r"((r)[0]), "=r"((r)[1]), "=r"((r)[2]), "=r"((r)[3]) : "r"(addr))

__device__ __forceinline__ void mma_f32(float* d, const uint32_t* a,
                                        uint32_t b0, uint32_t b1) {
    asm volatile(
        "mma.sync.aligned.m16n8k16.row.col.f32.f16.f16.f32 "
        "{%0,%1,%2,%3}, {%4,%5,%6,%7}, {%8,%9}, {%0,%1,%2,%3};"
        : "+f"(d[0]), "+f"(d[1]), "+f"(d[2]), "+f"(d[3])
        : "r"(a[0]), "r"(a[1]), "r"(a[2]), "r"(a[3]), "r"(b0), "r"(b1));
}

__device__ __forceinline__ uint32_t pack2h(h16 a, h16 b) {
    __half2 t; t.x = a; t.y = b;
    return *(uint32_t*)&t;
}

// ---------------- 1. fused prep: transpose | tsplit | head | wconv ---------
#define PREP_T1 2048
#define PREP_T2 3584
#define PREP_T3 4608
#define WS_NB1 40
#define WS_NB2 128
#define WS_NB3 512
#define PREP_NB (PREP_T3 + WS_NB1 + WS_NB2 + WS_NB3)   // 5288

__global__ void __launch_bounds__(256) k_prep(
    const float* __restrict__ x,
    const float* __restrict__ W1, const float* __restrict__ W2,
    const float* __restrict__ Wc1, const float* __restrict__ Wc2,
    const float* __restrict__ Wc3)
{
    __shared__ float t[32][33];
    int bi = blockIdx.x;
    int tid = threadIdx.x;
    int tx = tid & 31, ty = tid >> 5;

    if (bi < PREP_T1) {
        // ---- transpose x shape feats -> g_xhi ----
        int idx = bi;
        int cB = (idx & 7) * 32;
        int nB = ((idx >> 3) & 31) * 32;
        int b  = idx >> 8;
        const float* xb = x + (size_t)b * XCH * NPTS;
#pragma unroll
        for (int i = ty; i < 32; i += 8)
            t[i][tx] = xb[(size_t)(HEADC + cB + i) * NPTS + nB + tx];
        __syncthreads();
        size_t base = ((size_t)b * NPTS + nB) * SHAPEC + cB;
#pragma unroll
        for (int i = ty; i < 32; i += 8)
            g_xhi[base + (size_t)i * SHAPEC + tx] = __float2half_rn(t[tx][i]);
    } else if (bi < PREP_T2) {
        // ---- expert weight transpose (hi only) ----
        int r = bi - PREP_T1;
        const float* src; h16 *hi; int K, OUT, e, k0, o0;
        if (r < 1024) {
            e = r >> 6; int q = r & 63;
            k0 = (q & 7) * 32; o0 = (q >> 3) * 32;
            src = W1; hi = g_e1hi; K = SHAPEC; OUT = SC_HID;
        } else {
            r -= 1024;
            e = r >> 5; int q = r & 31;
            k0 = (q & 7) * 32; o0 = (q >> 3) * 32;
            src = W2; hi = g_e2hi; K = SC_HID; OUT = SC_OUT;
        }
        const float* s = src + (size_t)e * K * OUT;
#pragma unroll
        for (int i = ty; i < 32; i += 8)
            t[i][tx] = s[(size_t)(k0 + i) * OUT + o0 + tx];
        __syncthreads();
        size_t base = (size_t)e * OUT * K + (size_t)o0 * K + k0;
#pragma unroll
        for (int i = ty; i < 32; i += 8)
            hi[base + (size_t)i * K + tx] = __float2half_rn(t[tx][i]);
    } else if (bi < PREP_T3) {
        // ---- head channels + pad -> a0hi ----
        int i = (bi - PREP_T2) * 256 + tid;
        int p = i >> 5, s = i & 31;
        float v = 0.f;
        int col;
        if (s < 8) {
            int b = p >> 10, n = p & 1023;
            v = x[(size_t)b * XCH * NPTS + (size_t)s * NPTS + n];
            col = s;
        } else {
            col = 128 + s;
        }
        g_a0hi[(size_t)p * K0PAD + col] = __float2half_rn(v);
    } else {
        // ---- conv weight convert (hi only, 4 elems/thread, float4) ----
        int r = bi - PREP_T3;
        const float* w; h16* hi; int Kin, Kpad, total4, i4;
        if (r < WS_NB1) {
            w = Wc1; hi = g_w1hi; Kin = 136; Kpad = K0PAD;
            total4 = C1OUT * K0PAD / 4; i4 = r * 256 + tid;
        } else if (r < WS_NB1 + WS_NB2) {
            w = Wc2; hi = g_w2hi; Kin = C1OUT; Kpad = C1OUT;
            total4 = C2OUT * C1OUT / 4; i4 = (r - WS_NB1) * 256 + tid;
        } else {
            w = Wc3; hi = g_w3hi; Kin = C2OUT; Kpad = C2OUT;
            total4 = C3OUT * C2OUT / 4; i4 = (r - WS_NB1 - WS_NB2) * 256 + tid;
        }
        if (i4 >= total4) return;
        int i = i4 * 4;
        int c = i / Kpad, k = i - c * Kpad;
        float4 v = make_float4(0.f, 0.f, 0.f, 0.f);
        if (k < Kin)                                 // groups never straddle (Kin%4==0)
            v = *(const float4*)(w + (size_t)c * Kin + k);
        uint2 pk;
        pk.x = pack2h(__float2half_rn(v.x), __float2half_rn(v.y));
        pk.y = pack2h(__float2half_rn(v.z), __float2half_rn(v.w));
        *(uint2*)(hi + i) = pk;
    }
}

// ---------------- 2. counting sort (warp-aggregated atomics) ----------------
__global__ void k_build(const int* __restrict__ cats) {
    __shared__ int cnt[NEXPERT];
    __shared__ int off[NEXPERT + 1];
    __shared__ int cur[NEXPERT];
    int tid = threadIdx.x, lane = tid & 31;
    if (tid < NEXPERT) cnt[tid] = 0;
    __syncthreads();
    for (int i = tid; i < NPOINTS; i += blockDim.x) {
        int c = cats[i];
        unsigned m = __match_any_sync(0xFFFFFFFFu, c);
        int leader = __ffs(m) - 1;
        if (lane == leader) atomicAdd(&cnt[c], __popc(m));
    }
    __syncthreads();
    if (tid == 0) {
        int s = 0;
        for (int e = 0; e < NEXPERT; e++) { off[e] = s; s += cnt[e]; }
        off[NEXPERT] = s;
        int t = 0;
        for (int e = 0; e < NEXPERT; e++)
            for (int st = off[e]; st < off[e + 1]; st += ETILE) {
                g_tileExpert[t] = e;
                g_tileStart[t]  = st;
                g_tileLen[t]    = min(ETILE, off[e + 1] - st);
                t++;
            }
        g_nTiles = t;
    }
    __syncthreads();
    if (tid < NEXPERT) cur[tid] = off[tid];
    __syncthreads();
    for (int i = tid; i < NPOINTS; i += blockDim.x) {
        int c = cats[i];
        unsigned m = __match_any_sync(0xFFFFFFFFu, c);
        int leader = __ffs(m) - 1;
        int rank = __popc(m & ((1u << lane) - 1u));
        int base = 0;
        if (lane == leader) base = atomicAdd(&cur[c], __popc(m));
        base = __shfl_sync(m, base, leader);
        g_idx[base + rank] = i;
    }
}

// ---------------- 3. fused expert MLP (hi-only) ----------------
// smem: A 2x5120 @0; B 2x20480 @10240; H 40960 @51200 -> 92160 B
#define ESM_A  0
#define ESM_B  10240
#define ESM_H  51200
#define ESMEM  92160

__global__ void __launch_bounds__(256) k_expert_mma(
    const float* __restrict__ b1g, const float* __restrict__ b2g)
{
    int t = blockIdx.x;
    if (t >= g_nTiles) return;
    int e = g_tileExpert[t], start = g_tileStart[t], len = g_tileLen[t];

    extern __shared__ char smraw[];
    __shared__ int pidx[ETILE];
    __shared__ int gidx[ETILE];

    int tid = threadIdx.x, lane = tid & 31, wid = tid >> 5;
    uint32_t sb = smem_u32(smraw);

    if (tid < ETILE) {
        int pi = (tid < len) ? g_idx[start + tid] : -1;
        pidx[tid] = pi;
        gidx[tid] = pi < 0 ? 0 : pi;
    }
    __syncthreads();

    const h16* w1h = g_e1hi + (size_t)e * SC_HID * SHAPEC;
    const h16* w2h = g_e2hi + (size_t)e * SC_OUT * SC_HID;

    auto loadS1 = [&](int ks, int st) {
        {
            int row = tid >> 2, ch = tid & 3;
            const h16* src = g_xhi + (size_t)gidx[row] * SHAPEC + ks * 32 + ch * 8;
            CP_ASYNC16(sb + ESM_A + st * 5120 + (uint32_t)row * 80 + ch * 16, src);
        }
#pragma unroll
        for (int r = 0; r < 4; r++) {
            int id = tid + r * 256;
            int row = id >> 2, ch = id & 3;
            const h16* src = w1h + (size_t)row * SHAPEC + ks * 32 + ch * 8;
            CP_ASYNC16(sb + ESM_B + st * 20480 + (uint32_t)row * 80 + ch * 16, src);
        }
        CP_COMMIT();
    };
    auto loadS2 = [&](int ks, int st) {
#pragma unroll
        for (int r = 0; r < 2; r++) {
            int id = tid + r * 256;
            int row = id >> 2, ch = id & 3;
            const h16* src = w2h + (size_t)row * SC_HID + ks * 32 + ch * 8;
            CP_ASYNC16(sb + ESM_B + st * 10240 + (uint32_t)row * 80 + ch * 16, src);
        }
        CP_COMMIT();
    };

    // ======== stage 1: h[64,256] = relu(A @ W1T + b1) ====
    {
        float acc[4][4][4];
#pragma unroll
        for (int a = 0; a < 4; a++)
#pragma unroll
            for (int b = 0; b < 4; b++)
#pragma unroll
                for (int c = 0; c < 4; c++) acc[a][b][c] = 0.f;

        uint32_t rowA = (uint32_t)(lane & 15) * 80 + (lane >> 4) * 16;
        uint32_t rowB = (uint32_t)(wid * 32 + (lane & 15)) * 80 + (lane >> 4) * 16;

        loadS1(0, 0);
        for (int ks = 0; ks < 8; ks++) {
            CP_WAIT0();
            __syncthreads();
            if (ks + 1 < 8) loadS1(ks + 1, (ks + 1) & 1);
            uint32_t sba = sb + ESM_A + (ks & 1) * 5120;
            uint32_t sbb = sb + ESM_B + (ks & 1) * 20480;
#pragma unroll
            for (int s = 0; s < 2; s++) {
                uint32_t aH[4][4], bH[2][4];
#pragma unroll
                for (int mf = 0; mf < 4; mf++) {
                    uint32_t ad = sba + rowA + (uint32_t)mf * (16 * 80) + s * 32;
                    LDSM4(aH[mf], ad);
                }
#pragma unroll
                for (int p = 0; p < 2; p++) {
                    uint32_t bd = sbb + rowB + (uint32_t)p * (16 * 80) + s * 32;
                    LDSM4(bH[p], bd);
                }
#pragma unroll
                for (int mf = 0; mf < 4; mf++)
#pragma unroll
                    for (int nf = 0; nf < 4; nf++) {
                        int p = nf >> 1, sel = nf & 1;
                        mma_f32(acc[mf][nf], aH[mf], bH[p][sel], bH[p][sel + 2]);
                    }
            }
            __syncthreads();
        }

        loadS2(0, 0);

        const float* b1 = b1g + e * SC_HID;
#pragma unroll
        for (int mf = 0; mf < 4; mf++) {
            int row = mf * 16 + (lane >> 2);
#pragma unroll
            for (int nf = 0; nf < 4; nf++) {
                int col = wid * 32 + nf * 8 + 2 * (lane & 3);
                float b0v = b1[col], b1v = b1[col + 1];
                float v0 = fmaxf(acc[mf][nf][0] + b0v, 0.f);
                float v1 = fmaxf(acc[mf][nf][1] + b1v, 0.f);
                float v2 = fmaxf(acc[mf][nf][2] + b0v, 0.f);
                float v3 = fmaxf(acc[mf][nf][3] + b1v, 0.f);
                int ks = col >> 5, cw = col & 31;
                uint32_t off = (uint32_t)ks * 5120 + (uint32_t)row * 80 + cw * 2;
                *(uint32_t*)(smraw + ESM_H + off)
                    = pack2h(__float2half_rn(v0), __float2half_rn(v1));
                *(uint32_t*)(smraw + ESM_H + off + 8 * 80)
                    = pack2h(__float2half_rn(v2), __float2half_rn(v3));
            }
        }
    }
    __syncthreads();

    // ======== stage 2: o[64,128] = h @ W2T + b2 ====
    {
        int warp_m = wid & 1, warp_n = wid >> 1;
        float acc[2][4][4];
#pragma unroll
        for (int a = 0; a < 2; a++)
#pragma unroll
            for (int b = 0; b < 4; b++)
#pragma unroll
                for (int c = 0; c < 4; c++) acc[a][b][c] = 0.f;

        uint32_t rowA = (uint32_t)(warp_m * 32 + (lane & 15)) * 80 + (lane >> 4) * 16;
        uint32_t rowB = (uint32_t)(warp_n * 32 + (lane & 15)) * 80 + (lane >> 4) * 16;

        for (int ks = 0; ks < 8; ks++) {
            CP_WAIT0();
            __syncthreads();
            if (ks + 1 < 8) loadS2(ks + 1, (ks + 1) & 1);
            uint32_t hbase = sb + ESM_H + (uint32_t)ks * 5120;
            uint32_t sbb = sb + ESM_B + (ks & 1) * 10240;
#pragma unroll
            for (int s = 0; s < 2; s++) {
                uint32_t aH[2][4], bH[2][4];
#pragma unroll
                for (int mf = 0; mf < 2; mf++) {
                    uint32_t ad = hbase + rowA + (uint32_t)mf * (16 * 80) + s * 32;
                    LDSM4(aH[mf], ad);
                }
#pragma unroll
                for (int p = 0; p < 2; p++) {
                    uint32_t bd = sbb + rowB + (uint32_t)p * (16 * 80) + s * 32;
                    LDSM4(bH[p], bd);
                }
#pragma unroll
                for (int mf = 0; mf < 2; mf++)
#pragma unroll
                    for (int nf = 0; nf < 4; nf++) {
                        int p = nf >> 1, sel = nf & 1;
                        mma_f32(acc[mf][nf], aH[mf], bH[p][sel], bH[p][sel + 2]);
                    }
            }
            __syncthreads();
        }

        const float* b2 = b2g + e * SC_OUT;
#pragma unroll
        for (int mf = 0; mf < 2; mf++) {
            int row = warp_m * 32 + mf * 16 + (lane >> 2);
#pragma unroll
            for (int nf = 0; nf < 4; nf++) {
                int col = warp_n * 32 + nf * 8 + 2 * (lane & 3);
                float b0v = b2[col], b1v = b2[col + 1];
                float v0 = acc[mf][nf][0] + b0v, v1 = acc[mf][nf][1] + b1v;
                float v2 = acc[mf][nf][2] + b0v, v3 = acc[mf][nf][3] + b1v;
                int pi0 = pidx[row], pi1 = pidx[row + 8];
                if (pi0 >= 0)
                    *(uint32_t*)(g_a0hi + (size_t)pi0 * K0PAD + HEADC + col)
                        = pack2h(__float2half_rn(v0), __float2half_rn(v1));
                if (pi1 >= 0)
                    *(uint32_t*)(g_a0hi + (size_t)pi1 * K0PAD + HEADC + col)
                        = pack2h(__float2half_rn(v2), __float2half_rn(v3));
            }
        }
    }
}

// ---------------- 4. f16 mma GEMM: hi-only, FR*32-row tiles ----------------
template <int KTOT, int RELU, int SPLIT, int FR>
__global__ void __launch_bounds__(256, 2) gemm_mma(
    const h16* __restrict__ aHi, const h16* __restrict__ wHi,
    const float* __restrict__ bias,
    h16* __restrict__ oHi, int KOUT)
{
    extern __shared__ char smraw[];
    const int NK = KTOT / 32;
    const int MTILE = FR * 32;
    const int ASZ = MTILE * 80;
    const int STG = ASZ + 10240;
    int tid = threadIdx.x, lane = tid & 31, wid = tid >> 5;
    int warp_m = wid & 1, warp_n = wid >> 1;     // 2 x 4 warps
    int m0 = blockIdx.x * MTILE, c0 = blockIdx.y * 128;

    uint32_t smBase = smem_u32(smraw);
    uint32_t rowA = (uint32_t)(warp_m * (FR * 16) + (lane & 15)) * 80 + (lane >> 4) * 16;
    uint32_t rowB = (uint32_t)(warp_n * 32 + (lane & 15)) * 80 + (lane >> 4) * 16;

    float acc[FR][4][4];
#pragma unroll
    for (int a = 0; a < FR; a++)
#pragma unroll
        for (int b = 0; b < 4; b++)
#pragma unroll
            for (int c = 0; c < 4; c++) acc[a][b][c] = 0.f;

    auto loadStage = [&](int ks, int st) {
        uint32_t sbs = smBase + st * STG;
#pragma unroll
        for (int i = 0; i < MTILE * 4; i += 256) {
            int c = tid + i;
            int row = c >> 2, ch = c & 3;
            const h16* src = aHi + (size_t)(m0 + row) * KTOT + ks * 32 + ch * 8;
            CP_ASYNC16(sbs + (uint32_t)row * 80 + ch * 16, src);
        }
#pragma unroll
        for (int i = 0; i < 2; i++) {
            int c = tid + i * 256;
            int row = c >> 2, ch = c & 3;
            const h16* src = wHi + (size_t)(c0 + row) * KTOT + ks * 32 + ch * 8;
            CP_ASYNC16(sbs + ASZ + (uint32_t)row * 80 + ch * 16, src);
        }
        CP_COMMIT();
    };

    loadStage(0, 0);
    if (NK > 1) loadStage(1, 1);
    for (int ks = 0; ks < NK; ks++) {
        if (ks < NK - 1) CP_WAIT1(); else CP_WAIT0();
        __syncthreads();
        if (ks + 2 < NK) loadStage(ks + 2, (ks + 2) % 3);

        uint32_t sbs = smBase + (ks % 3) * STG;
#pragma unroll
        for (int s = 0; s < 2; s++) {
            uint32_t aH[FR][4], bH[2][4];
#pragma unroll
            for (int mf = 0; mf < FR; mf++) {
                uint32_t ad = sbs + rowA + (uint32_t)mf * (16 * 80) + s * 32;
                LDSM4(aH[mf], ad);
            }
#pragma unroll
            for (int p = 0; p < 2; p++) {
                uint32_t bd = sbs + ASZ + rowB + (uint32_t)p * (16 * 80) + s * 32;
                LDSM4(bH[p], bd);
            }
#pragma unroll
            for (int mf = 0; mf < FR; mf++)
#pragma unroll
                for (int nf = 0; nf < 4; nf++) {
                    int p = nf >> 1, sel = nf & 1;
                    mma_f32(acc[mf][nf], aH[mf], bH[p][sel], bH[p][sel + 2]);
                }
        }
    }

    if (SPLIT) {
#pragma unroll
        for (int mf = 0; mf < FR; mf++) {
            int row = m0 + warp_m * (FR * 16) + mf * 16 + (lane >> 2);
#pragma unroll
            for (int nf = 0; nf < 4; nf++) {
                int col = c0 + warp_n * 32 + nf * 8 + 2 * (lane & 3);
                float b0v = bias[col], b1v = bias[col + 1];
                float v0 = acc[mf][nf][0] + b0v, v1 = acc[mf][nf][1] + b1v;
                float v2 = acc[mf][nf][2] + b0v, v3 = acc[mf][nf][3] + b1v;
                if (RELU) {
                    v0 = fmaxf(v0, 0.f); v1 = fmaxf(v1, 0.f);
                    v2 = fmaxf(v2, 0.f); v3 = fmaxf(v3, 0.f);
                }
                *(uint32_t*)(oHi + (size_t)row * KOUT + col)
                    = pack2h(__float2half_rn(v0), __float2half_rn(v1));
                *(uint32_t*)(oHi + (size_t)(row + 8) * KOUT + col)
                    = pack2h(__float2half_rn(v2), __float2half_rn(v3));
            }
        }
    } else {
        // ---- fused max-pool epilogue: partial max over MTILE rows ----
        __syncthreads();
        float* pm = (float*)smraw;               // [2][128]
#pragma unroll
        for (int nf = 0; nf < 4; nf++) {
            float c0m = -FLT_MAX, c1m = -FLT_MAX;
#pragma unroll
            for (int mf = 0; mf < FR; mf++) {
                int col = c0 + warp_n * 32 + nf * 8 + 2 * (lane & 3);
                float b0v = bias[col], b1v = bias[col + 1];
                c0m = fmaxf(c0m, fmaxf(acc[mf][nf][0] + b0v, acc[mf][nf][2] + b0v));
                c1m = fmaxf(c1m, fmaxf(acc[mf][nf][1] + b1v, acc[mf][nf][3] + b1v));
            }
#pragma unroll
            for (int o = 4; o < 32; o <<= 1) {
                c0m = fmaxf(c0m, __shfl_xor_sync(0xFFFFFFFFu, c0m, o));
                c1m = fmaxf(c1m, __shfl_xor_sync(0xFFFFFFFFu, c1m, o));
            }
            if (lane < 4) {
                int cc = warp_n * 32 + nf * 8 + 2 * lane;
                pm[warp_m * 128 + cc]     = c0m;
                pm[warp_m * 128 + cc + 1] = c1m;
            }
        }
        __syncthreads();
        if (tid < 64) {
            int cc = tid * 2;
            float m0v = fmaxf(pm[cc],     pm[128 + cc]);
            float m1v = fmaxf(pm[cc + 1], pm[128 + cc + 1]);
            int b = m0 >> 10, part = (m0 >> 7) & (NPART - 1);
            *(float2*)(g_part + (size_t)(b * NPART + part) * C3OUT + c0 + cc)
                = make_float2(m0v, m1v);
        }
    }
}

// ---------------- 5. decoder MLP (POOL=1 builds latent from g_part) --------
template <int RELU, int POOL>
__global__ void __launch_bounds__(256) mlp8(
    const float* __restrict__ A, const float* __restrict__ W,
    const float* __restrict__ bias, float* __restrict__ Out,
    int K, int N, float* __restrict__ extra, int we)
{
    extern __shared__ float Ash[];
    __shared__ float red[256 * 8];
    int tid = threadIdx.x;
    if (POOL) {
        // build latent [8,1024] from pool partials
        for (int i = tid; i < 8 * 1024; i += 256) {
            int b = i >> 10, c = i & 1023;
            const float* gp = g_part + (size_t)(b * NPART) * C3OUT + c;
            float m = gp[0];
#pragma unroll
            for (int part = 1; part < NPART; part++)
                m = fmaxf(m, gp[(size_t)part * C3OUT]);
            Ash[i] = m;
            if (we && blockIdx.x == 0) extra[i] = m;
        }
    } else {
        for (int i = tid; i < 8 * K / 4; i += 256)
            ((float4*)Ash)[i] = ((const float4*)A)[i];
    }
    __syncthreads();

    int col   = blockIdx.x * 32 + (tid & 31);
    int slice = tid >> 5;
    int kPer  = K >> 3;
    int k0    = slice * kPer;

    float acc[8];
#pragma unroll
    for (int bb = 0; bb < 8; bb++) acc[bb] = 0.f;

    for (int k = k0; k < k0 + kPer; k += 16) {
        float w[16];
#pragma unroll
        for (int j = 0; j < 16; j++)
            w[j] = W[(size_t)(k + j) * N + col];
#pragma unroll
        for (int bb = 0; bb < 8; bb++) {
            const float4* a4p = (const float4*)(Ash + bb * K + k);
#pragma unroll
            for (int q = 0; q < 4; q++) {
                float4 a = a4p[q];
                acc[bb] = fmaf(a.x, w[q * 4 + 0], acc[bb]);
                acc[bb] = fmaf(a.y, w[q * 4 + 1], acc[bb]);
                acc[bb] = fmaf(a.z, w[q * 4 + 2], acc[bb]);
                acc[bb] = fmaf(a.w, w[q * 4 + 3], acc[bb]);
            }
        }
    }
#pragma unroll
    for (int bb = 0; bb < 8; bb++) red[tid * 8 + bb] = acc[bb];
    __syncthreads();
    if (tid < 32) {
        float bsv = bias[col];
#pragma unroll
        for (int bb = 0; bb < 8; bb++) {
            float v = bsv;
#pragma unroll
            for (int s = 0; s < 8; s++)
                v += red[(tid + s * 32) * 8 + bb];
            if (RELU) v = fmaxf(v, 0.f);
            Out[(size_t)bb * N + col] = v;
        }
    }
}

// ---------------- launch ----------------
extern "C" void kernel_launch(void* const* d_in, const int* in_sizes, int n_in,
                              void* d_out, int out_size) {
    const float* x    = (const float*)d_in[0];
    const int*   cats = (const int*)  d_in[1];
    const float* W1   = (const float*)d_in[2];
    const float* b1   = (const float*)d_in[3];
    const float* W2   = (const float*)d_in[4];
    const float* b2   = (const float*)d_in[5];
    const float* Wc1  = (const float*)d_in[6];
    const float* bc1  = (const float*)d_in[7];
    const float* Wc2  = (const float*)d_in[8];
    const float* bc2  = (const float*)d_in[9];
    const float* Wc3  = (const float*)d_in[10];
    const float* bc3  = (const float*)d_in[11];
    const float* Wd1  = (const float*)d_in[12];
    const float* bd1  = (const float*)d_in[13];
    const float* Wd2  = (const float*)d_in[14];
    const float* bd2  = (const float*)d_in[15];
    const float* Wd3  = (const float*)d_in[16];
    const float* bd3  = (const float*)d_in[17];
    float* out = (float*)d_out;

    const int GS2 = 3 * (64 * 80 + 10240);    // FR=2 stages
    const int GS4 = 3 * (128 * 80 + 10240);   // FR=4 stages

    cudaFuncSetAttribute(k_expert_mma, cudaFuncAttributeMaxDynamicSharedMemorySize, ESMEM);
    cudaFuncSetAttribute(mlp8<1, 1>, cudaFuncAttributeMaxDynamicSharedMemorySize, 65536);
    cudaFuncSetAttribute(mlp8<1, 0>, cudaFuncAttributeMaxDynamicSharedMemorySize, 65536);
    cudaFuncSetAttribute(mlp8<0, 0>, cudaFuncAttributeMaxDynamicSharedMemorySize, 65536);
    cudaFuncSetAttribute(gemm_mma<K0PAD, 1, 1, 2>, cudaFuncAttributeMaxDynamicSharedMemorySize, GS2);
    cudaFuncSetAttribute(gemm_mma<C1OUT, 1, 1, 4>, cudaFuncAttributeMaxDynamicSharedMemorySize, GS4);
    cudaFuncSetAttribute(gemm_mma<C2OUT, 0, 0, 4>, cudaFuncAttributeMaxDynamicSharedMemorySize, GS4);

    h16 *p_a0h, *p_a1h, *p_a2h, *p_w1h, *p_w2h, *p_w3h;
    float *p_d1, *p_d2;
    cudaGetSymbolAddress((void**)&p_a0h, g_a0hi);
    cudaGetSymbolAddress((void**)&p_a1h, g_a1hi);
    cudaGetSymbolAddress((void**)&p_a2h, g_a2hi);
    cudaGetSymbolAddress((void**)&p_w1h, g_w1hi);
    cudaGetSymbolAddress((void**)&p_w2h, g_w2hi);
    cudaGetSymbolAddress((void**)&p_w3h, g_w3hi);
    cudaGetSymbolAddress((void**)&p_d1,  g_d1);
    cudaGetSymbolAddress((void**)&p_d2,  g_d2);

    k_prep<<<PREP_NB, 256>>>(x, W1, W2, Wc1, Wc2, Wc3);
    k_build<<<1, 1024>>>(cats);
    k_expert_mma<<<MAXTILES, 256, ESMEM>>>(b1, b2);

    // conv stack: all hi-only; gemm1 FR=2, gemm2/3 FR=4; gemm3 fuses pool
    gemm_mma<K0PAD, 1, 1, 2><<<dim3(128, C1OUT / 128), 256, GS2>>>(
        p_a0h, p_w1h, bc1, p_a1h, C1OUT);
    gemm_mma<C1OUT, 1, 1, 4><<<dim3(64, C2OUT / 128), 256, GS4>>>(
        p_a1h, p_w2h, bc2, p_a2h, C2OUT);
    gemm_mma<C2OUT, 0, 0, 4><<<dim3(64, C3OUT / 128), 256, GS4>>>(
        p_a2h, p_w3h, bc3, (h16*)0, C3OUT);

    // decoder: mlp1 fuses the final pool reduction (POOL=1)
    int write_extra = (out_size >= 65536 + 8192) ? 1 : 0;
    mlp8<1, 1><<<DEC1 / 32, 256, 8 * DEC1 * 4>>>(
        (const float*)0, Wd1, bd1, p_d1, DEC1, DEC1, out + 65536, write_extra);
    mlp8<1, 0><<<DEC2 / 32, 256, 8 * DEC1 * 4>>>(
        p_d1, Wd2, bd2, p_d2, DEC1, DEC2, (float*)0, 0);
    mlp8<0, 0><<<DEC3 / 32, 256, 8 * DEC2 * 4>>>(
        p_d2, Wd3, bd3, out, DEC2, DEC3, (float*)0, 0);
}